// round 1
// baseline (speedup 1.0000x reference)
#include <cuda_runtime.h>
#include <math.h>

// ---------------------------------------------------------------------------
// EPA_Layer: B=16, H=W=64, C=256, HID=64
// Inputs (metadata order): x, Wq, Wk, Wvc, Wvs, Wc1, Wc2, Wconv, Wconvt, gamma, beta
// Output: float32 [16,64,64,256]
// ---------------------------------------------------------------------------

#define NB   16
#define NC   256
#define NH   64
#define NHW  4096       // 64*64
#define NM   65536      // B*H*W

// Scratch (bss, allocated at module load — no runtime allocation)
__device__ float g_q  [NB * NC * NHW];   // [B,C,H,W]
__device__ float g_k  [NB * NC * NHW];   // [B,C,H,W]
__device__ float g_vc [NM * NC];         // [B,H,W,C]
__device__ float g_vs [NM * NC];         // [B,H,W,C]
__device__ float g_as [NB * NC * NHW];   // attn_s [B,C,64,64] (logits -> softmaxed in place)
__device__ float g_ac [NB * NC * NHW];   // attn_c [B,C,64,64]
__device__ float g_c1 [NB * NC * 1024];  // conv3x3 out (relu) [B,C,32,32]
__device__ float g_sb [NB * NC * NHW];   // convT out (relu)   [B,C,64,64]
__device__ float g_wt2[4 * NC * 1024];   // packed convT weights per parity class [cl][co][ci*4+t]
__device__ float g_pool[NB * NC];
__device__ float g_gate[NB * NC];

// ---------------------------------------------------------------------------
// K1: fused 4-way projection GEMM.
// out[m,d] = sum_c X[m,c] * W[d,c];  X = x as [65536, 256]
// which = blockIdx.y>>2 selects Wq/Wk/Wvc/Wvs; q,k scattered to [B,C,HW],
// vc,vs stay [M,C].
// ---------------------------------------------------------------------------
__global__ __launch_bounds__(256) void k_proj(
    const float* __restrict__ x,
    const float* __restrict__ Wq, const float* __restrict__ Wk,
    const float* __restrict__ Wvc, const float* __restrict__ Wvs)
{
    __shared__ float As[16][68];
    __shared__ float Bs[16][68];
    int m0 = blockIdx.x << 6;
    int nb = blockIdx.y;
    int which = nb >> 2;
    int d0 = (nb & 3) << 6;
    const float* W = (which == 0) ? Wq : (which == 1) ? Wk : (which == 2) ? Wvc : Wvs;
    int tid = threadIdx.x;
    int tx = tid & 15, ty = tid >> 4;
    float acc[4][4] = {};

    for (int k0 = 0; k0 < 256; k0 += 16) {
        #pragma unroll
        for (int l = 0; l < 4; l++) {
            int idx = tid + l * 256;
            int row = idx >> 4, col = idx & 15;      // col-fast: coalesced over k
            As[col][row] = x[(size_t)(m0 + row) * 256 + k0 + col];
            Bs[col][row] = W[(size_t)(d0 + row) * 256 + k0 + col];
        }
        __syncthreads();
        #pragma unroll
        for (int kk = 0; kk < 16; kk++) {
            float4 av = *(const float4*)&As[kk][ty << 2];
            float4 bv = *(const float4*)&Bs[kk][tx << 2];
            float a[4] = {av.x, av.y, av.z, av.w};
            float b[4] = {bv.x, bv.y, bv.z, bv.w};
            #pragma unroll
            for (int i = 0; i < 4; i++)
                #pragma unroll
                for (int j = 0; j < 4; j++)
                    acc[i][j] += a[i] * b[j];
        }
        __syncthreads();
    }

    int b = m0 >> 12;
    if (which < 2) {
        float* dst = (which == 0) ? g_q : g_k;
        int hw0 = (m0 & 4095) + (ty << 2);
        #pragma unroll
        for (int j = 0; j < 4; j++) {
            int d = d0 + (tx << 2) + j;
            float4 v = make_float4(acc[0][j], acc[1][j], acc[2][j], acc[3][j]);
            *(float4*)&dst[(size_t)(b * 256 + d) * 4096 + hw0] = v;
        }
    } else {
        float* dst = (which == 2) ? g_vc : g_vs;
        #pragma unroll
        for (int i = 0; i < 4; i++) {
            int m = m0 + (ty << 2) + i;
            float4 v = make_float4(acc[i][0], acc[i][1], acc[i][2], acc[i][3]);
            *(float4*)&dst[(size_t)m * 256 + d0 + (tx << 2)] = v;
        }
    }
}

// ---------------------------------------------------------------------------
// K2: per-(b,c) attention logits.
//   S1[h,g] = sum_w Q[h,w]K[g,w]   -> g_as
//   S2[w,v] = sum_h Q[h,w]K[h,v]   -> g_ac
// One block per bc; Q/K slices are contiguous 16KB each.
// ---------------------------------------------------------------------------
__global__ __launch_bounds__(256) void k_attn(void)
{
    __shared__ float Qs[64][68];
    __shared__ float Ks[64][68];
    int bc = blockIdx.x;
    const float* Q = g_q + (size_t)bc * 4096;
    const float* K = g_k + (size_t)bc * 4096;
    int tid = threadIdx.x, tx = tid & 15, ty = tid >> 4;

    // ---- Phase 1: S1 = Q K^T. Store transposed: Qs[w][h] ----
    #pragma unroll
    for (int l = 0; l < 16; l++) {
        int idx = tid + l * 256;
        int h = idx >> 6, w = idx & 63;
        Qs[w][h] = Q[idx];
        Ks[w][h] = K[idx];
    }
    __syncthreads();
    {
        float acc[4][4] = {};
        for (int w = 0; w < 64; w++) {
            float4 av = *(const float4*)&Qs[w][ty << 2];   // Q[h][w], h block
            float4 bv = *(const float4*)&Ks[w][tx << 2];   // K[g][w], g block
            float a[4] = {av.x, av.y, av.z, av.w};
            float b[4] = {bv.x, bv.y, bv.z, bv.w};
            #pragma unroll
            for (int i = 0; i < 4; i++)
                #pragma unroll
                for (int j = 0; j < 4; j++)
                    acc[i][j] += a[i] * b[j];
        }
        float* out = g_as + (size_t)bc * 4096;
        #pragma unroll
        for (int i = 0; i < 4; i++) {
            float4 v = make_float4(acc[i][0], acc[i][1], acc[i][2], acc[i][3]);
            *(float4*)&out[((ty << 2) + i) * 64 + (tx << 2)] = v;
        }
    }
    __syncthreads();

    // ---- Phase 2: S2 = Q^T K. Natural layout: Qs[h][w] ----
    #pragma unroll
    for (int l = 0; l < 16; l++) {
        int idx = tid + l * 256;
        Qs[idx >> 6][idx & 63] = Q[idx];
        Ks[idx >> 6][idx & 63] = K[idx];
    }
    __syncthreads();
    {
        float acc[4][4] = {};
        for (int h = 0; h < 64; h++) {
            float4 av = *(const float4*)&Qs[h][ty << 2];   // Q[h][w], w block
            float4 bv = *(const float4*)&Ks[h][tx << 2];   // K[h][v], v block
            float a[4] = {av.x, av.y, av.z, av.w};
            float b[4] = {bv.x, bv.y, bv.z, bv.w};
            #pragma unroll
            for (int i = 0; i < 4; i++)
                #pragma unroll
                for (int j = 0; j < 4; j++)
                    acc[i][j] += a[i] * b[j];
        }
        float* out = g_ac + (size_t)bc * 4096;
        #pragma unroll
        for (int i = 0; i < 4; i++) {
            float4 v = make_float4(acc[i][0], acc[i][1], acc[i][2], acc[i][3]);
            *(float4*)&out[((ty << 2) + i) * 64 + (tx << 2)] = v;
        }
    }
}

// ---------------------------------------------------------------------------
// K3: softmax over the channel axis (stride 4096 floats) in place.
// One thread per (b, spatial) position; coalesced across threads per c-step.
// Online max/sum pass, then normalize pass.
// ---------------------------------------------------------------------------
__global__ __launch_bounds__(256) void k_softmax(int which)
{
    float* t = which ? g_ac : g_as;
    int p = blockIdx.x * 256 + threadIdx.x;   // 0..65535
    int b = p >> 12, pos = p & 4095;
    float* base = t + (size_t)b * (256 * 4096) + pos;
    float m = -3.0e38f, s = 0.f;
    for (int c = 0; c < 256; c++) {
        float v = base[(size_t)c << 12];
        float nm = fmaxf(m, v);
        s = s * __expf(m - nm) + __expf(v - nm);
        m = nm;
    }
    float inv = 1.0f / s;
    for (int c = 0; c < 256; c++) {
        size_t o = (size_t)c << 12;
        base[o] = __expf(base[o] - m) * inv;
    }
}

// ---------------------------------------------------------------------------
// K4: conv3x3 stride2 pad1 on softmax(attn_s), relu. Implicit GEMM:
// M=16384 (b,oy,ox), N=256 (co), K=2304 (ci,ky,kx). B = Wconv contiguous in k.
// ---------------------------------------------------------------------------
__global__ __launch_bounds__(256) void k_conv(const float* __restrict__ Wconv)
{
    __shared__ float As[16][68];
    __shared__ float Bs[16][68];
    int m0 = blockIdx.x << 6;
    int n0 = blockIdx.y << 6;
    int tid = threadIdx.x, tx = tid & 15, ty = tid >> 4;
    float acc[4][4] = {};

    for (int k0 = 0; k0 < 2304; k0 += 16) {
        #pragma unroll
        for (int l = 0; l < 4; l++) {
            int idx = tid + l * 256;
            // A: row-fast (m contiguous -> near-coalesced gather)
            int colA = idx >> 6, rowA = idx & 63;
            int kk = k0 + colA;
            int ci = kk / 9;
            int t9 = kk - ci * 9;
            int ky = t9 / 3;
            int kx = t9 - ky * 3;
            int m = m0 + rowA;
            int b = m >> 10, r = m & 1023;
            int oy = r >> 5, ox = r & 31;
            int iy = 2 * oy - 1 + ky, ix = 2 * ox - 1 + kx;
            float v = 0.f;
            if ((unsigned)iy < 64u && (unsigned)ix < 64u)
                v = g_as[(((size_t)b * 256 + ci) * 64 + iy) * 64 + ix];
            As[colA][rowA] = v;
            // B: col-fast (k contiguous -> coalesced)
            int colB = idx & 15, rowB = idx >> 4;
            Bs[colB][rowB] = Wconv[(size_t)(n0 + rowB) * 2304 + k0 + colB];
        }
        __syncthreads();
        #pragma unroll
        for (int kk = 0; kk < 16; kk++) {
            float4 av = *(const float4*)&As[kk][ty << 2];
            float4 bv = *(const float4*)&Bs[kk][tx << 2];
            float a[4] = {av.x, av.y, av.z, av.w};
            float b[4] = {bv.x, bv.y, bv.z, bv.w};
            #pragma unroll
            for (int i = 0; i < 4; i++)
                #pragma unroll
                for (int j = 0; j < 4; j++)
                    acc[i][j] += a[i] * b[j];
        }
        __syncthreads();
    }

    int b = m0 >> 10;
    int mbase = m0 + (ty << 2);
    int r0 = mbase & 1023;
    int oy = r0 >> 5, ox0 = r0 & 31;
    #pragma unroll
    for (int j = 0; j < 4; j++) {
        int co = n0 + (tx << 2) + j;
        float4 v = make_float4(fmaxf(acc[0][j], 0.f), fmaxf(acc[1][j], 0.f),
                               fmaxf(acc[2][j], 0.f), fmaxf(acc[3][j], 0.f));
        *(float4*)&g_c1[(((size_t)b * 256 + co) * 32 + oy) * 32 + ox0] = v;
    }
}

// ---------------------------------------------------------------------------
// K5: pack convT weights per output parity class.
// Wt2[cl][co][ci*4+t] = Wconvt[ci][co][1-py+2*ty][1-px+2*tx]
// ---------------------------------------------------------------------------
__global__ void k_packwt(const float* __restrict__ Wconvt)
{
    int i = blockIdx.x * 256 + threadIdx.x;       // 4*256*1024
    int cl = i >> 18;
    int rem = i & 262143;
    int co = rem >> 10;
    int k = rem & 1023;
    int ci = k >> 2, t = k & 3;
    int tyk = t >> 1, txk = t & 1;
    int py = cl >> 1, px = cl & 1;
    int ky = 1 - py + 2 * tyk, kx = 1 - px + 2 * txk;
    g_wt2[i] = Wconvt[(((size_t)ci * 256 + co) * 4 + ky) * 4 + kx];
}

// ---------------------------------------------------------------------------
// K6: convT 4x4 stride2 pad1 + relu, by parity class (blockIdx.z).
// For class (py,px): out(y=2ys+py, x=2xs+px) = sum_{ci,ty,tx} c1[ci][ys+py-ty][xs+px-tx] * Wt2
// Implicit GEMM: M=16384 (b,ys,xs), N=256 (co), K=1024 (ci,t).
// ---------------------------------------------------------------------------
__global__ __launch_bounds__(256) void k_convt(void)
{
    __shared__ float As[16][68];
    __shared__ float Bs[16][68];
    int cl = blockIdx.z;
    int py = cl >> 1, px = cl & 1;
    int m0 = blockIdx.x << 6;
    int n0 = blockIdx.y << 6;
    int tid = threadIdx.x, tx = tid & 15, ty = tid >> 4;
    float acc[4][4] = {};

    for (int k0 = 0; k0 < 1024; k0 += 16) {
        #pragma unroll
        for (int l = 0; l < 4; l++) {
            int idx = tid + l * 256;
            int colA = idx >> 6, rowA = idx & 63;
            int kk = k0 + colA;
            int ci = kk >> 2, t = kk & 3;
            int tyk = t >> 1, txk = t & 1;
            int m = m0 + rowA;
            int b = m >> 10;
            int ys = (m >> 5) & 31, xs = m & 31;
            int ii = ys + py - tyk, jj = xs + px - txk;
            float v = 0.f;
            if ((unsigned)ii < 32u && (unsigned)jj < 32u)
                v = g_c1[(((size_t)b * 256 + ci) * 32 + ii) * 32 + jj];
            As[colA][rowA] = v;
            int colB = idx & 15, rowB = idx >> 4;
            Bs[colB][rowB] = g_wt2[((size_t)cl * 256 + n0 + rowB) * 1024 + k0 + colB];
        }
        __syncthreads();
        #pragma unroll
        for (int kk = 0; kk < 16; kk++) {
            float4 av = *(const float4*)&As[kk][ty << 2];
            float4 bv = *(const float4*)&Bs[kk][tx << 2];
            float a[4] = {av.x, av.y, av.z, av.w};
            float b[4] = {bv.x, bv.y, bv.z, bv.w};
            #pragma unroll
            for (int i = 0; i < 4; i++)
                #pragma unroll
                for (int j = 0; j < 4; j++)
                    acc[i][j] += a[i] * b[j];
        }
        __syncthreads();
    }

    int b = m0 >> 10;
    #pragma unroll
    for (int i = 0; i < 4; i++) {
        int m = m0 + (ty << 2) + i;
        int ys = (m >> 5) & 31, xs = m & 31;
        int y = 2 * ys + py, x2 = 2 * xs + px;
        #pragma unroll
        for (int j = 0; j < 4; j++) {
            int co = n0 + (tx << 2) + j;
            g_sb[(((size_t)b * 256 + co) * 64 + y) * 64 + x2] = fmaxf(acc[i][j], 0.f);
        }
    }
}

// ---------------------------------------------------------------------------
// K7: global mean pool of softmax(attn_c) per (b,c)
// ---------------------------------------------------------------------------
__global__ __launch_bounds__(256) void k_pool(void)
{
    int bc = blockIdx.x;
    const float* p = g_ac + (size_t)bc * 4096;
    float s = 0.f;
    for (int i = threadIdx.x; i < 4096; i += 256) s += p[i];
    __shared__ float red[8];
    #pragma unroll
    for (int o = 16; o > 0; o >>= 1) s += __shfl_down_sync(0xffffffffu, s, o);
    int w = threadIdx.x >> 5;
    if ((threadIdx.x & 31) == 0) red[w] = s;
    __syncthreads();
    if (threadIdx.x == 0) {
        float t = 0.f;
        #pragma unroll
        for (int i = 0; i < 8; i++) t += red[i];
        g_pool[bc] = t * (1.0f / 4096.0f);
    }
}

// ---------------------------------------------------------------------------
// K8: SE MLP: gate = sigmoid(relu(pool @ Wc1^T) @ Wc2^T)
// ---------------------------------------------------------------------------
__global__ __launch_bounds__(256) void k_se(const float* __restrict__ Wc1,
                                            const float* __restrict__ Wc2)
{
    int b = blockIdx.x;
    __shared__ float pool[256];
    __shared__ float hid[64];
    int t = threadIdx.x;
    pool[t] = g_pool[b * 256 + t];
    __syncthreads();
    if (t < 64) {
        float s = 0.f;
        for (int c = 0; c < 256; c++) s += pool[c] * Wc1[t * 256 + c];
        hid[t] = fmaxf(s, 0.f);
    }
    __syncthreads();
    float s = 0.f;
    #pragma unroll
    for (int j = 0; j < 64; j++) s += hid[j] * Wc2[t * 64 + j];
    g_gate[b * 256 + t] = 1.0f / (1.0f + __expf(-s));
}

// ---------------------------------------------------------------------------
// K9: fused residual + LayerNorm over C.
// y = x + s[b,c,h,w]*vs + gate[b,c]*attn_c[b,c,h,w]*vc; LN over c.
// One block per spatial position; c = threadIdx.x.
// ---------------------------------------------------------------------------
__global__ __launch_bounds__(256) void k_fuse(const float* __restrict__ x,
                                              const float* __restrict__ gamma,
                                              const float* __restrict__ beta,
                                              float* __restrict__ out)
{
    int m = blockIdx.x;              // 0..65535
    int b = m >> 12, hw = m & 4095;
    int c = threadIdx.x;
    size_t chw = ((size_t)(b * 256 + c)) * 4096 + hw;
    size_t mi = (size_t)m * 256 + c;
    float sv = g_sb[chw];
    float av = g_ac[chw];
    float gt = g_gate[b * 256 + c];
    float y = x[mi] + sv * g_vs[mi] + gt * av * g_vc[mi];

    float s1 = y, s2 = y * y;
    #pragma unroll
    for (int o = 16; o > 0; o >>= 1) {
        s1 += __shfl_down_sync(0xffffffffu, s1, o);
        s2 += __shfl_down_sync(0xffffffffu, s2, o);
    }
    __shared__ float ra[8], rb[8], fin[2];
    int w = c >> 5;
    if ((c & 31) == 0) { ra[w] = s1; rb[w] = s2; }
    __syncthreads();
    if (c == 0) {
        float a = 0.f, bb = 0.f;
        #pragma unroll
        for (int i = 0; i < 8; i++) { a += ra[i]; bb += rb[i]; }
        fin[0] = a; fin[1] = bb;
    }
    __syncthreads();
    float mu = fin[0] * (1.0f / 256.0f);
    float var = fin[1] * (1.0f / 256.0f) - mu * mu;
    out[mi] = (y - mu) * rsqrtf(var + 1e-5f) * gamma[c] + beta[c];
}

// ---------------------------------------------------------------------------
extern "C" void kernel_launch(void* const* d_in, const int* in_sizes, int n_in,
                              void* d_out, int out_size)
{
    const float* x      = (const float*)d_in[0];
    const float* Wq     = (const float*)d_in[1];
    const float* Wk     = (const float*)d_in[2];
    const float* Wvc    = (const float*)d_in[3];
    const float* Wvs    = (const float*)d_in[4];
    const float* Wc1    = (const float*)d_in[5];
    const float* Wc2    = (const float*)d_in[6];
    const float* Wconv  = (const float*)d_in[7];
    const float* Wconvt = (const float*)d_in[8];
    const float* gamma  = (const float*)d_in[9];
    const float* beta   = (const float*)d_in[10];
    float* out = (float*)d_out;

    // projections (q,k -> [B,C,HW]; vc,vs -> [M,C])
    k_proj<<<dim3(1024, 16), 256>>>(x, Wq, Wk, Wvc, Wvs);
    // attention logits per (b,c)
    k_attn<<<4096, 256>>>();
    // channel softmax (in place)
    k_softmax<<<256, 256>>>(0);   // attn_s
    k_softmax<<<256, 256>>>(1);   // attn_c
    // convT weight repack (independent of above)
    k_packwt<<<4096, 256>>>(Wconvt);
    // spatial branch
    k_conv<<<dim3(256, 4), 256>>>(Wconv);
    k_convt<<<dim3(256, 4, 4), 256>>>();
    // channel branch
    k_pool<<<4096, 256>>>();
    k_se<<<16, 256>>>(Wc1, Wc2);
    // fuse + layernorm
    k_fuse<<<65536, 256>>>(x, gamma, beta, out);
}

// round 3
// speedup vs baseline: 2.0851x; 2.0851x over previous
#include <cuda_runtime.h>
#include <math.h>

// ---------------------------------------------------------------------------
// EPA_Layer: B=16, H=W=64, C=256, HID=64
// Inputs: x, Wq, Wk, Wvc, Wvs, Wc1, Wc2, Wconv, Wconvt, gamma, beta
// Output: float32 [16,64,64,256]
// Round 3 (= Round 2 resubmit after infra failure):
// all GEMMs on tensor cores (mma.sync m16n8k8 tf32, fp32 accum)
// ---------------------------------------------------------------------------

#define NB   16
#define NC   256
#define NHW  4096
#define NM   65536

__device__ float g_q  [NB * NC * NHW];   // [B,C,H,W]
__device__ float g_k  [NB * NC * NHW];   // [B,C,H,W]
__device__ float g_vc [NM * NC];         // [B,H,W,C]
__device__ float g_vs [NM * NC];         // [B,H,W,C]
__device__ float g_as [NB * NC * NHW];   // attn_s [B,C,64,64]
__device__ float g_ac [NB * NC * NHW];   // attn_c [B,C,64,64]
__device__ float g_c1 [NB * NC * 1024];  // conv3x3+relu [B,C,32,32]
__device__ float g_sb [NB * NC * NHW];   // convT+relu   [B,C,64,64]
__device__ float g_wt2[4 * NC * 1024];   // packed convT weights [cl][co][ci*4+t]
__device__ float g_pool[NB * NC];
__device__ float g_gate[NB * NC];

__device__ __forceinline__ unsigned f2tf(float x) {
    unsigned u; asm("cvt.rna.tf32.f32 %0, %1;" : "=r"(u) : "f"(x)); return u;
}

__device__ __forceinline__ void mma_tf32(float* c, const unsigned* a, const unsigned* b) {
    asm volatile(
        "mma.sync.aligned.m16n8k8.row.col.f32.tf32.tf32.f32 "
        "{%0,%1,%2,%3}, {%4,%5,%6,%7}, {%8,%9}, {%0,%1,%2,%3};"
        : "+f"(c[0]), "+f"(c[1]), "+f"(c[2]), "+f"(c[3])
        : "r"(a[0]), "r"(a[1]), "r"(a[2]), "r"(a[3]), "r"(b[0]), "r"(b[1]));
}

// ---------------------------------------------------------------------------
// K1: fused 4-way projection GEMM (tensor core).
// out[m,d] = sum_c X[m,c] * W[d,c]; BM=128, BN=64, BK=16.
// ---------------------------------------------------------------------------
__global__ __launch_bounds__(256) void k_proj(
    const float* __restrict__ x,
    const float* __restrict__ Wq, const float* __restrict__ Wk,
    const float* __restrict__ Wvc, const float* __restrict__ Wvs)
{
    __shared__ unsigned As[128][20];
    __shared__ unsigned Bs[64][20];
    int m0 = blockIdx.x << 7;
    int nb = blockIdx.y;
    int which = nb >> 2;
    int d0 = (nb & 3) << 6;
    const float* W = (which == 0) ? Wq : (which == 1) ? Wk : (which == 2) ? Wvc : Wvs;
    int tid = threadIdx.x, lane = tid & 31, wid = tid >> 5;
    int warpM = wid >> 1, warpN = wid & 1;
    int g = lane >> 2, tig = lane & 3;
    int am = tid >> 2, akq = tid & 3;
    float acc[2][4][4] = {};
    float4 ra0, ra1, rbv;

    auto gload = [&](int k0) {
        ra0 = *(const float4*)&x[(size_t)(m0 + am) * 256 + k0 + (akq << 2)];
        ra1 = *(const float4*)&x[(size_t)(m0 + am + 64) * 256 + k0 + (akq << 2)];
        rbv = *(const float4*)&W[(size_t)(d0 + am) * 256 + k0 + (akq << 2)];
    };
    auto sstore = [&]() {
        *(uint4*)&As[am][akq << 2] =
            make_uint4(f2tf(ra0.x), f2tf(ra0.y), f2tf(ra0.z), f2tf(ra0.w));
        *(uint4*)&As[am + 64][akq << 2] =
            make_uint4(f2tf(ra1.x), f2tf(ra1.y), f2tf(ra1.z), f2tf(ra1.w));
        *(uint4*)&Bs[am][akq << 2] =
            make_uint4(f2tf(rbv.x), f2tf(rbv.y), f2tf(rbv.z), f2tf(rbv.w));
    };

    gload(0); sstore(); __syncthreads();
    for (int k0 = 0; k0 < 256; k0 += 16) {
        bool more = (k0 + 16) < 256;
        if (more) gload(k0 + 16);
        #pragma unroll
        for (int ks = 0; ks < 2; ks++) {
            int kk = ks << 3;
            unsigned a[2][4], b[4][2];
            #pragma unroll
            for (int mt = 0; mt < 2; mt++) {
                int row = (warpM << 5) + (mt << 4) + g;
                a[mt][0] = As[row][kk + tig];     a[mt][1] = As[row + 8][kk + tig];
                a[mt][2] = As[row][kk + tig + 4]; a[mt][3] = As[row + 8][kk + tig + 4];
            }
            #pragma unroll
            for (int nt = 0; nt < 4; nt++) {
                int col = (warpN << 5) + (nt << 3) + g;
                b[nt][0] = Bs[col][kk + tig]; b[nt][1] = Bs[col][kk + tig + 4];
            }
            #pragma unroll
            for (int mt = 0; mt < 2; mt++)
                #pragma unroll
                for (int nt = 0; nt < 4; nt++)
                    mma_tf32(acc[mt][nt], a[mt], b[nt]);
        }
        __syncthreads();
        if (more) { sstore(); __syncthreads(); }
    }

    int b = m0 >> 12;
    int hw0 = m0 & 4095;
    if (which < 2) {
        float* dst = (which == 0) ? g_q : g_k;
        #pragma unroll
        for (int mt = 0; mt < 2; mt++)
            #pragma unroll
            for (int nt = 0; nt < 4; nt++) {
                int row = (warpM << 5) + (mt << 4) + g;
                int col = (warpN << 5) + (nt << 3) + (tig << 1);
                float* c = acc[mt][nt];
                size_t bi = (size_t)((b << 8) + d0 + col) * 4096 + hw0;
                dst[bi + row]            = c[0];
                dst[bi + 4096 + row]     = c[1];
                dst[bi + row + 8]        = c[2];
                dst[bi + 4096 + row + 8] = c[3];
            }
    } else {
        float* dst = (which == 2) ? g_vc : g_vs;
        #pragma unroll
        for (int mt = 0; mt < 2; mt++)
            #pragma unroll
            for (int nt = 0; nt < 4; nt++) {
                int row = (warpM << 5) + (mt << 4) + g;
                int col = (warpN << 5) + (nt << 3) + (tig << 1);
                float* c = acc[mt][nt];
                *(float2*)&dst[(size_t)(m0 + row) * 256 + d0 + col] =
                    make_float2(c[0], c[1]);
                *(float2*)&dst[(size_t)(m0 + row + 8) * 256 + d0 + col] =
                    make_float2(c[2], c[3]);
            }
    }
}

// ---------------------------------------------------------------------------
// K2: per-(b,c) attention logits (tensor core). One smem image of Q,K ([h][w])
// serves both phases: phase1 S1=Q K^T, phase2 S2=Q^T K (read transposed).
// 8 warps; each computes a 16x32 output tile per phase.
// ---------------------------------------------------------------------------
__global__ __launch_bounds__(256) void k_attn(void)
{
    __shared__ unsigned Qs[64][68];
    __shared__ unsigned Ks[64][68];
    int bc = blockIdx.x;
    const float* Q = g_q + (size_t)bc * 4096;
    const float* K = g_k + (size_t)bc * 4096;
    int tid = threadIdx.x, lane = tid & 31, wid = tid >> 5;
    int warpM = wid >> 1, warpN = wid & 1;
    int g = lane >> 2, tig = lane & 3;

    #pragma unroll
    for (int l = 0; l < 16; l++) {
        int idx = tid + (l << 8);
        Qs[idx >> 6][idx & 63] = f2tf(Q[idx]);
        Ks[idx >> 6][idx & 63] = f2tf(K[idx]);
    }
    __syncthreads();

    // Phase 1: S1[h][gg] = sum_w Q[h][w] K[gg][w]
    {
        float acc[4][4] = {};
        #pragma unroll
        for (int ks = 0; ks < 8; ks++) {
            int kk = ks << 3;
            unsigned a[4], b[4][2];
            int row = (warpM << 4) + g;
            a[0] = Qs[row][kk + tig];     a[1] = Qs[row + 8][kk + tig];
            a[2] = Qs[row][kk + tig + 4]; a[3] = Qs[row + 8][kk + tig + 4];
            #pragma unroll
            for (int nt = 0; nt < 4; nt++) {
                int col = (warpN << 5) + (nt << 3) + g;
                b[nt][0] = Ks[col][kk + tig]; b[nt][1] = Ks[col][kk + tig + 4];
            }
            #pragma unroll
            for (int nt = 0; nt < 4; nt++) mma_tf32(acc[nt], a, b[nt]);
        }
        float* out = g_as + (size_t)bc * 4096;
        #pragma unroll
        for (int nt = 0; nt < 4; nt++) {
            int row = (warpM << 4) + g;
            int col = (warpN << 5) + (nt << 3) + (tig << 1);
            *(float2*)&out[row * 64 + col]       = make_float2(acc[nt][0], acc[nt][1]);
            *(float2*)&out[(row + 8) * 64 + col] = make_float2(acc[nt][2], acc[nt][3]);
        }
    }
    // Phase 2: S2[w][v] = sum_h Q[h][w] K[h][v]  (same smem, transposed reads)
    {
        float acc[4][4] = {};
        #pragma unroll
        for (int ks = 0; ks < 8; ks++) {
            int kk = ks << 3;
            unsigned a[4], b[4][2];
            int row = (warpM << 4) + g;
            a[0] = Qs[kk + tig][row];     a[1] = Qs[kk + tig][row + 8];
            a[2] = Qs[kk + tig + 4][row]; a[3] = Qs[kk + tig + 4][row + 8];
            #pragma unroll
            for (int nt = 0; nt < 4; nt++) {
                int col = (warpN << 5) + (nt << 3) + g;
                b[nt][0] = Ks[kk + tig][col]; b[nt][1] = Ks[kk + tig + 4][col];
            }
            #pragma unroll
            for (int nt = 0; nt < 4; nt++) mma_tf32(acc[nt], a, b[nt]);
        }
        float* out = g_ac + (size_t)bc * 4096;
        #pragma unroll
        for (int nt = 0; nt < 4; nt++) {
            int row = (warpM << 4) + g;
            int col = (warpN << 5) + (nt << 3) + (tig << 1);
            *(float2*)&out[row * 64 + col]       = make_float2(acc[nt][0], acc[nt][1]);
            *(float2*)&out[(row + 8) * 64 + col] = make_float2(acc[nt][2], acc[nt][3]);
        }
    }
}

// ---------------------------------------------------------------------------
// K3: channel softmax (axis c, stride 4096) in place.
// blockIdx.y selects tensor (0 = attn_s, 1 = attn_c).
// ---------------------------------------------------------------------------
__global__ __launch_bounds__(256) void k_softmax(void)
{
    float* t = blockIdx.y ? g_ac : g_as;
    int p = blockIdx.x * 256 + threadIdx.x;
    int b = p >> 12, pos = p & 4095;
    float* base = t + (size_t)b * (256 * 4096) + pos;
    float m = -3.0e38f, s = 0.f;
    for (int c = 0; c < 256; c++) {
        float v = base[(size_t)c << 12];
        float nm = fmaxf(m, v);
        s = s * __expf(m - nm) + __expf(v - nm);
        m = nm;
    }
    float inv = 1.0f / s;
    for (int c = 0; c < 256; c++) {
        size_t o = (size_t)c << 12;
        base[o] = __expf(base[o] - m) * inv;
    }
}

// ---------------------------------------------------------------------------
// K4: conv3x3 s2 p1 + relu on attn_s (tensor core implicit GEMM).
// M=16384, N=256, K=2304.
// ---------------------------------------------------------------------------
__global__ __launch_bounds__(256) void k_conv(const float* __restrict__ Wconv)
{
    __shared__ unsigned As[16][136];
    __shared__ unsigned Bs[64][20];
    int m0 = blockIdx.x << 7;
    int n0 = blockIdx.y << 6;
    int tid = threadIdx.x, lane = tid & 31, wid = tid >> 5;
    int warpM = wid >> 1, warpN = wid & 1;
    int g = lane >> 2, tig = lane & 3;
    int b = m0 >> 10;
    float acc[2][4][4] = {};
    float rga[8]; float4 rgb;

    auto gload = [&](int k0) {
        #pragma unroll
        for (int l = 0; l < 8; l++) {
            int idx = tid + (l << 8);
            int kcol = idx >> 7, m = idx & 127;
            int kk = k0 + kcol;
            int ci = kk / 9;
            int t9 = kk - ci * 9;
            int ky = t9 / 3;
            int kx = t9 - ky * 3;
            int r = (m0 + m) & 1023;
            int oy = r >> 5, ox = r & 31;
            int iy = 2 * oy - 1 + ky, ix = 2 * ox - 1 + kx;
            float v = 0.f;
            if ((unsigned)iy < 64u && (unsigned)ix < 64u)
                v = g_as[(((size_t)(b << 8) + ci) * 64 + iy) * 64 + ix];
            rga[l] = v;
        }
        rgb = *(const float4*)&Wconv[(size_t)(n0 + (tid >> 2)) * 2304 + k0 + ((tid & 3) << 2)];
    };
    auto sstore = [&]() {
        #pragma unroll
        for (int l = 0; l < 8; l++) {
            int idx = tid + (l << 8);
            As[idx >> 7][idx & 127] = f2tf(rga[l]);
        }
        *(uint4*)&Bs[tid >> 2][(tid & 3) << 2] =
            make_uint4(f2tf(rgb.x), f2tf(rgb.y), f2tf(rgb.z), f2tf(rgb.w));
    };

    gload(0); sstore(); __syncthreads();
    for (int k0 = 0; k0 < 2304; k0 += 16) {
        bool more = (k0 + 16) < 2304;
        if (more) gload(k0 + 16);
        #pragma unroll
        for (int ks = 0; ks < 2; ks++) {
            int kk = ks << 3;
            unsigned a[2][4], bfr[4][2];
            #pragma unroll
            for (int mt = 0; mt < 2; mt++) {
                int row = (warpM << 5) + (mt << 4) + g;
                a[mt][0] = As[kk + tig][row];     a[mt][1] = As[kk + tig][row + 8];
                a[mt][2] = As[kk + tig + 4][row]; a[mt][3] = As[kk + tig + 4][row + 8];
            }
            #pragma unroll
            for (int nt = 0; nt < 4; nt++) {
                int col = (warpN << 5) + (nt << 3) + g;
                bfr[nt][0] = Bs[col][kk + tig]; bfr[nt][1] = Bs[col][kk + tig + 4];
            }
            #pragma unroll
            for (int mt = 0; mt < 2; mt++)
                #pragma unroll
                for (int nt = 0; nt < 4; nt++)
                    mma_tf32(acc[mt][nt], a[mt], bfr[nt]);
        }
        __syncthreads();
        if (more) { sstore(); __syncthreads(); }
    }

    #pragma unroll
    for (int mt = 0; mt < 2; mt++)
        #pragma unroll
        for (int nt = 0; nt < 4; nt++) {
            int row = (warpM << 5) + (mt << 4) + g;
            int col = n0 + (warpN << 5) + (nt << 3) + (tig << 1);
            float* c = acc[mt][nt];
            int r1 = (m0 + row) & 1023;
            size_t b1 = (((size_t)(b << 8) + col) << 10) + r1;
            g_c1[b1]        = fmaxf(c[0], 0.f);
            g_c1[b1 + 1024] = fmaxf(c[1], 0.f);
            int r2 = (m0 + row + 8) & 1023;
            size_t b2 = (((size_t)(b << 8) + col) << 10) + r2;
            g_c1[b2]        = fmaxf(c[2], 0.f);
            g_c1[b2 + 1024] = fmaxf(c[3], 0.f);
        }
}

// ---------------------------------------------------------------------------
// K5: pack convT weights per parity class.
// ---------------------------------------------------------------------------
__global__ void k_packwt(const float* __restrict__ Wconvt)
{
    int i = blockIdx.x * 256 + threadIdx.x;
    int cl = i >> 18;
    int rem = i & 262143;
    int co = rem >> 10;
    int k = rem & 1023;
    int ci = k >> 2, t = k & 3;
    int tyk = t >> 1, txk = t & 1;
    int py = cl >> 1, px = cl & 1;
    int ky = 1 - py + 2 * tyk, kx = 1 - px + 2 * txk;
    g_wt2[i] = Wconvt[(((size_t)ci * 256 + co) * 4 + ky) * 4 + kx];
}

// ---------------------------------------------------------------------------
// K6: convT 4x4 s2 p1 + relu by parity class (tensor core implicit GEMM).
// M=16384, N=256, K=1024 per class.
// ---------------------------------------------------------------------------
__global__ __launch_bounds__(256) void k_convt(void)
{
    __shared__ unsigned As[16][136];
    __shared__ unsigned Bs[64][20];
    int cl = blockIdx.z;
    int py = cl >> 1, px = cl & 1;
    int m0 = blockIdx.x << 7;
    int n0 = blockIdx.y << 6;
    int tid = threadIdx.x, lane = tid & 31, wid = tid >> 5;
    int warpM = wid >> 1, warpN = wid & 1;
    int g = lane >> 2, tig = lane & 3;
    int b = m0 >> 10;
    float acc[2][4][4] = {};
    float rga[8]; float4 rgb;

    auto gload = [&](int k0) {
        #pragma unroll
        for (int l = 0; l < 8; l++) {
            int idx = tid + (l << 8);
            int kcol = idx >> 7, m = idx & 127;
            int kk = k0 + kcol;
            int ci = kk >> 2, t = kk & 3;
            int tyk = t >> 1, txk = t & 1;
            int mm = m0 + m;
            int ys = (mm >> 5) & 31, xs = mm & 31;
            int ii = ys + py - tyk, jj = xs + px - txk;
            float v = 0.f;
            if ((unsigned)ii < 32u && (unsigned)jj < 32u)
                v = g_c1[(((size_t)(b << 8) + ci) << 10) + (ii << 5) + jj];
            rga[l] = v;
        }
        rgb = *(const float4*)&g_wt2[((size_t)(cl << 8) + n0 + (tid >> 2)) * 1024 + k0 + ((tid & 3) << 2)];
    };
    auto sstore = [&]() {
        #pragma unroll
        for (int l = 0; l < 8; l++) {
            int idx = tid + (l << 8);
            As[idx >> 7][idx & 127] = f2tf(rga[l]);
        }
        *(uint4*)&Bs[tid >> 2][(tid & 3) << 2] =
            make_uint4(f2tf(rgb.x), f2tf(rgb.y), f2tf(rgb.z), f2tf(rgb.w));
    };

    gload(0); sstore(); __syncthreads();
    for (int k0 = 0; k0 < 1024; k0 += 16) {
        bool more = (k0 + 16) < 1024;
        if (more) gload(k0 + 16);
        #pragma unroll
        for (int ks = 0; ks < 2; ks++) {
            int kk = ks << 3;
            unsigned a[2][4], bfr[4][2];
            #pragma unroll
            for (int mt = 0; mt < 2; mt++) {
                int row = (warpM << 5) + (mt << 4) + g;
                a[mt][0] = As[kk + tig][row];     a[mt][1] = As[kk + tig][row + 8];
                a[mt][2] = As[kk + tig + 4][row]; a[mt][3] = As[kk + tig + 4][row + 8];
            }
            #pragma unroll
            for (int nt = 0; nt < 4; nt++) {
                int col = (warpN << 5) + (nt << 3) + g;
                bfr[nt][0] = Bs[col][kk + tig]; bfr[nt][1] = Bs[col][kk + tig + 4];
            }
            #pragma unroll
            for (int mt = 0; mt < 2; mt++)
                #pragma unroll
                for (int nt = 0; nt < 4; nt++)
                    mma_tf32(acc[mt][nt], a[mt], bfr[nt]);
        }
        __syncthreads();
        if (more) { sstore(); __syncthreads(); }
    }

    #pragma unroll
    for (int mt = 0; mt < 2; mt++)
        #pragma unroll
        for (int nt = 0; nt < 4; nt++) {
            int row = (warpM << 5) + (mt << 4) + g;
            int col = n0 + (warpN << 5) + (nt << 3) + (tig << 1);
            float* c = acc[mt][nt];
            int mm1 = m0 + row;
            int ys1 = (mm1 >> 5) & 31, xs1 = mm1 & 31;
            size_t b1 = (((size_t)(b << 8) + col) << 12) +
                        ((2 * ys1 + py) << 6) + (2 * xs1 + px);
            g_sb[b1]        = fmaxf(c[0], 0.f);
            g_sb[b1 + 4096] = fmaxf(c[1], 0.f);
            int mm2 = mm1 + 8;
            int ys2 = (mm2 >> 5) & 31, xs2 = mm2 & 31;
            size_t b2 = (((size_t)(b << 8) + col) << 12) +
                        ((2 * ys2 + py) << 6) + (2 * xs2 + px);
            g_sb[b2]        = fmaxf(c[2], 0.f);
            g_sb[b2 + 4096] = fmaxf(c[3], 0.f);
        }
}

// ---------------------------------------------------------------------------
// K7: global mean pool of attn_c per (b,c)
// ---------------------------------------------------------------------------
__global__ __launch_bounds__(256) void k_pool(void)
{
    int bc = blockIdx.x;
    const float* p = g_ac + (size_t)bc * 4096;
    float s = 0.f;
    for (int i = threadIdx.x; i < 4096; i += 256) s += p[i];
    __shared__ float red[8];
    #pragma unroll
    for (int o = 16; o > 0; o >>= 1) s += __shfl_down_sync(0xffffffffu, s, o);
    int w = threadIdx.x >> 5;
    if ((threadIdx.x & 31) == 0) red[w] = s;
    __syncthreads();
    if (threadIdx.x == 0) {
        float t = 0.f;
        #pragma unroll
        for (int i = 0; i < 8; i++) t += red[i];
        g_pool[bc] = t * (1.0f / 4096.0f);
    }
}

// ---------------------------------------------------------------------------
// K8: SE MLP
// ---------------------------------------------------------------------------
__global__ __launch_bounds__(256) void k_se(const float* __restrict__ Wc1,
                                            const float* __restrict__ Wc2)
{
    int b = blockIdx.x;
    __shared__ float pool[256];
    __shared__ float hid[64];
    int t = threadIdx.x;
    pool[t] = g_pool[b * 256 + t];
    __syncthreads();
    if (t < 64) {
        float s = 0.f;
        for (int c = 0; c < 256; c++) s += pool[c] * Wc1[t * 256 + c];
        hid[t] = fmaxf(s, 0.f);
    }
    __syncthreads();
    float s = 0.f;
    #pragma unroll
    for (int j = 0; j < 64; j++) s += hid[j] * Wc2[t * 64 + j];
    g_gate[b * 256 + t] = 1.0f / (1.0f + __expf(-s));
}

// ---------------------------------------------------------------------------
// K9: fused residual + LayerNorm over C.
// ---------------------------------------------------------------------------
__global__ __launch_bounds__(256) void k_fuse(const float* __restrict__ x,
                                              const float* __restrict__ gamma,
                                              const float* __restrict__ beta,
                                              float* __restrict__ out)
{
    int m = blockIdx.x;
    int b = m >> 12, hw = m & 4095;
    int c = threadIdx.x;
    size_t chw = ((size_t)(b * 256 + c)) * 4096 + hw;
    size_t mi = (size_t)m * 256 + c;
    float sv = g_sb[chw];
    float av = g_ac[chw];
    float gt = g_gate[b * 256 + c];
    float y = x[mi] + sv * g_vs[mi] + gt * av * g_vc[mi];

    float s1 = y, s2 = y * y;
    #pragma unroll
    for (int o = 16; o > 0; o >>= 1) {
        s1 += __shfl_down_sync(0xffffffffu, s1, o);
        s2 += __shfl_down_sync(0xffffffffu, s2, o);
    }
    __shared__ float ra[8], rb[8], fin[2];
    int w = c >> 5;
    if ((c & 31) == 0) { ra[w] = s1; rb[w] = s2; }
    __syncthreads();
    if (c == 0) {
        float a = 0.f, bb = 0.f;
        #pragma unroll
        for (int i = 0; i < 8; i++) { a += ra[i]; bb += rb[i]; }
        fin[0] = a; fin[1] = bb;
    }
    __syncthreads();
    float mu = fin[0] * (1.0f / 256.0f);
    float var = fin[1] * (1.0f / 256.0f) - mu * mu;
    out[mi] = (y - mu) * rsqrtf(var + 1e-5f) * gamma[c] + beta[c];
}

// ---------------------------------------------------------------------------
extern "C" void kernel_launch(void* const* d_in, const int* in_sizes, int n_in,
                              void* d_out, int out_size)
{
    const float* x      = (const float*)d_in[0];
    const float* Wq     = (const float*)d_in[1];
    const float* Wk     = (const float*)d_in[2];
    const float* Wvc    = (const float*)d_in[3];
    const float* Wvs    = (const float*)d_in[4];
    const float* Wc1    = (const float*)d_in[5];
    const float* Wc2    = (const float*)d_in[6];
    const float* Wconv  = (const float*)d_in[7];
    const float* Wconvt = (const float*)d_in[8];
    const float* gamma  = (const float*)d_in[9];
    const float* beta   = (const float*)d_in[10];
    float* out = (float*)d_out;

    k_proj<<<dim3(512, 16), 256>>>(x, Wq, Wk, Wvc, Wvs);
    k_attn<<<4096, 256>>>();
    k_softmax<<<dim3(256, 2), 256>>>();
    k_packwt<<<4096, 256>>>(Wconvt);
    k_conv<<<dim3(128, 4), 256>>>(Wconv);
    k_convt<<<dim3(128, 4, 4), 256>>>();
    k_pool<<<4096, 256>>>();
    k_se<<<16, 256>>>(Wc1, Wc2);
    k_fuse<<<65536, 256>>>(x, gamma, beta, out);
}

// round 4
// speedup vs baseline: 2.2975x; 1.1019x over previous
#include <cuda_runtime.h>
#include <cuda_fp16.h>
#include <math.h>

// ---------------------------------------------------------------------------
// EPA_Layer: B=16, H=W=64, C=256, HID=64
// Round 4: mixed precision tensor cores.
//   q/k proj + attention logits: tf32 m16n8k8 (softmax-sensitive)
//   vc/vs proj, conv3x3, convT4x4: fp16 m16n8k16 (2x rate, ~tf32 precision
//   for in-range operands). fp16 intermediates halve gather traffic.
//   k_fuse: smem-transposed tiles (kills 8x sector amplification).
// ---------------------------------------------------------------------------

#define NB   16
#define NC   256
#define NHW  4096
#define NM   65536

__device__ float  g_q  [NB * NC * NHW];   // [B,C,H,W]
__device__ float  g_k  [NB * NC * NHW];   // [B,C,H,W]
__device__ float  g_vc [NM * NC];         // [B,H,W,C]
__device__ float  g_vs [NM * NC];         // [B,H,W,C]
__device__ float  g_as [NB * NC * NHW];   // attn_s logits [B,C,64,64]
__device__ float  g_ac [NB * NC * NHW];   // attn_c [B,C,64,64] (softmaxed in place)
__device__ __half g_asb[NB * NC * NHW];   // softmax(attn_s) fp16, conv input
__device__ __half g_c1b[NB * NC * 1024];  // conv3x3+relu fp16 [B,C,32,32]
__device__ float  g_sb [NB * NC * NHW];   // convT+relu fp32 [B,C,64,64]
__device__ __half g_wt2[4 * NC * 1024];   // packed convT weights fp16 [cl][co][ci*4+t]
__device__ float  g_pool[NB * NC];
__device__ float  g_gate[NB * NC];

__device__ __forceinline__ unsigned f2tf(float x) {
    unsigned u; asm("cvt.rna.tf32.f32 %0, %1;" : "=r"(u) : "f"(x)); return u;
}
__device__ __forceinline__ unsigned packh2(float a, float b) {
    __half2 h = __floats2half2_rn(a, b);
    return *(unsigned*)&h;
}
__device__ __forceinline__ unsigned packhh(__half a, __half b) {
    __half2 h = __halves2half2(a, b);
    return *(unsigned*)&h;
}

__device__ __forceinline__ void mma_tf32(float* c, const unsigned* a, const unsigned* b) {
    asm volatile(
        "mma.sync.aligned.m16n8k8.row.col.f32.tf32.tf32.f32 "
        "{%0,%1,%2,%3}, {%4,%5,%6,%7}, {%8,%9}, {%0,%1,%2,%3};"
        : "+f"(c[0]), "+f"(c[1]), "+f"(c[2]), "+f"(c[3])
        : "r"(a[0]), "r"(a[1]), "r"(a[2]), "r"(a[3]), "r"(b[0]), "r"(b[1]));
}
__device__ __forceinline__ void mma_f16(float* c, const unsigned* a, const unsigned* b) {
    asm volatile(
        "mma.sync.aligned.m16n8k16.row.col.f32.f16.f16.f32 "
        "{%0,%1,%2,%3}, {%4,%5,%6,%7}, {%8,%9}, {%0,%1,%2,%3};"
        : "+f"(c[0]), "+f"(c[1]), "+f"(c[2]), "+f"(c[3])
        : "r"(a[0]), "r"(a[1]), "r"(a[2]), "r"(a[3]), "r"(b[0]), "r"(b[1]));
}

// ---------------------------------------------------------------------------
// K1a: q/k projection (tf32). BM=128, BN=64, BK=16.
// out[b,d,hw] = sum_c x[m,c] W[d,c], scattered to [B,C,HW].
// ---------------------------------------------------------------------------
__global__ __launch_bounds__(256) void k_proj(
    const float* __restrict__ x,
    const float* __restrict__ Wq, const float* __restrict__ Wk)
{
    __shared__ unsigned As[128][20];
    __shared__ unsigned Bs[64][20];
    int m0 = blockIdx.x << 7;
    int nb = blockIdx.y;
    int which = nb >> 2;
    int d0 = (nb & 3) << 6;
    const float* W = which ? Wk : Wq;
    int tid = threadIdx.x, lane = tid & 31, wid = tid >> 5;
    int warpM = wid >> 1, warpN = wid & 1;
    int g = lane >> 2, tig = lane & 3;
    int am = tid >> 2, akq = tid & 3;
    float acc[2][4][4] = {};
    float4 ra0, ra1, rbv;

    auto gload = [&](int k0) {
        ra0 = *(const float4*)&x[(size_t)(m0 + am) * 256 + k0 + (akq << 2)];
        ra1 = *(const float4*)&x[(size_t)(m0 + am + 64) * 256 + k0 + (akq << 2)];
        rbv = *(const float4*)&W[(size_t)(d0 + am) * 256 + k0 + (akq << 2)];
    };
    auto sstore = [&]() {
        *(uint4*)&As[am][akq << 2] =
            make_uint4(f2tf(ra0.x), f2tf(ra0.y), f2tf(ra0.z), f2tf(ra0.w));
        *(uint4*)&As[am + 64][akq << 2] =
            make_uint4(f2tf(ra1.x), f2tf(ra1.y), f2tf(ra1.z), f2tf(ra1.w));
        *(uint4*)&Bs[am][akq << 2] =
            make_uint4(f2tf(rbv.x), f2tf(rbv.y), f2tf(rbv.z), f2tf(rbv.w));
    };

    gload(0); sstore(); __syncthreads();
    for (int k0 = 0; k0 < 256; k0 += 16) {
        bool more = (k0 + 16) < 256;
        if (more) gload(k0 + 16);
        #pragma unroll
        for (int ks = 0; ks < 2; ks++) {
            int kk = ks << 3;
            unsigned a[2][4], b[4][2];
            #pragma unroll
            for (int mt = 0; mt < 2; mt++) {
                int row = (warpM << 5) + (mt << 4) + g;
                a[mt][0] = As[row][kk + tig];     a[mt][1] = As[row + 8][kk + tig];
                a[mt][2] = As[row][kk + tig + 4]; a[mt][3] = As[row + 8][kk + tig + 4];
            }
            #pragma unroll
            for (int nt = 0; nt < 4; nt++) {
                int col = (warpN << 5) + (nt << 3) + g;
                b[nt][0] = Bs[col][kk + tig]; b[nt][1] = Bs[col][kk + tig + 4];
            }
            #pragma unroll
            for (int mt = 0; mt < 2; mt++)
                #pragma unroll
                for (int nt = 0; nt < 4; nt++)
                    mma_tf32(acc[mt][nt], a[mt], b[nt]);
        }
        __syncthreads();
        if (more) { sstore(); __syncthreads(); }
    }

    int b = m0 >> 12;
    int hw0 = m0 & 4095;
    float* dst = which ? g_k : g_q;
    #pragma unroll
    for (int mt = 0; mt < 2; mt++)
        #pragma unroll
        for (int nt = 0; nt < 4; nt++) {
            int row = (warpM << 5) + (mt << 4) + g;
            int col = (warpN << 5) + (nt << 3) + (tig << 1);
            float* c = acc[mt][nt];
            size_t bi = (size_t)((b << 8) + d0 + col) * 4096 + hw0;
            dst[bi + row]            = c[0];
            dst[bi + 4096 + row]     = c[1];
            dst[bi + row + 8]        = c[2];
            dst[bi + 4096 + row + 8] = c[3];
        }
}

// ---------------------------------------------------------------------------
// K1b: vc/vs projection (fp16). BM=128, BN=64, BK=32.
// ---------------------------------------------------------------------------
__global__ __launch_bounds__(256) void k_projv(
    const float* __restrict__ x,
    const float* __restrict__ Wvc, const float* __restrict__ Wvs)
{
    __shared__ unsigned As[128][20];   // [row][kp], kp = half2 pair index
    __shared__ unsigned Bs[64][20];
    int m0 = blockIdx.x << 7;
    int nb = blockIdx.y;
    int which = nb >> 2;
    int d0 = (nb & 3) << 6;
    const float* W = which ? Wvs : Wvc;
    int tid = threadIdx.x, lane = tid & 31, wid = tid >> 5;
    int warpM = wid >> 1, warpN = wid & 1;
    int g = lane >> 2, tig = lane & 3;
    float acc[2][4][4] = {};
    float4 ra[4], rb[2];

    auto gload = [&](int k0) {
        #pragma unroll
        for (int l = 0; l < 4; l++) {
            int idx = tid + (l << 8);
            ra[l] = *(const float4*)&x[(size_t)(m0 + (idx >> 3)) * 256 + k0 + ((idx & 7) << 2)];
        }
        #pragma unroll
        for (int l = 0; l < 2; l++) {
            int idx = tid + (l << 8);
            rb[l] = *(const float4*)&W[(size_t)(d0 + (idx >> 3)) * 256 + k0 + ((idx & 7) << 2)];
        }
    };
    auto sstore = [&]() {
        #pragma unroll
        for (int l = 0; l < 4; l++) {
            int idx = tid + (l << 8);
            *(uint2*)&As[idx >> 3][(idx & 7) << 1] =
                make_uint2(packh2(ra[l].x, ra[l].y), packh2(ra[l].z, ra[l].w));
        }
        #pragma unroll
        for (int l = 0; l < 2; l++) {
            int idx = tid + (l << 8);
            *(uint2*)&Bs[idx >> 3][(idx & 7) << 1] =
                make_uint2(packh2(rb[l].x, rb[l].y), packh2(rb[l].z, rb[l].w));
        }
    };

    gload(0); sstore(); __syncthreads();
    for (int k0 = 0; k0 < 256; k0 += 32) {
        bool more = (k0 + 32) < 256;
        if (more) gload(k0 + 32);
        #pragma unroll
        for (int ks = 0; ks < 2; ks++) {
            int kb = ks << 3;
            unsigned a[2][4], bf[4][2];
            #pragma unroll
            for (int mt = 0; mt < 2; mt++) {
                int row = (warpM << 5) + (mt << 4) + g;
                a[mt][0] = As[row][kb + tig];     a[mt][1] = As[row + 8][kb + tig];
                a[mt][2] = As[row][kb + 4 + tig]; a[mt][3] = As[row + 8][kb + 4 + tig];
            }
            #pragma unroll
            for (int nt = 0; nt < 4; nt++) {
                int col = (warpN << 5) + (nt << 3) + g;
                bf[nt][0] = Bs[col][kb + tig]; bf[nt][1] = Bs[col][kb + 4 + tig];
            }
            #pragma unroll
            for (int mt = 0; mt < 2; mt++)
                #pragma unroll
                for (int nt = 0; nt < 4; nt++)
                    mma_f16(acc[mt][nt], a[mt], bf[nt]);
        }
        __syncthreads();
        if (more) { sstore(); __syncthreads(); }
    }

    float* dst = which ? g_vs : g_vc;
    #pragma unroll
    for (int mt = 0; mt < 2; mt++)
        #pragma unroll
        for (int nt = 0; nt < 4; nt++) {
            int row = (warpM << 5) + (mt << 4) + g;
            int col = (warpN << 5) + (nt << 3) + (tig << 1);
            float* c = acc[mt][nt];
            *(float2*)&dst[(size_t)(m0 + row) * 256 + d0 + col] =
                make_float2(c[0], c[1]);
            *(float2*)&dst[(size_t)(m0 + row + 8) * 256 + d0 + col] =
                make_float2(c[2], c[3]);
        }
}

// ---------------------------------------------------------------------------
// K2: per-(b,c) attention logits (tf32). One smem image serves both phases.
// ---------------------------------------------------------------------------
__global__ __launch_bounds__(256) void k_attn(void)
{
    __shared__ unsigned Qs[64][68];
    __shared__ unsigned Ks[64][68];
    int bc = blockIdx.x;
    const float* Q = g_q + (size_t)bc * 4096;
    const float* K = g_k + (size_t)bc * 4096;
    int tid = threadIdx.x, lane = tid & 31, wid = tid >> 5;
    int warpM = wid >> 1, warpN = wid & 1;
    int g = lane >> 2, tig = lane & 3;

    #pragma unroll
    for (int l = 0; l < 16; l++) {
        int idx = tid + (l << 8);
        Qs[idx >> 6][idx & 63] = f2tf(Q[idx]);
        Ks[idx >> 6][idx & 63] = f2tf(K[idx]);
    }
    __syncthreads();

    {   // Phase 1: S1[h][gg] = sum_w Q[h][w] K[gg][w]
        float acc[4][4] = {};
        #pragma unroll
        for (int ks = 0; ks < 8; ks++) {
            int kk = ks << 3;
            unsigned a[4], b[4][2];
            int row = (warpM << 4) + g;
            a[0] = Qs[row][kk + tig];     a[1] = Qs[row + 8][kk + tig];
            a[2] = Qs[row][kk + tig + 4]; a[3] = Qs[row + 8][kk + tig + 4];
            #pragma unroll
            for (int nt = 0; nt < 4; nt++) {
                int col = (warpN << 5) + (nt << 3) + g;
                b[nt][0] = Ks[col][kk + tig]; b[nt][1] = Ks[col][kk + tig + 4];
            }
            #pragma unroll
            for (int nt = 0; nt < 4; nt++) mma_tf32(acc[nt], a, b[nt]);
        }
        float* out = g_as + (size_t)bc * 4096;
        #pragma unroll
        for (int nt = 0; nt < 4; nt++) {
            int row = (warpM << 4) + g;
            int col = (warpN << 5) + (nt << 3) + (tig << 1);
            *(float2*)&out[row * 64 + col]       = make_float2(acc[nt][0], acc[nt][1]);
            *(float2*)&out[(row + 8) * 64 + col] = make_float2(acc[nt][2], acc[nt][3]);
        }
    }
    {   // Phase 2: S2[w][v] = sum_h Q[h][w] K[h][v]
        float acc[4][4] = {};
        #pragma unroll
        for (int ks = 0; ks < 8; ks++) {
            int kk = ks << 3;
            unsigned a[4], b[4][2];
            int row = (warpM << 4) + g;
            a[0] = Qs[kk + tig][row];     a[1] = Qs[kk + tig][row + 8];
            a[2] = Qs[kk + tig + 4][row]; a[3] = Qs[kk + tig + 4][row + 8];
            #pragma unroll
            for (int nt = 0; nt < 4; nt++) {
                int col = (warpN << 5) + (nt << 3) + g;
                b[nt][0] = Ks[kk + tig][col]; b[nt][1] = Ks[kk + tig + 4][col];
            }
            #pragma unroll
            for (int nt = 0; nt < 4; nt++) mma_tf32(acc[nt], a, b[nt]);
        }
        float* out = g_ac + (size_t)bc * 4096;
        #pragma unroll
        for (int nt = 0; nt < 4; nt++) {
            int row = (warpM << 4) + g;
            int col = (warpN << 5) + (nt << 3) + (tig << 1);
            *(float2*)&out[row * 64 + col]       = make_float2(acc[nt][0], acc[nt][1]);
            *(float2*)&out[(row + 8) * 64 + col] = make_float2(acc[nt][2], acc[nt][3]);
        }
    }
}

// ---------------------------------------------------------------------------
// K3: channel softmax (axis c, stride 4096).
// y=0: attn_s -> fp16 g_asb (conv input). y=1: attn_c in place (fp32).
// ---------------------------------------------------------------------------
__global__ __launch_bounds__(256) void k_softmax(void)
{
    int which = blockIdx.y;
    float* t = which ? g_ac : g_as;
    int p = blockIdx.x * 256 + threadIdx.x;
    int b = p >> 12, pos = p & 4095;
    float* base = t + (size_t)b * (256 * 4096) + pos;
    float m = -3.0e38f, s = 0.f;
    for (int c = 0; c < 256; c++) {
        float v = base[(size_t)c << 12];
        float nm = fmaxf(m, v);
        s = s * __expf(m - nm) + __expf(v - nm);
        m = nm;
    }
    float inv = 1.0f / s;
    if (which) {
        for (int c = 0; c < 256; c++) {
            size_t o = (size_t)c << 12;
            base[o] = __expf(base[o] - m) * inv;
        }
    } else {
        __half* ob = g_asb + (size_t)b * (256 * 4096) + pos;
        for (int c = 0; c < 256; c++) {
            size_t o = (size_t)c << 12;
            ob[o] = __float2half(__expf(base[o] - m) * inv);
        }
    }
}

// ---------------------------------------------------------------------------
// K4: conv3x3 s2 p1 + relu (fp16 implicit GEMM). M=16384, N=256, K=2304, BK=32.
// ---------------------------------------------------------------------------
__global__ __launch_bounds__(256) void k_conv(const float* __restrict__ Wconv)
{
    __shared__ unsigned Ap[16][136];   // [kp][m]
    __shared__ unsigned Bs[64][20];    // [co][kp]
    int m0 = blockIdx.x << 7;
    int n0 = blockIdx.y << 6;
    int tid = threadIdx.x, lane = tid & 31, wid = tid >> 5;
    int warpM = wid >> 1, warpN = wid & 1;
    int g = lane >> 2, tig = lane & 3;
    int b = m0 >> 10;
    float acc[2][4][4] = {};
    unsigned rga[8]; float4 rgb[2];

    auto gather1 = [&](int kk, int m) -> __half {
        int ci = kk / 9;
        int t9 = kk - ci * 9;
        int ky = t9 / 3;
        int kx = t9 - ky * 3;
        int r = (m0 + m) & 1023;
        int oy = r >> 5, ox = r & 31;
        int iy = 2 * oy - 1 + ky, ix = 2 * ox - 1 + kx;
        __half v = __float2half(0.f);
        if ((unsigned)iy < 64u && (unsigned)ix < 64u)
            v = g_asb[(((size_t)((b << 8) + ci)) << 12) + (iy << 6) + ix];
        return v;
    };
    auto gload = [&](int k0) {
        #pragma unroll
        for (int l = 0; l < 8; l++) {
            int idx = tid + (l << 8);
            int kp = idx >> 7, m = idx & 127;
            int kk = k0 + (kp << 1);
            rga[l] = packhh(gather1(kk, m), gather1(kk + 1, m));
        }
        #pragma unroll
        for (int l = 0; l < 2; l++) {
            int idx = tid + (l << 8);
            rgb[l] = *(const float4*)&Wconv[(size_t)(n0 + (idx >> 3)) * 2304 + k0 + ((idx & 7) << 2)];
        }
    };
    auto sstore = [&]() {
        #pragma unroll
        for (int l = 0; l < 8; l++) {
            int idx = tid + (l << 8);
            Ap[idx >> 7][idx & 127] = rga[l];
        }
        #pragma unroll
        for (int l = 0; l < 2; l++) {
            int idx = tid + (l << 8);
            *(uint2*)&Bs[idx >> 3][(idx & 7) << 1] =
                make_uint2(packh2(rgb[l].x, rgb[l].y), packh2(rgb[l].z, rgb[l].w));
        }
    };

    gload(0); sstore(); __syncthreads();
    for (int k0 = 0; k0 < 2304; k0 += 32) {
        bool more = (k0 + 32) < 2304;
        if (more) gload(k0 + 32);
        #pragma unroll
        for (int ks = 0; ks < 2; ks++) {
            int kb = ks << 3;
            unsigned a[2][4], bf[4][2];
            #pragma unroll
            for (int mt = 0; mt < 2; mt++) {
                int row = (warpM << 5) + (mt << 4) + g;
                a[mt][0] = Ap[kb + tig][row];     a[mt][1] = Ap[kb + tig][row + 8];
                a[mt][2] = Ap[kb + 4 + tig][row]; a[mt][3] = Ap[kb + 4 + tig][row + 8];
            }
            #pragma unroll
            for (int nt = 0; nt < 4; nt++) {
                int col = (warpN << 5) + (nt << 3) + g;
                bf[nt][0] = Bs[col][kb + tig]; bf[nt][1] = Bs[col][kb + 4 + tig];
            }
            #pragma unroll
            for (int mt = 0; mt < 2; mt++)
                #pragma unroll
                for (int nt = 0; nt < 4; nt++)
                    mma_f16(acc[mt][nt], a[mt], bf[nt]);
        }
        __syncthreads();
        if (more) { sstore(); __syncthreads(); }
    }

    #pragma unroll
    for (int mt = 0; mt < 2; mt++)
        #pragma unroll
        for (int nt = 0; nt < 4; nt++) {
            int row = (warpM << 5) + (mt << 4) + g;
            int col = n0 + (warpN << 5) + (nt << 3) + (tig << 1);
            float* c = acc[mt][nt];
            int r1 = (m0 + row) & 1023;
            size_t b1 = (((size_t)((b << 8) + col)) << 10) + r1;
            g_c1b[b1]        = __float2half(fmaxf(c[0], 0.f));
            g_c1b[b1 + 1024] = __float2half(fmaxf(c[1], 0.f));
            int r2 = (m0 + row + 8) & 1023;
            size_t b2 = (((size_t)((b << 8) + col)) << 10) + r2;
            g_c1b[b2]        = __float2half(fmaxf(c[2], 0.f));
            g_c1b[b2 + 1024] = __float2half(fmaxf(c[3], 0.f));
        }
}

// ---------------------------------------------------------------------------
// K5: pack convT weights per parity class (fp16).
// ---------------------------------------------------------------------------
__global__ void k_packwt(const float* __restrict__ Wconvt)
{
    int i = blockIdx.x * 256 + threadIdx.x;
    int cl = i >> 18;
    int rem = i & 262143;
    int co = rem >> 10;
    int k = rem & 1023;
    int ci = k >> 2, t = k & 3;
    int tyk = t >> 1, txk = t & 1;
    int py = cl >> 1, px = cl & 1;
    int ky = 1 - py + 2 * tyk, kx = 1 - px + 2 * txk;
    g_wt2[i] = __float2half(Wconvt[(((size_t)ci * 256 + co) * 4 + ky) * 4 + kx]);
}

// ---------------------------------------------------------------------------
// K6: convT 4x4 s2 p1 + relu by parity class (fp16 implicit GEMM).
// M=16384, N=256, K=1024 per class, BK=32.
// ---------------------------------------------------------------------------
__global__ __launch_bounds__(256) void k_convt(void)
{
    __shared__ unsigned Ap[16][136];
    __shared__ unsigned Bs[64][20];
    int cl = blockIdx.z;
    int py = cl >> 1, px = cl & 1;
    int m0 = blockIdx.x << 7;
    int n0 = blockIdx.y << 6;
    int tid = threadIdx.x, lane = tid & 31, wid = tid >> 5;
    int warpM = wid >> 1, warpN = wid & 1;
    int g = lane >> 2, tig = lane & 3;
    int b = m0 >> 10;
    float acc[2][4][4] = {};
    unsigned rga[8]; uint2 rgb[2];

    auto gather1 = [&](int kk, int m) -> __half {
        int ci = kk >> 2, t = kk & 3;
        int tyk = t >> 1, txk = t & 1;
        int mm = m0 + m;
        int ys = (mm >> 5) & 31, xs = mm & 31;
        int ii = ys + py - tyk, jj = xs + px - txk;
        __half v = __float2half(0.f);
        if ((unsigned)ii < 32u && (unsigned)jj < 32u)
            v = g_c1b[(((size_t)((b << 8) + ci)) << 10) + (ii << 5) + jj];
        return v;
    };
    auto gload = [&](int k0) {
        #pragma unroll
        for (int l = 0; l < 8; l++) {
            int idx = tid + (l << 8);
            int kp = idx >> 7, m = idx & 127;
            int kk = k0 + (kp << 1);
            rga[l] = packhh(gather1(kk, m), gather1(kk + 1, m));
        }
        #pragma unroll
        for (int l = 0; l < 2; l++) {
            int idx = tid + (l << 8);
            rgb[l] = *(const uint2*)&g_wt2[(((size_t)((cl << 8) + n0 + (idx >> 3))) << 10) + k0 + ((idx & 7) << 2)];
        }
    };
    auto sstore = [&]() {
        #pragma unroll
        for (int l = 0; l < 8; l++) {
            int idx = tid + (l << 8);
            Ap[idx >> 7][idx & 127] = rga[l];
        }
        #pragma unroll
        for (int l = 0; l < 2; l++) {
            int idx = tid + (l << 8);
            *(uint2*)&Bs[idx >> 3][(idx & 7) << 1] = rgb[l];
        }
    };

    gload(0); sstore(); __syncthreads();
    for (int k0 = 0; k0 < 1024; k0 += 32) {
        bool more = (k0 + 32) < 1024;
        if (more) gload(k0 + 32);
        #pragma unroll
        for (int ks = 0; ks < 2; ks++) {
            int kb = ks << 3;
            unsigned a[2][4], bf[4][2];
            #pragma unroll
            for (int mt = 0; mt < 2; mt++) {
                int row = (warpM << 5) + (mt << 4) + g;
                a[mt][0] = Ap[kb + tig][row];     a[mt][1] = Ap[kb + tig][row + 8];
                a[mt][2] = Ap[kb + 4 + tig][row]; a[mt][3] = Ap[kb + 4 + tig][row + 8];
            }
            #pragma unroll
            for (int nt = 0; nt < 4; nt++) {
                int col = (warpN << 5) + (nt << 3) + g;
                bf[nt][0] = Bs[col][kb + tig]; bf[nt][1] = Bs[col][kb + 4 + tig];
            }
            #pragma unroll
            for (int mt = 0; mt < 2; mt++)
                #pragma unroll
                for (int nt = 0; nt < 4; nt++)
                    mma_f16(acc[mt][nt], a[mt], bf[nt]);
        }
        __syncthreads();
        if (more) { sstore(); __syncthreads(); }
    }

    #pragma unroll
    for (int mt = 0; mt < 2; mt++)
        #pragma unroll
        for (int nt = 0; nt < 4; nt++) {
            int row = (warpM << 5) + (mt << 4) + g;
            int col = n0 + (warpN << 5) + (nt << 3) + (tig << 1);
            float* c = acc[mt][nt];
            int mm1 = m0 + row;
            int ys1 = (mm1 >> 5) & 31, xs1 = mm1 & 31;
            size_t b1 = (((size_t)((b << 8) + col)) << 12) +
                        ((2 * ys1 + py) << 6) + (2 * xs1 + px);
            g_sb[b1]        = fmaxf(c[0], 0.f);
            g_sb[b1 + 4096] = fmaxf(c[1], 0.f);
            int mm2 = mm1 + 8;
            int ys2 = (mm2 >> 5) & 31, xs2 = mm2 & 31;
            size_t b2 = (((size_t)((b << 8) + col)) << 12) +
                        ((2 * ys2 + py) << 6) + (2 * xs2 + px);
            g_sb[b2]        = fmaxf(c[2], 0.f);
            g_sb[b2 + 4096] = fmaxf(c[3], 0.f);
        }
}

// ---------------------------------------------------------------------------
// K7: global mean pool of attn_c per (b,c)
// ---------------------------------------------------------------------------
__global__ __launch_bounds__(256) void k_pool(void)
{
    int bc = blockIdx.x;
    const float* p = g_ac + (size_t)bc * 4096;
    float s = 0.f;
    for (int i = threadIdx.x; i < 4096; i += 256) s += p[i];
    __shared__ float red[8];
    #pragma unroll
    for (int o = 16; o > 0; o >>= 1) s += __shfl_down_sync(0xffffffffu, s, o);
    int w = threadIdx.x >> 5;
    if ((threadIdx.x & 31) == 0) red[w] = s;
    __syncthreads();
    if (threadIdx.x == 0) {
        float t = 0.f;
        #pragma unroll
        for (int i = 0; i < 8; i++) t += red[i];
        g_pool[bc] = t * (1.0f / 4096.0f);
    }
}

// ---------------------------------------------------------------------------
// K8: SE MLP
// ---------------------------------------------------------------------------
__global__ __launch_bounds__(256) void k_se(const float* __restrict__ Wc1,
                                            const float* __restrict__ Wc2)
{
    int b = blockIdx.x;
    __shared__ float pool[256];
    __shared__ float hid[64];
    int t = threadIdx.x;
    pool[t] = g_pool[b * 256 + t];
    __syncthreads();
    if (t < 64) {
        float s = 0.f;
        for (int c = 0; c < 256; c++) s += pool[c] * Wc1[t * 256 + c];
        hid[t] = fmaxf(s, 0.f);
    }
    __syncthreads();
    float s = 0.f;
    #pragma unroll
    for (int j = 0; j < 64; j++) s += hid[j] * Wc2[t * 64 + j];
    g_gate[b * 256 + t] = 1.0f / (1.0f + __expf(-s));
}

// ---------------------------------------------------------------------------
// K9: fused residual + LayerNorm, smem-transposed tiles.
// Block = 32 hw positions x 256 channels. g_sb/g_ac loaded coalesced
// (thread = c, 32 contiguous hw), consumed transposed from smem.
// ---------------------------------------------------------------------------
__global__ __launch_bounds__(256) void k_fuse(const float* __restrict__ x,
                                              const float* __restrict__ gamma,
                                              const float* __restrict__ beta,
                                              float* __restrict__ out)
{
    __shared__ float tile[256][33];
    __shared__ float red1[8][32], red2[8][32];
    __shared__ float smu[32], sri[32];
    int blk = blockIdx.x;                 // 0..2047
    int b = blk >> 7;
    int hw0 = (blk & 127) << 5;
    int t = threadIdx.x;
    int hw = t & 31, c0 = (t >> 5) << 5;  // warp -> 32-channel slab

    {   // load convT output tile: thread = channel t, 32 contiguous hw
        const float* src = g_sb + (((size_t)(b * 256 + t)) << 12) + hw0;
        #pragma unroll
        for (int j = 0; j < 32; j += 4) {
            float4 v = *(const float4*)&src[j];
            tile[t][j] = v.x; tile[t][j + 1] = v.y;
            tile[t][j + 2] = v.z; tile[t][j + 3] = v.w;
        }
    }
    __syncthreads();

    float yv[32];
    size_t mi = ((size_t)(b * 4096 + hw0 + hw)) * 256 + c0;
    #pragma unroll
    for (int i = 0; i < 32; i += 4) {
        float4 xv  = *(const float4*)&x[mi + i];
        float4 vs4 = *(const float4*)&g_vs[mi + i];
        yv[i]     = xv.x + tile[c0 + i][hw]     * vs4.x;
        yv[i + 1] = xv.y + tile[c0 + i + 1][hw] * vs4.y;
        yv[i + 2] = xv.z + tile[c0 + i + 2][hw] * vs4.z;
        yv[i + 3] = xv.w + tile[c0 + i + 3][hw] * vs4.w;
    }
    __syncthreads();

    {   // reload tile with softmaxed attn_c
        const float* src = g_ac + (((size_t)(b * 256 + t)) << 12) + hw0;
        #pragma unroll
        for (int j = 0; j < 32; j += 4) {
            float4 v = *(const float4*)&src[j];
            tile[t][j] = v.x; tile[t][j + 1] = v.y;
            tile[t][j + 2] = v.z; tile[t][j + 3] = v.w;
        }
    }
    __syncthreads();

    #pragma unroll
    for (int i = 0; i < 32; i += 4) {
        float4 vc4 = *(const float4*)&g_vc[mi + i];
        float4 gt4 = *(const float4*)&g_gate[b * 256 + c0 + i];
        yv[i]     += gt4.x * tile[c0 + i][hw]     * vc4.x;
        yv[i + 1] += gt4.y * tile[c0 + i + 1][hw] * vc4.y;
        yv[i + 2] += gt4.z * tile[c0 + i + 2][hw] * vc4.z;
        yv[i + 3] += gt4.w * tile[c0 + i + 3][hw] * vc4.w;
    }

    float s1 = 0.f, s2 = 0.f;
    #pragma unroll
    for (int i = 0; i < 32; i++) { s1 += yv[i]; s2 += yv[i] * yv[i]; }
    red1[t >> 5][hw] = s1; red2[t >> 5][hw] = s2;
    __syncthreads();
    if (t < 32) {
        float a = 0.f, bb = 0.f;
        #pragma unroll
        for (int w = 0; w < 8; w++) { a += red1[w][t]; bb += red2[w][t]; }
        float mu = a * (1.0f / 256.0f);
        float var = bb * (1.0f / 256.0f) - mu * mu;
        smu[t] = mu; sri[t] = rsqrtf(var + 1e-5f);
    }
    __syncthreads();
    float mu = smu[hw], ri = sri[hw];
    #pragma unroll
    for (int i = 0; i < 32; i += 4) {
        float4 gm = *(const float4*)&gamma[c0 + i];
        float4 bt = *(const float4*)&beta[c0 + i];
        float4 o;
        o.x = (yv[i]     - mu) * ri * gm.x + bt.x;
        o.y = (yv[i + 1] - mu) * ri * gm.y + bt.y;
        o.z = (yv[i + 2] - mu) * ri * gm.z + bt.z;
        o.w = (yv[i + 3] - mu) * ri * gm.w + bt.w;
        *(float4*)&out[mi + i] = o;
    }
}

// ---------------------------------------------------------------------------
extern "C" void kernel_launch(void* const* d_in, const int* in_sizes, int n_in,
                              void* d_out, int out_size)
{
    const float* x      = (const float*)d_in[0];
    const float* Wq     = (const float*)d_in[1];
    const float* Wk     = (const float*)d_in[2];
    const float* Wvc    = (const float*)d_in[3];
    const float* Wvs    = (const float*)d_in[4];
    const float* Wc1    = (const float*)d_in[5];
    const float* Wc2    = (const float*)d_in[6];
    const float* Wconv  = (const float*)d_in[7];
    const float* Wconvt = (const float*)d_in[8];
    const float* gamma  = (const float*)d_in[9];
    const float* beta   = (const float*)d_in[10];
    float* out = (float*)d_out;

    k_proj <<<dim3(512, 8), 256>>>(x, Wq, Wk);
    k_projv<<<dim3(512, 8), 256>>>(x, Wvc, Wvs);
    k_attn <<<4096, 256>>>();
    k_softmax<<<dim3(256, 2), 256>>>();
    k_packwt<<<4096, 256>>>(Wconvt);
    k_conv <<<dim3(128, 4), 256>>>(Wconv);
    k_convt<<<dim3(128, 4, 4), 256>>>();
    k_pool <<<4096, 256>>>();
    k_se   <<<16, 256>>>(Wc1, Wc2);
    k_fuse <<<2048, 256>>>(x, gamma, beta, out);
}

// round 5
// speedup vs baseline: 2.6389x; 1.1486x over previous
#include <cuda_runtime.h>
#include <cuda_fp16.h>
#include <math.h>

// ---------------------------------------------------------------------------
// EPA_Layer: B=16, H=W=64, C=256, HID=64
// Round 5: full fp16 tensor-core pipeline (fp32 accumulate everywhere).
//   - unified 4-way fp16 projection (q/k stored fp16 [B,C,HW])
//   - fp16 attention logits (dual smem images for the transposed phase)
//   - softmax with 4 independent ILP chains
//   - convT output fp16
// ---------------------------------------------------------------------------

#define NB   16
#define NC   256
#define NHW  4096
#define NM   65536

__device__ __half g_qh [NB * NC * NHW];   // q fp16 [B,C,H,W]
__device__ __half g_kh [NB * NC * NHW];   // k fp16 [B,C,H,W]
__device__ float  g_vc [NM * NC];         // [B,H,W,C]
__device__ float  g_vs [NM * NC];         // [B,H,W,C]
__device__ float  g_as [NB * NC * NHW];   // attn_s logits [B,C,64,64]
__device__ float  g_ac [NB * NC * NHW];   // attn_c [B,C,64,64] (softmaxed in place)
__device__ __half g_asb[NB * NC * NHW];   // softmax(attn_s) fp16 (conv input)
__device__ __half g_c1b[NB * NC * 1024];  // conv3x3+relu fp16 [B,C,32,32]
__device__ __half g_sbh[NB * NC * NHW];   // convT+relu fp16 [B,C,64,64]
__device__ __half g_wt2[4 * NC * 1024];   // packed convT weights fp16
__device__ float  g_pool[NB * NC];
__device__ float  g_gate[NB * NC];

__device__ __forceinline__ unsigned packh2(float a, float b) {
    __half2 h = __floats2half2_rn(a, b);
    return *(unsigned*)&h;
}
__device__ __forceinline__ unsigned packhh(__half a, __half b) {
    __half2 h = __halves2half2(a, b);
    return *(unsigned*)&h;
}
__device__ __forceinline__ void mma_f16(float* c, const unsigned* a, const unsigned* b) {
    asm volatile(
        "mma.sync.aligned.m16n8k16.row.col.f32.f16.f16.f32 "
        "{%0,%1,%2,%3}, {%4,%5,%6,%7}, {%8,%9}, {%0,%1,%2,%3};"
        : "+f"(c[0]), "+f"(c[1]), "+f"(c[2]), "+f"(c[3])
        : "r"(a[0]), "r"(a[1]), "r"(a[2]), "r"(a[3]), "r"(b[0]), "r"(b[1]));
}

// ---------------------------------------------------------------------------
// K1: unified 4-way projection (fp16 mma). BM=128, BN=64, BK=32.
// which = blockIdx.y>>2: 0=q,1=k (fp16 -> [B,C,HW]); 2=vc,3=vs (fp32 [M,C]).
// ---------------------------------------------------------------------------
__global__ __launch_bounds__(256) void k_proj(
    const float* __restrict__ x,
    const float* __restrict__ Wq, const float* __restrict__ Wk,
    const float* __restrict__ Wvc, const float* __restrict__ Wvs)
{
    __shared__ unsigned As[128][20];   // half2 units
    __shared__ unsigned Bs[64][20];
    int m0 = blockIdx.x << 7;
    int nb = blockIdx.y;
    int which = nb >> 2;
    int d0 = (nb & 3) << 6;
    const float* W = (which == 0) ? Wq : (which == 1) ? Wk : (which == 2) ? Wvc : Wvs;
    int tid = threadIdx.x, lane = tid & 31, wid = tid >> 5;
    int warpM = wid >> 1, warpN = wid & 1;
    int g = lane >> 2, tig = lane & 3;
    float acc[2][4][4] = {};
    float4 ra[4], rb[2];

    auto gload = [&](int k0) {
        #pragma unroll
        for (int l = 0; l < 4; l++) {
            int idx = tid + (l << 8);
            ra[l] = *(const float4*)&x[(size_t)(m0 + (idx >> 3)) * 256 + k0 + ((idx & 7) << 2)];
        }
        #pragma unroll
        for (int l = 0; l < 2; l++) {
            int idx = tid + (l << 8);
            rb[l] = *(const float4*)&W[(size_t)(d0 + (idx >> 3)) * 256 + k0 + ((idx & 7) << 2)];
        }
    };
    auto sstore = [&]() {
        #pragma unroll
        for (int l = 0; l < 4; l++) {
            int idx = tid + (l << 8);
            *(uint2*)&As[idx >> 3][(idx & 7) << 1] =
                make_uint2(packh2(ra[l].x, ra[l].y), packh2(ra[l].z, ra[l].w));
        }
        #pragma unroll
        for (int l = 0; l < 2; l++) {
            int idx = tid + (l << 8);
            *(uint2*)&Bs[idx >> 3][(idx & 7) << 1] =
                make_uint2(packh2(rb[l].x, rb[l].y), packh2(rb[l].z, rb[l].w));
        }
    };

    gload(0); sstore(); __syncthreads();
    for (int k0 = 0; k0 < 256; k0 += 32) {
        bool more = (k0 + 32) < 256;
        if (more) gload(k0 + 32);
        #pragma unroll
        for (int ks = 0; ks < 2; ks++) {
            int kb = ks << 3;
            unsigned a[2][4], bf[4][2];
            #pragma unroll
            for (int mt = 0; mt < 2; mt++) {
                int row = (warpM << 5) + (mt << 4) + g;
                a[mt][0] = As[row][kb + tig];     a[mt][1] = As[row + 8][kb + tig];
                a[mt][2] = As[row][kb + 4 + tig]; a[mt][3] = As[row + 8][kb + 4 + tig];
            }
            #pragma unroll
            for (int nt = 0; nt < 4; nt++) {
                int col = (warpN << 5) + (nt << 3) + g;
                bf[nt][0] = Bs[col][kb + tig]; bf[nt][1] = Bs[col][kb + 4 + tig];
            }
            #pragma unroll
            for (int mt = 0; mt < 2; mt++)
                #pragma unroll
                for (int nt = 0; nt < 4; nt++)
                    mma_f16(acc[mt][nt], a[mt], bf[nt]);
        }
        __syncthreads();
        if (more) { sstore(); __syncthreads(); }
    }

    if (which < 2) {
        __half* dst = which ? g_kh : g_qh;
        int b = m0 >> 12;
        int hw0 = m0 & 4095;
        #pragma unroll
        for (int mt = 0; mt < 2; mt++)
            #pragma unroll
            for (int nt = 0; nt < 4; nt++) {
                int row = (warpM << 5) + (mt << 4) + g;
                int col = (warpN << 5) + (nt << 3) + (tig << 1);
                float* c = acc[mt][nt];
                size_t bi = (size_t)((b << 8) + d0 + col) * 4096 + hw0;
                dst[bi + row]            = __float2half(c[0]);
                dst[bi + 4096 + row]     = __float2half(c[1]);
                dst[bi + row + 8]        = __float2half(c[2]);
                dst[bi + 4096 + row + 8] = __float2half(c[3]);
            }
    } else {
        float* dst = (which == 2) ? g_vc : g_vs;
        #pragma unroll
        for (int mt = 0; mt < 2; mt++)
            #pragma unroll
            for (int nt = 0; nt < 4; nt++) {
                int row = (warpM << 5) + (mt << 4) + g;
                int col = (warpN << 5) + (nt << 3) + (tig << 1);
                float* c = acc[mt][nt];
                *(float2*)&dst[(size_t)(m0 + row) * 256 + d0 + col] =
                    make_float2(c[0], c[1]);
                *(float2*)&dst[(size_t)(m0 + row + 8) * 256 + d0 + col] =
                    make_float2(c[2], c[3]);
            }
    }
}

// ---------------------------------------------------------------------------
// K2: per-(b,c) attention logits (fp16 mma, fp32 accum).
// Dual smem images: natural [h][w] (phase 1) + transposed [w][h] (phase 2),
// since fp16 fragments need k-contiguous half2 pairs.
// ---------------------------------------------------------------------------
__global__ __launch_bounds__(256) void k_attn(void)
{
    __shared__ __half Qs[64][72];   // [h][w]
    __shared__ __half Ks[64][72];
    __shared__ __half Qt[64][72];   // [w][h]
    __shared__ __half Kt[64][72];
    int bc = blockIdx.x;
    const __half* Q = g_qh + (size_t)bc * 4096;
    const __half* K = g_kh + (size_t)bc * 4096;
    int tid = threadIdx.x, lane = tid & 31, wid = tid >> 5;
    int warpM = wid >> 1, warpN = wid & 1;
    int g = lane >> 2, tig = lane & 3;

    #pragma unroll
    for (int l = 0; l < 16; l++) {
        int idx = tid + (l << 8);
        int h = idx >> 6, w = idx & 63;
        __half qv = Q[idx], kv = K[idx];
        Qs[h][w] = qv; Ks[h][w] = kv;
        Qt[w][h] = qv; Kt[w][h] = kv;
    }
    __syncthreads();

    {   // Phase 1: S1[h][gg] = sum_w Q[h][w] K[gg][w]
        float acc[4][4] = {};
        #pragma unroll
        for (int ks = 0; ks < 4; ks++) {
            int kh = ks << 4;
            unsigned a[4], b[4][2];
            int row = (warpM << 4) + g;
            a[0] = *(const unsigned*)&Qs[row][kh + (tig << 1)];
            a[1] = *(const unsigned*)&Qs[row + 8][kh + (tig << 1)];
            a[2] = *(const unsigned*)&Qs[row][kh + 8 + (tig << 1)];
            a[3] = *(const unsigned*)&Qs[row + 8][kh + 8 + (tig << 1)];
            #pragma unroll
            for (int nt = 0; nt < 4; nt++) {
                int col = (warpN << 5) + (nt << 3) + g;
                b[nt][0] = *(const unsigned*)&Ks[col][kh + (tig << 1)];
                b[nt][1] = *(const unsigned*)&Ks[col][kh + 8 + (tig << 1)];
            }
            #pragma unroll
            for (int nt = 0; nt < 4; nt++) mma_f16(acc[nt], a, b[nt]);
        }
        float* out = g_as + (size_t)bc * 4096;
        #pragma unroll
        for (int nt = 0; nt < 4; nt++) {
            int row = (warpM << 4) + g;
            int col = (warpN << 5) + (nt << 3) + (tig << 1);
            *(float2*)&out[row * 64 + col]       = make_float2(acc[nt][0], acc[nt][1]);
            *(float2*)&out[(row + 8) * 64 + col] = make_float2(acc[nt][2], acc[nt][3]);
        }
    }
    {   // Phase 2: S2[w][v] = sum_h Q[h][w] K[h][v]
        float acc[4][4] = {};
        #pragma unroll
        for (int ks = 0; ks < 4; ks++) {
            int kh = ks << 4;
            unsigned a[4], b[4][2];
            int row = (warpM << 4) + g;
            a[0] = *(const unsigned*)&Qt[row][kh + (tig << 1)];
            a[1] = *(const unsigned*)&Qt[row + 8][kh + (tig << 1)];
            a[2] = *(const unsigned*)&Qt[row][kh + 8 + (tig << 1)];
            a[3] = *(const unsigned*)&Qt[row + 8][kh + 8 + (tig << 1)];
            #pragma unroll
            for (int nt = 0; nt < 4; nt++) {
                int col = (warpN << 5) + (nt << 3) + g;
                b[nt][0] = *(const unsigned*)&Kt[col][kh + (tig << 1)];
                b[nt][1] = *(const unsigned*)&Kt[col][kh + 8 + (tig << 1)];
            }
            #pragma unroll
            for (int nt = 0; nt < 4; nt++) mma_f16(acc[nt], a, b[nt]);
        }
        float* out = g_ac + (size_t)bc * 4096;
        #pragma unroll
        for (int nt = 0; nt < 4; nt++) {
            int row = (warpM << 4) + g;
            int col = (warpN << 5) + (nt << 3) + (tig << 1);
            *(float2*)&out[row * 64 + col]       = make_float2(acc[nt][0], acc[nt][1]);
            *(float2*)&out[(row + 8) * 64 + col] = make_float2(acc[nt][2], acc[nt][3]);
        }
    }
}

// ---------------------------------------------------------------------------
// K3: channel softmax (axis c, stride 4096), 4 independent ILP chains.
// y=0: attn_s -> fp16 g_asb. y=1: attn_c in place (fp32).
// ---------------------------------------------------------------------------
__global__ __launch_bounds__(256) void k_softmax(void)
{
    int which = blockIdx.y;
    float* t = which ? g_ac : g_as;
    int p = blockIdx.x * 256 + threadIdx.x;
    int b = p >> 12, pos = p & 4095;
    float* base = t + (size_t)b * (256 * 4096) + pos;

    float m0 = -3.0e38f, m1 = m0, m2 = m0, m3 = m0;
    float s0 = 0.f, s1 = 0.f, s2 = 0.f, s3 = 0.f;
    for (int c = 0; c < 64; c++) {
        float v0 = base[(size_t)c << 12];
        float v1 = base[(size_t)(c + 64) << 12];
        float v2 = base[(size_t)(c + 128) << 12];
        float v3 = base[(size_t)(c + 192) << 12];
        float n0 = fmaxf(m0, v0); s0 = s0 * __expf(m0 - n0) + __expf(v0 - n0); m0 = n0;
        float n1 = fmaxf(m1, v1); s1 = s1 * __expf(m1 - n1) + __expf(v1 - n1); m1 = n1;
        float n2 = fmaxf(m2, v2); s2 = s2 * __expf(m2 - n2) + __expf(v2 - n2); m2 = n2;
        float n3 = fmaxf(m3, v3); s3 = s3 * __expf(m3 - n3) + __expf(v3 - n3); m3 = n3;
    }
    float M = fmaxf(fmaxf(m0, m1), fmaxf(m2, m3));
    float S = s0 * __expf(m0 - M) + s1 * __expf(m1 - M) +
              s2 * __expf(m2 - M) + s3 * __expf(m3 - M);
    float inv = 1.0f / S;

    if (which) {
        for (int c = 0; c < 64; c++) {
            size_t o0 = (size_t)c << 12, o1 = (size_t)(c + 64) << 12;
            size_t o2 = (size_t)(c + 128) << 12, o3 = (size_t)(c + 192) << 12;
            float v0 = base[o0], v1 = base[o1], v2 = base[o2], v3 = base[o3];
            base[o0] = __expf(v0 - M) * inv;
            base[o1] = __expf(v1 - M) * inv;
            base[o2] = __expf(v2 - M) * inv;
            base[o3] = __expf(v3 - M) * inv;
        }
    } else {
        __half* ob = g_asb + (size_t)b * (256 * 4096) + pos;
        for (int c = 0; c < 64; c++) {
            size_t o0 = (size_t)c << 12, o1 = (size_t)(c + 64) << 12;
            size_t o2 = (size_t)(c + 128) << 12, o3 = (size_t)(c + 192) << 12;
            float v0 = base[o0], v1 = base[o1], v2 = base[o2], v3 = base[o3];
            ob[o0] = __float2half(__expf(v0 - M) * inv);
            ob[o1] = __float2half(__expf(v1 - M) * inv);
            ob[o2] = __float2half(__expf(v2 - M) * inv);
            ob[o3] = __float2half(__expf(v3 - M) * inv);
        }
    }
}

// ---------------------------------------------------------------------------
// K4: conv3x3 s2 p1 + relu (fp16 implicit GEMM). M=16384, N=256, K=2304, BK=32.
// ---------------------------------------------------------------------------
__global__ __launch_bounds__(256) void k_conv(const float* __restrict__ Wconv)
{
    __shared__ unsigned Ap[16][136];   // [kp][m]
    __shared__ unsigned Bs[64][20];
    int m0 = blockIdx.x << 7;
    int n0 = blockIdx.y << 6;
    int tid = threadIdx.x, lane = tid & 31, wid = tid >> 5;
    int warpM = wid >> 1, warpN = wid & 1;
    int g = lane >> 2, tig = lane & 3;
    int b = m0 >> 10;
    float acc[2][4][4] = {};
    unsigned rga[8]; float4 rgb[2];

    auto gather1 = [&](int kk, int m) -> __half {
        int ci = kk / 9;
        int t9 = kk - ci * 9;
        int ky = t9 / 3;
        int kx = t9 - ky * 3;
        int r = (m0 + m) & 1023;
        int oy = r >> 5, ox = r & 31;
        int iy = 2 * oy - 1 + ky, ix = 2 * ox - 1 + kx;
        __half v = __float2half(0.f);
        if ((unsigned)iy < 64u && (unsigned)ix < 64u)
            v = g_asb[(((size_t)((b << 8) + ci)) << 12) + (iy << 6) + ix];
        return v;
    };
    auto gload = [&](int k0) {
        #pragma unroll
        for (int l = 0; l < 8; l++) {
            int idx = tid + (l << 8);
            int kp = idx >> 7, m = idx & 127;
            int kk = k0 + (kp << 1);
            rga[l] = packhh(gather1(kk, m), gather1(kk + 1, m));
        }
        #pragma unroll
        for (int l = 0; l < 2; l++) {
            int idx = tid + (l << 8);
            rgb[l] = *(const float4*)&Wconv[(size_t)(n0 + (idx >> 3)) * 2304 + k0 + ((idx & 7) << 2)];
        }
    };
    auto sstore = [&]() {
        #pragma unroll
        for (int l = 0; l < 8; l++) {
            int idx = tid + (l << 8);
            Ap[idx >> 7][idx & 127] = rga[l];
        }
        #pragma unroll
        for (int l = 0; l < 2; l++) {
            int idx = tid + (l << 8);
            *(uint2*)&Bs[idx >> 3][(idx & 7) << 1] =
                make_uint2(packh2(rgb[l].x, rgb[l].y), packh2(rgb[l].z, rgb[l].w));
        }
    };

    gload(0); sstore(); __syncthreads();
    for (int k0 = 0; k0 < 2304; k0 += 32) {
        bool more = (k0 + 32) < 2304;
        if (more) gload(k0 + 32);
        #pragma unroll
        for (int ks = 0; ks < 2; ks++) {
            int kb = ks << 3;
            unsigned a[2][4], bf[4][2];
            #pragma unroll
            for (int mt = 0; mt < 2; mt++) {
                int row = (warpM << 5) + (mt << 4) + g;
                a[mt][0] = Ap[kb + tig][row];     a[mt][1] = Ap[kb + tig][row + 8];
                a[mt][2] = Ap[kb + 4 + tig][row]; a[mt][3] = Ap[kb + 4 + tig][row + 8];
            }
            #pragma unroll
            for (int nt = 0; nt < 4; nt++) {
                int col = (warpN << 5) + (nt << 3) + g;
                bf[nt][0] = Bs[col][kb + tig]; bf[nt][1] = Bs[col][kb + 4 + tig];
            }
            #pragma unroll
            for (int mt = 0; mt < 2; mt++)
                #pragma unroll
                for (int nt = 0; nt < 4; nt++)
                    mma_f16(acc[mt][nt], a[mt], bf[nt]);
        }
        __syncthreads();
        if (more) { sstore(); __syncthreads(); }
    }

    #pragma unroll
    for (int mt = 0; mt < 2; mt++)
        #pragma unroll
        for (int nt = 0; nt < 4; nt++) {
            int row = (warpM << 5) + (mt << 4) + g;
            int col = n0 + (warpN << 5) + (nt << 3) + (tig << 1);
            float* c = acc[mt][nt];
            int r1 = (m0 + row) & 1023;
            size_t b1 = (((size_t)((b << 8) + col)) << 10) + r1;
            g_c1b[b1]        = __float2half(fmaxf(c[0], 0.f));
            g_c1b[b1 + 1024] = __float2half(fmaxf(c[1], 0.f));
            int r2 = (m0 + row + 8) & 1023;
            size_t b2 = (((size_t)((b << 8) + col)) << 10) + r2;
            g_c1b[b2]        = __float2half(fmaxf(c[2], 0.f));
            g_c1b[b2 + 1024] = __float2half(fmaxf(c[3], 0.f));
        }
}

// ---------------------------------------------------------------------------
// K5: pack convT weights per parity class (fp16).
// ---------------------------------------------------------------------------
__global__ void k_packwt(const float* __restrict__ Wconvt)
{
    int i = blockIdx.x * 256 + threadIdx.x;
    int cl = i >> 18;
    int rem = i & 262143;
    int co = rem >> 10;
    int k = rem & 1023;
    int ci = k >> 2, t = k & 3;
    int tyk = t >> 1, txk = t & 1;
    int py = cl >> 1, px = cl & 1;
    int ky = 1 - py + 2 * tyk, kx = 1 - px + 2 * txk;
    g_wt2[i] = __float2half(Wconvt[(((size_t)ci * 256 + co) * 4 + ky) * 4 + kx]);
}

// ---------------------------------------------------------------------------
// K6: convT 4x4 s2 p1 + relu by parity class (fp16). M=16384, N=256, K=1024.
// ---------------------------------------------------------------------------
__global__ __launch_bounds__(256) void k_convt(void)
{
    __shared__ unsigned Ap[16][136];
    __shared__ unsigned Bs[64][20];
    int cl = blockIdx.z;
    int py = cl >> 1, px = cl & 1;
    int m0 = blockIdx.x << 7;
    int n0 = blockIdx.y << 6;
    int tid = threadIdx.x, lane = tid & 31, wid = tid >> 5;
    int warpM = wid >> 1, warpN = wid & 1;
    int g = lane >> 2, tig = lane & 3;
    int b = m0 >> 10;
    float acc[2][4][4] = {};
    unsigned rga[8]; uint2 rgb[2];

    auto gather1 = [&](int kk, int m) -> __half {
        int ci = kk >> 2, t = kk & 3;
        int tyk = t >> 1, txk = t & 1;
        int mm = m0 + m;
        int ys = (mm >> 5) & 31, xs = mm & 31;
        int ii = ys + py - tyk, jj = xs + px - txk;
        __half v = __float2half(0.f);
        if ((unsigned)ii < 32u && (unsigned)jj < 32u)
            v = g_c1b[(((size_t)((b << 8) + ci)) << 10) + (ii << 5) + jj];
        return v;
    };
    auto gload = [&](int k0) {
        #pragma unroll
        for (int l = 0; l < 8; l++) {
            int idx = tid + (l << 8);
            int kp = idx >> 7, m = idx & 127;
            int kk = k0 + (kp << 1);
            rga[l] = packhh(gather1(kk, m), gather1(kk + 1, m));
        }
        #pragma unroll
        for (int l = 0; l < 2; l++) {
            int idx = tid + (l << 8);
            rgb[l] = *(const uint2*)&g_wt2[(((size_t)((cl << 8) + n0 + (idx >> 3))) << 10) + k0 + ((idx & 7) << 2)];
        }
    };
    auto sstore = [&]() {
        #pragma unroll
        for (int l = 0; l < 8; l++) {
            int idx = tid + (l << 8);
            Ap[idx >> 7][idx & 127] = rga[l];
        }
        #pragma unroll
        for (int l = 0; l < 2; l++) {
            int idx = tid + (l << 8);
            *(uint2*)&Bs[idx >> 3][(idx & 7) << 1] = rgb[l];
        }
    };

    gload(0); sstore(); __syncthreads();
    for (int k0 = 0; k0 < 1024; k0 += 32) {
        bool more = (k0 + 32) < 1024;
        if (more) gload(k0 + 32);
        #pragma unroll
        for (int ks = 0; ks < 2; ks++) {
            int kb = ks << 3;
            unsigned a[2][4], bf[4][2];
            #pragma unroll
            for (int mt = 0; mt < 2; mt++) {
                int row = (warpM << 5) + (mt << 4) + g;
                a[mt][0] = Ap[kb + tig][row];     a[mt][1] = Ap[kb + tig][row + 8];
                a[mt][2] = Ap[kb + 4 + tig][row]; a[mt][3] = Ap[kb + 4 + tig][row + 8];
            }
            #pragma unroll
            for (int nt = 0; nt < 4; nt++) {
                int col = (warpN << 5) + (nt << 3) + g;
                bf[nt][0] = Bs[col][kb + tig]; bf[nt][1] = Bs[col][kb + 4 + tig];
            }
            #pragma unroll
            for (int mt = 0; mt < 2; mt++)
                #pragma unroll
                for (int nt = 0; nt < 4; nt++)
                    mma_f16(acc[mt][nt], a[mt], bf[nt]);
        }
        __syncthreads();
        if (more) { sstore(); __syncthreads(); }
    }

    #pragma unroll
    for (int mt = 0; mt < 2; mt++)
        #pragma unroll
        for (int nt = 0; nt < 4; nt++) {
            int row = (warpM << 5) + (mt << 4) + g;
            int col = n0 + (warpN << 5) + (nt << 3) + (tig << 1);
            float* c = acc[mt][nt];
            int mm1 = m0 + row;
            int ys1 = (mm1 >> 5) & 31, xs1 = mm1 & 31;
            size_t b1 = (((size_t)((b << 8) + col)) << 12) +
                        ((2 * ys1 + py) << 6) + (2 * xs1 + px);
            g_sbh[b1]        = __float2half(fmaxf(c[0], 0.f));
            g_sbh[b1 + 4096] = __float2half(fmaxf(c[1], 0.f));
            int mm2 = mm1 + 8;
            int ys2 = (mm2 >> 5) & 31, xs2 = mm2 & 31;
            size_t b2 = (((size_t)((b << 8) + col)) << 12) +
                        ((2 * ys2 + py) << 6) + (2 * xs2 + px);
            g_sbh[b2]        = __float2half(fmaxf(c[2], 0.f));
            g_sbh[b2 + 4096] = __float2half(fmaxf(c[3], 0.f));
        }
}

// ---------------------------------------------------------------------------
// K7: global mean pool of attn_c per (b,c)
// ---------------------------------------------------------------------------
__global__ __launch_bounds__(256) void k_pool(void)
{
    int bc = blockIdx.x;
    const float* p = g_ac + (size_t)bc * 4096;
    float s = 0.f;
    for (int i = threadIdx.x; i < 4096; i += 256) s += p[i];
    __shared__ float red[8];
    #pragma unroll
    for (int o = 16; o > 0; o >>= 1) s += __shfl_down_sync(0xffffffffu, s, o);
    int w = threadIdx.x >> 5;
    if ((threadIdx.x & 31) == 0) red[w] = s;
    __syncthreads();
    if (threadIdx.x == 0) {
        float t = 0.f;
        #pragma unroll
        for (int i = 0; i < 8; i++) t += red[i];
        g_pool[bc] = t * (1.0f / 4096.0f);
    }
}

// ---------------------------------------------------------------------------
// K8: SE MLP
// ---------------------------------------------------------------------------
__global__ __launch_bounds__(256) void k_se(const float* __restrict__ Wc1,
                                            const float* __restrict__ Wc2)
{
    int b = blockIdx.x;
    __shared__ float pool[256];
    __shared__ float hid[64];
    int t = threadIdx.x;
    pool[t] = g_pool[b * 256 + t];
    __syncthreads();
    if (t < 64) {
        float s = 0.f;
        for (int c = 0; c < 256; c++) s += pool[c] * Wc1[t * 256 + c];
        hid[t] = fmaxf(s, 0.f);
    }
    __syncthreads();
    float s = 0.f;
    #pragma unroll
    for (int j = 0; j < 64; j++) s += hid[j] * Wc2[t * 64 + j];
    g_gate[b * 256 + t] = 1.0f / (1.0f + __expf(-s));
}

// ---------------------------------------------------------------------------
// K9: fused residual + LayerNorm, smem-transposed tiles.
// ---------------------------------------------------------------------------
__global__ __launch_bounds__(256) void k_fuse(const float* __restrict__ x,
                                              const float* __restrict__ gamma,
                                              const float* __restrict__ beta,
                                              float* __restrict__ out)
{
    __shared__ float tile[256][33];
    __shared__ float red1[8][32], red2[8][32];
    __shared__ float smu[32], sri[32];
    int blk = blockIdx.x;                 // 0..2047
    int b = blk >> 7;
    int hw0 = (blk & 127) << 5;
    int t = threadIdx.x;
    int hw = t & 31, c0 = (t >> 5) << 5;

    {   // load convT output tile (fp16): thread = channel t, 32 contiguous hw
        const __half* src = g_sbh + (((size_t)(b * 256 + t)) << 12) + hw0;
        #pragma unroll
        for (int j = 0; j < 32; j += 8) {
            uint4 raw = *(const uint4*)&src[j];
            const __half2* hp = (const __half2*)&raw;
            #pragma unroll
            for (int q = 0; q < 4; q++) {
                float2 f = __half22float2(hp[q]);
                tile[t][j + (q << 1)]     = f.x;
                tile[t][j + (q << 1) + 1] = f.y;
            }
        }
    }
    __syncthreads();

    float yv[32];
    size_t mi = ((size_t)(b * 4096 + hw0 + hw)) * 256 + c0;
    #pragma unroll
    for (int i = 0; i < 32; i += 4) {
        float4 xv  = *(const float4*)&x[mi + i];
        float4 vs4 = *(const float4*)&g_vs[mi + i];
        yv[i]     = xv.x + tile[c0 + i][hw]     * vs4.x;
        yv[i + 1] = xv.y + tile[c0 + i + 1][hw] * vs4.y;
        yv[i + 2] = xv.z + tile[c0 + i + 2][hw] * vs4.z;
        yv[i + 3] = xv.w + tile[c0 + i + 3][hw] * vs4.w;
    }
    __syncthreads();

    {   // reload tile with softmaxed attn_c (fp32)
        const float* src = g_ac + (((size_t)(b * 256 + t)) << 12) + hw0;
        #pragma unroll
        for (int j = 0; j < 32; j += 4) {
            float4 v = *(const float4*)&src[j];
            tile[t][j] = v.x; tile[t][j + 1] = v.y;
            tile[t][j + 2] = v.z; tile[t][j + 3] = v.w;
        }
    }
    __syncthreads();

    #pragma unroll
    for (int i = 0; i < 32; i += 4) {
        float4 vc4 = *(const float4*)&g_vc[mi + i];
        float4 gt4 = *(const float4*)&g_gate[b * 256 + c0 + i];
        yv[i]     += gt4.x * tile[c0 + i][hw]     * vc4.x;
        yv[i + 1] += gt4.y * tile[c0 + i + 1][hw] * vc4.y;
        yv[i + 2] += gt4.z * tile[c0 + i + 2][hw] * vc4.z;
        yv[i + 3] += gt4.w * tile[c0 + i + 3][hw] * vc4.w;
    }

    float s1 = 0.f, s2 = 0.f;
    #pragma unroll
    for (int i = 0; i < 32; i++) { s1 += yv[i]; s2 += yv[i] * yv[i]; }
    red1[t >> 5][hw] = s1; red2[t >> 5][hw] = s2;
    __syncthreads();
    if (t < 32) {
        float a = 0.f, bb = 0.f;
        #pragma unroll
        for (int w = 0; w < 8; w++) { a += red1[w][t]; bb += red2[w][t]; }
        float mu = a * (1.0f / 256.0f);
        float var = bb * (1.0f / 256.0f) - mu * mu;
        smu[t] = mu; sri[t] = rsqrtf(var + 1e-5f);
    }
    __syncthreads();
    float mu = smu[hw], ri = sri[hw];
    #pragma unroll
    for (int i = 0; i < 32; i += 4) {
        float4 gm = *(const float4*)&gamma[c0 + i];
        float4 bt = *(const float4*)&beta[c0 + i];
        float4 o;
        o.x = (yv[i]     - mu) * ri * gm.x + bt.x;
        o.y = (yv[i + 1] - mu) * ri * gm.y + bt.y;
        o.z = (yv[i + 2] - mu) * ri * gm.z + bt.z;
        o.w = (yv[i + 3] - mu) * ri * gm.w + bt.w;
        *(float4*)&out[mi + i] = o;
    }
}

// ---------------------------------------------------------------------------
extern "C" void kernel_launch(void* const* d_in, const int* in_sizes, int n_in,
                              void* d_out, int out_size)
{
    const float* x      = (const float*)d_in[0];
    const float* Wq     = (const float*)d_in[1];
    const float* Wk     = (const float*)d_in[2];
    const float* Wvc    = (const float*)d_in[3];
    const float* Wvs    = (const float*)d_in[4];
    const float* Wc1    = (const float*)d_in[5];
    const float* Wc2    = (const float*)d_in[6];
    const float* Wconv  = (const float*)d_in[7];
    const float* Wconvt = (const float*)d_in[8];
    const float* gamma  = (const float*)d_in[9];
    const float* beta   = (const float*)d_in[10];
    float* out = (float*)d_out;

    k_proj <<<dim3(512, 16), 256>>>(x, Wq, Wk, Wvc, Wvs);
    k_attn <<<4096, 256>>>();
    k_softmax<<<dim3(256, 2), 256>>>();
    k_packwt<<<4096, 256>>>(Wconvt);
    k_conv <<<dim3(128, 4), 256>>>(Wconv);
    k_convt<<<dim3(128, 4, 4), 256>>>();
    k_pool <<<4096, 256>>>();
    k_se   <<<16, 256>>>(Wc1, Wc2);
    k_fuse <<<2048, 256>>>(x, gamma, beta, out);
}

// round 6
// speedup vs baseline: 2.6446x; 1.0022x over previous
#include <cuda_runtime.h>
#include <cuda_fp16.h>
#include <math.h>

// ---------------------------------------------------------------------------
// EPA_Layer: B=16, H=W=64, C=256, HID=64
// Round 5: full fp16 tensor-core pipeline (fp32 accumulate everywhere).
//   - unified 4-way fp16 projection (q/k stored fp16 [B,C,HW])
//   - fp16 attention logits (dual smem images for the transposed phase)
//   - softmax with 4 independent ILP chains
//   - convT output fp16
// ---------------------------------------------------------------------------

#define NB   16
#define NC   256
#define NHW  4096
#define NM   65536

__device__ __half g_qh [NB * NC * NHW];   // q fp16 [B,C,H,W]
__device__ __half g_kh [NB * NC * NHW];   // k fp16 [B,C,H,W]
__device__ float  g_vc [NM * NC];         // [B,H,W,C]
__device__ float  g_vs [NM * NC];         // [B,H,W,C]
__device__ float  g_as [NB * NC * NHW];   // attn_s logits [B,C,64,64]
__device__ float  g_ac [NB * NC * NHW];   // attn_c [B,C,64,64] (softmaxed in place)
__device__ __half g_asb[NB * NC * NHW];   // softmax(attn_s) fp16 (conv input)
__device__ __half g_c1b[NB * NC * 1024];  // conv3x3+relu fp16 [B,C,32,32]
__device__ __half g_sbh[NB * NC * NHW];   // convT+relu fp16 [B,C,64,64]
__device__ __half g_wt2[4 * NC * 1024];   // packed convT weights fp16
__device__ float  g_pool[NB * NC];
__device__ float  g_gate[NB * NC];

__device__ __forceinline__ unsigned packh2(float a, float b) {
    __half2 h = __floats2half2_rn(a, b);
    return *(unsigned*)&h;
}
__device__ __forceinline__ unsigned packhh(__half a, __half b) {
    __half2 h = __halves2half2(a, b);
    return *(unsigned*)&h;
}
__device__ __forceinline__ void mma_f16(float* c, const unsigned* a, const unsigned* b) {
    asm volatile(
        "mma.sync.aligned.m16n8k16.row.col.f32.f16.f16.f32 "
        "{%0,%1,%2,%3}, {%4,%5,%6,%7}, {%8,%9}, {%0,%1,%2,%3};"
        : "+f"(c[0]), "+f"(c[1]), "+f"(c[2]), "+f"(c[3])
        : "r"(a[0]), "r"(a[1]), "r"(a[2]), "r"(a[3]), "r"(b[0]), "r"(b[1]));
}

// ---------------------------------------------------------------------------
// K1: unified 4-way projection (fp16 mma). BM=128, BN=64, BK=32.
// which = blockIdx.y>>2: 0=q,1=k (fp16 -> [B,C,HW]); 2=vc,3=vs (fp32 [M,C]).
// ---------------------------------------------------------------------------
__global__ __launch_bounds__(256) void k_proj(
    const float* __restrict__ x,
    const float* __restrict__ Wq, const float* __restrict__ Wk,
    const float* __restrict__ Wvc, const float* __restrict__ Wvs)
{
    __shared__ unsigned As[128][20];   // half2 units
    __shared__ unsigned Bs[64][20];
    int m0 = blockIdx.x << 7;
    int nb = blockIdx.y;
    int which = nb >> 2;
    int d0 = (nb & 3) << 6;
    const float* W = (which == 0) ? Wq : (which == 1) ? Wk : (which == 2) ? Wvc : Wvs;
    int tid = threadIdx.x, lane = tid & 31, wid = tid >> 5;
    int warpM = wid >> 1, warpN = wid & 1;
    int g = lane >> 2, tig = lane & 3;
    float acc[2][4][4] = {};
    float4 ra[4], rb[2];

    auto gload = [&](int k0) {
        #pragma unroll
        for (int l = 0; l < 4; l++) {
            int idx = tid + (l << 8);
            ra[l] = *(const float4*)&x[(size_t)(m0 + (idx >> 3)) * 256 + k0 + ((idx & 7) << 2)];
        }
        #pragma unroll
        for (int l = 0; l < 2; l++) {
            int idx = tid + (l << 8);
            rb[l] = *(const float4*)&W[(size_t)(d0 + (idx >> 3)) * 256 + k0 + ((idx & 7) << 2)];
        }
    };
    auto sstore = [&]() {
        #pragma unroll
        for (int l = 0; l < 4; l++) {
            int idx = tid + (l << 8);
            *(uint2*)&As[idx >> 3][(idx & 7) << 1] =
                make_uint2(packh2(ra[l].x, ra[l].y), packh2(ra[l].z, ra[l].w));
        }
        #pragma unroll
        for (int l = 0; l < 2; l++) {
            int idx = tid + (l << 8);
            *(uint2*)&Bs[idx >> 3][(idx & 7) << 1] =
                make_uint2(packh2(rb[l].x, rb[l].y), packh2(rb[l].z, rb[l].w));
        }
    };

    gload(0); sstore(); __syncthreads();
    for (int k0 = 0; k0 < 256; k0 += 32) {
        bool more = (k0 + 32) < 256;
        if (more) gload(k0 + 32);
        #pragma unroll
        for (int ks = 0; ks < 2; ks++) {
            int kb = ks << 3;
            unsigned a[2][4], bf[4][2];
            #pragma unroll
            for (int mt = 0; mt < 2; mt++) {
                int row = (warpM << 5) + (mt << 4) + g;
                a[mt][0] = As[row][kb + tig];     a[mt][1] = As[row + 8][kb + tig];
                a[mt][2] = As[row][kb + 4 + tig]; a[mt][3] = As[row + 8][kb + 4 + tig];
            }
            #pragma unroll
            for (int nt = 0; nt < 4; nt++) {
                int col = (warpN << 5) + (nt << 3) + g;
                bf[nt][0] = Bs[col][kb + tig]; bf[nt][1] = Bs[col][kb + 4 + tig];
            }
            #pragma unroll
            for (int mt = 0; mt < 2; mt++)
                #pragma unroll
                for (int nt = 0; nt < 4; nt++)
                    mma_f16(acc[mt][nt], a[mt], bf[nt]);
        }
        __syncthreads();
        if (more) { sstore(); __syncthreads(); }
    }

    if (which < 2) {
        __half* dst = which ? g_kh : g_qh;
        int b = m0 >> 12;
        int hw0 = m0 & 4095;
        #pragma unroll
        for (int mt = 0; mt < 2; mt++)
            #pragma unroll
            for (int nt = 0; nt < 4; nt++) {
                int row = (warpM << 5) + (mt << 4) + g;
                int col = (warpN << 5) + (nt << 3) + (tig << 1);
                float* c = acc[mt][nt];
                size_t bi = (size_t)((b << 8) + d0 + col) * 4096 + hw0;
                dst[bi + row]            = __float2half(c[0]);
                dst[bi + 4096 + row]     = __float2half(c[1]);
                dst[bi + row + 8]        = __float2half(c[2]);
                dst[bi + 4096 + row + 8] = __float2half(c[3]);
            }
    } else {
        float* dst = (which == 2) ? g_vc : g_vs;
        #pragma unroll
        for (int mt = 0; mt < 2; mt++)
            #pragma unroll
            for (int nt = 0; nt < 4; nt++) {
                int row = (warpM << 5) + (mt << 4) + g;
                int col = (warpN << 5) + (nt << 3) + (tig << 1);
                float* c = acc[mt][nt];
                *(float2*)&dst[(size_t)(m0 + row) * 256 + d0 + col] =
                    make_float2(c[0], c[1]);
                *(float2*)&dst[(size_t)(m0 + row + 8) * 256 + d0 + col] =
                    make_float2(c[2], c[3]);
            }
    }
}

// ---------------------------------------------------------------------------
// K2: per-(b,c) attention logits (fp16 mma, fp32 accum).
// Dual smem images: natural [h][w] (phase 1) + transposed [w][h] (phase 2),
// since fp16 fragments need k-contiguous half2 pairs.
// ---------------------------------------------------------------------------
__global__ __launch_bounds__(256) void k_attn(void)
{
    __shared__ __half Qs[64][72];   // [h][w]
    __shared__ __half Ks[64][72];
    __shared__ __half Qt[64][72];   // [w][h]
    __shared__ __half Kt[64][72];
    int bc = blockIdx.x;
    const __half* Q = g_qh + (size_t)bc * 4096;
    const __half* K = g_kh + (size_t)bc * 4096;
    int tid = threadIdx.x, lane = tid & 31, wid = tid >> 5;
    int warpM = wid >> 1, warpN = wid & 1;
    int g = lane >> 2, tig = lane & 3;

    #pragma unroll
    for (int l = 0; l < 16; l++) {
        int idx = tid + (l << 8);
        int h = idx >> 6, w = idx & 63;
        __half qv = Q[idx], kv = K[idx];
        Qs[h][w] = qv; Ks[h][w] = kv;
        Qt[w][h] = qv; Kt[w][h] = kv;
    }
    __syncthreads();

    {   // Phase 1: S1[h][gg] = sum_w Q[h][w] K[gg][w]
        float acc[4][4] = {};
        #pragma unroll
        for (int ks = 0; ks < 4; ks++) {
            int kh = ks << 4;
            unsigned a[4], b[4][2];
            int row = (warpM << 4) + g;
            a[0] = *(const unsigned*)&Qs[row][kh + (tig << 1)];
            a[1] = *(const unsigned*)&Qs[row + 8][kh + (tig << 1)];
            a[2] = *(const unsigned*)&Qs[row][kh + 8 + (tig << 1)];
            a[3] = *(const unsigned*)&Qs[row + 8][kh + 8 + (tig << 1)];
            #pragma unroll
            for (int nt = 0; nt < 4; nt++) {
                int col = (warpN << 5) + (nt << 3) + g;
                b[nt][0] = *(const unsigned*)&Ks[col][kh + (tig << 1)];
                b[nt][1] = *(const unsigned*)&Ks[col][kh + 8 + (tig << 1)];
            }
            #pragma unroll
            for (int nt = 0; nt < 4; nt++) mma_f16(acc[nt], a, b[nt]);
        }
        float* out = g_as + (size_t)bc * 4096;
        #pragma unroll
        for (int nt = 0; nt < 4; nt++) {
            int row = (warpM << 4) + g;
            int col = (warpN << 5) + (nt << 3) + (tig << 1);
            *(float2*)&out[row * 64 + col]       = make_float2(acc[nt][0], acc[nt][1]);
            *(float2*)&out[(row + 8) * 64 + col] = make_float2(acc[nt][2], acc[nt][3]);
        }
    }
    {   // Phase 2: S2[w][v] = sum_h Q[h][w] K[h][v]
        float acc[4][4] = {};
        #pragma unroll
        for (int ks = 0; ks < 4; ks++) {
            int kh = ks << 4;
            unsigned a[4], b[4][2];
            int row = (warpM << 4) + g;
            a[0] = *(const unsigned*)&Qt[row][kh + (tig << 1)];
            a[1] = *(const unsigned*)&Qt[row + 8][kh + (tig << 1)];
            a[2] = *(const unsigned*)&Qt[row][kh + 8 + (tig << 1)];
            a[3] = *(const unsigned*)&Qt[row + 8][kh + 8 + (tig << 1)];
            #pragma unroll
            for (int nt = 0; nt < 4; nt++) {
                int col = (warpN << 5) + (nt << 3) + g;
                b[nt][0] = *(const unsigned*)&Kt[col][kh + (tig << 1)];
                b[nt][1] = *(const unsigned*)&Kt[col][kh + 8 + (tig << 1)];
            }
            #pragma unroll
            for (int nt = 0; nt < 4; nt++) mma_f16(acc[nt], a, b[nt]);
        }
        float* out = g_ac + (size_t)bc * 4096;
        #pragma unroll
        for (int nt = 0; nt < 4; nt++) {
            int row = (warpM << 4) + g;
            int col = (warpN << 5) + (nt << 3) + (tig << 1);
            *(float2*)&out[row * 64 + col]       = make_float2(acc[nt][0], acc[nt][1]);
            *(float2*)&out[(row + 8) * 64 + col] = make_float2(acc[nt][2], acc[nt][3]);
        }
    }
}

// ---------------------------------------------------------------------------
// K3: channel softmax (axis c, stride 4096), 4 independent ILP chains.
// y=0: attn_s -> fp16 g_asb. y=1: attn_c in place (fp32).
// ---------------------------------------------------------------------------
__global__ __launch_bounds__(256) void k_softmax(void)
{
    int which = blockIdx.y;
    float* t = which ? g_ac : g_as;
    int p = blockIdx.x * 256 + threadIdx.x;
    int b = p >> 12, pos = p & 4095;
    float* base = t + (size_t)b * (256 * 4096) + pos;

    float m0 = -3.0e38f, m1 = m0, m2 = m0, m3 = m0;
    float s0 = 0.f, s1 = 0.f, s2 = 0.f, s3 = 0.f;
    for (int c = 0; c < 64; c++) {
        float v0 = base[(size_t)c << 12];
        float v1 = base[(size_t)(c + 64) << 12];
        float v2 = base[(size_t)(c + 128) << 12];
        float v3 = base[(size_t)(c + 192) << 12];
        float n0 = fmaxf(m0, v0); s0 = s0 * __expf(m0 - n0) + __expf(v0 - n0); m0 = n0;
        float n1 = fmaxf(m1, v1); s1 = s1 * __expf(m1 - n1) + __expf(v1 - n1); m1 = n1;
        float n2 = fmaxf(m2, v2); s2 = s2 * __expf(m2 - n2) + __expf(v2 - n2); m2 = n2;
        float n3 = fmaxf(m3, v3); s3 = s3 * __expf(m3 - n3) + __expf(v3 - n3); m3 = n3;
    }
    float M = fmaxf(fmaxf(m0, m1), fmaxf(m2, m3));
    float S = s0 * __expf(m0 - M) + s1 * __expf(m1 - M) +
              s2 * __expf(m2 - M) + s3 * __expf(m3 - M);
    float inv = 1.0f / S;

    if (which) {
        for (int c = 0; c < 64; c++) {
            size_t o0 = (size_t)c << 12, o1 = (size_t)(c + 64) << 12;
            size_t o2 = (size_t)(c + 128) << 12, o3 = (size_t)(c + 192) << 12;
            float v0 = base[o0], v1 = base[o1], v2 = base[o2], v3 = base[o3];
            base[o0] = __expf(v0 - M) * inv;
            base[o1] = __expf(v1 - M) * inv;
            base[o2] = __expf(v2 - M) * inv;
            base[o3] = __expf(v3 - M) * inv;
        }
    } else {
        __half* ob = g_asb + (size_t)b * (256 * 4096) + pos;
        for (int c = 0; c < 64; c++) {
            size_t o0 = (size_t)c << 12, o1 = (size_t)(c + 64) << 12;
            size_t o2 = (size_t)(c + 128) << 12, o3 = (size_t)(c + 192) << 12;
            float v0 = base[o0], v1 = base[o1], v2 = base[o2], v3 = base[o3];
            ob[o0] = __float2half(__expf(v0 - M) * inv);
            ob[o1] = __float2half(__expf(v1 - M) * inv);
            ob[o2] = __float2half(__expf(v2 - M) * inv);
            ob[o3] = __float2half(__expf(v3 - M) * inv);
        }
    }
}

// ---------------------------------------------------------------------------
// K4: conv3x3 s2 p1 + relu (fp16 implicit GEMM). M=16384, N=256, K=2304, BK=32.
// ---------------------------------------------------------------------------
__global__ __launch_bounds__(256) void k_conv(const float* __restrict__ Wconv)
{
    __shared__ unsigned Ap[16][136];   // [kp][m]
    __shared__ unsigned Bs[64][20];
    int m0 = blockIdx.x << 7;
    int n0 = blockIdx.y << 6;
    int tid = threadIdx.x, lane = tid & 31, wid = tid >> 5;
    int warpM = wid >> 1, warpN = wid & 1;
    int g = lane >> 2, tig = lane & 3;
    int b = m0 >> 10;
    float acc[2][4][4] = {};
    unsigned rga[8]; float4 rgb[2];

    auto gather1 = [&](int kk, int m) -> __half {
        int ci = kk / 9;
        int t9 = kk - ci * 9;
        int ky = t9 / 3;
        int kx = t9 - ky * 3;
        int r = (m0 + m) & 1023;
        int oy = r >> 5, ox = r & 31;
        int iy = 2 * oy - 1 + ky, ix = 2 * ox - 1 + kx;
        __half v = __float2half(0.f);
        if ((unsigned)iy < 64u && (unsigned)ix < 64u)
            v = g_asb[(((size_t)((b << 8) + ci)) << 12) + (iy << 6) + ix];
        return v;
    };
    auto gload = [&](int k0) {
        #pragma unroll
        for (int l = 0; l < 8; l++) {
            int idx = tid + (l << 8);
            int kp = idx >> 7, m = idx & 127;
            int kk = k0 + (kp << 1);
            rga[l] = packhh(gather1(kk, m), gather1(kk + 1, m));
        }
        #pragma unroll
        for (int l = 0; l < 2; l++) {
            int idx = tid + (l << 8);
            rgb[l] = *(const float4*)&Wconv[(size_t)(n0 + (idx >> 3)) * 2304 + k0 + ((idx & 7) << 2)];
        }
    };
    auto sstore = [&]() {
        #pragma unroll
        for (int l = 0; l < 8; l++) {
            int idx = tid + (l << 8);
            Ap[idx >> 7][idx & 127] = rga[l];
        }
        #pragma unroll
        for (int l = 0; l < 2; l++) {
            int idx = tid + (l << 8);
            *(uint2*)&Bs[idx >> 3][(idx & 7) << 1] =
                make_uint2(packh2(rgb[l].x, rgb[l].y), packh2(rgb[l].z, rgb[l].w));
        }
    };

    gload(0); sstore(); __syncthreads();
    for (int k0 = 0; k0 < 2304; k0 += 32) {
        bool more = (k0 + 32) < 2304;
        if (more) gload(k0 + 32);
        #pragma unroll
        for (int ks = 0; ks < 2; ks++) {
            int kb = ks << 3;
            unsigned a[2][4], bf[4][2];
            #pragma unroll
            for (int mt = 0; mt < 2; mt++) {
                int row = (warpM << 5) + (mt << 4) + g;
                a[mt][0] = Ap[kb + tig][row];     a[mt][1] = Ap[kb + tig][row + 8];
                a[mt][2] = Ap[kb + 4 + tig][row]; a[mt][3] = Ap[kb + 4 + tig][row + 8];
            }
            #pragma unroll
            for (int nt = 0; nt < 4; nt++) {
                int col = (warpN << 5) + (nt << 3) + g;
                bf[nt][0] = Bs[col][kb + tig]; bf[nt][1] = Bs[col][kb + 4 + tig];
            }
            #pragma unroll
            for (int mt = 0; mt < 2; mt++)
                #pragma unroll
                for (int nt = 0; nt < 4; nt++)
                    mma_f16(acc[mt][nt], a[mt], bf[nt]);
        }
        __syncthreads();
        if (more) { sstore(); __syncthreads(); }
    }

    #pragma unroll
    for (int mt = 0; mt < 2; mt++)
        #pragma unroll
        for (int nt = 0; nt < 4; nt++) {
            int row = (warpM << 5) + (mt << 4) + g;
            int col = n0 + (warpN << 5) + (nt << 3) + (tig << 1);
            float* c = acc[mt][nt];
            int r1 = (m0 + row) & 1023;
            size_t b1 = (((size_t)((b << 8) + col)) << 10) + r1;
            g_c1b[b1]        = __float2half(fmaxf(c[0], 0.f));
            g_c1b[b1 + 1024] = __float2half(fmaxf(c[1], 0.f));
            int r2 = (m0 + row + 8) & 1023;
            size_t b2 = (((size_t)((b << 8) + col)) << 10) + r2;
            g_c1b[b2]        = __float2half(fmaxf(c[2], 0.f));
            g_c1b[b2 + 1024] = __float2half(fmaxf(c[3], 0.f));
        }
}

// ---------------------------------------------------------------------------
// K5: pack convT weights per parity class (fp16).
// ---------------------------------------------------------------------------
__global__ void k_packwt(const float* __restrict__ Wconvt)
{
    int i = blockIdx.x * 256 + threadIdx.x;
    int cl = i >> 18;
    int rem = i & 262143;
    int co = rem >> 10;
    int k = rem & 1023;
    int ci = k >> 2, t = k & 3;
    int tyk = t >> 1, txk = t & 1;
    int py = cl >> 1, px = cl & 1;
    int ky = 1 - py + 2 * tyk, kx = 1 - px + 2 * txk;
    g_wt2[i] = __float2half(Wconvt[(((size_t)ci * 256 + co) * 4 + ky) * 4 + kx]);
}

// ---------------------------------------------------------------------------
// K6: convT 4x4 s2 p1 + relu by parity class (fp16). M=16384, N=256, K=1024.
// ---------------------------------------------------------------------------
__global__ __launch_bounds__(256) void k_convt(void)
{
    __shared__ unsigned Ap[16][136];
    __shared__ unsigned Bs[64][20];
    int cl = blockIdx.z;
    int py = cl >> 1, px = cl & 1;
    int m0 = blockIdx.x << 7;
    int n0 = blockIdx.y << 6;
    int tid = threadIdx.x, lane = tid & 31, wid = tid >> 5;
    int warpM = wid >> 1, warpN = wid & 1;
    int g = lane >> 2, tig = lane & 3;
    int b = m0 >> 10;
    float acc[2][4][4] = {};
    unsigned rga[8]; uint2 rgb[2];

    auto gather1 = [&](int kk, int m) -> __half {
        int ci = kk >> 2, t = kk & 3;
        int tyk = t >> 1, txk = t & 1;
        int mm = m0 + m;
        int ys = (mm >> 5) & 31, xs = mm & 31;
        int ii = ys + py - tyk, jj = xs + px - txk;
        __half v = __float2half(0.f);
        if ((unsigned)ii < 32u && (unsigned)jj < 32u)
            v = g_c1b[(((size_t)((b << 8) + ci)) << 10) + (ii << 5) + jj];
        return v;
    };
    auto gload = [&](int k0) {
        #pragma unroll
        for (int l = 0; l < 8; l++) {
            int idx = tid + (l << 8);
            int kp = idx >> 7, m = idx & 127;
            int kk = k0 + (kp << 1);
            rga[l] = packhh(gather1(kk, m), gather1(kk + 1, m));
        }
        #pragma unroll
        for (int l = 0; l < 2; l++) {
            int idx = tid + (l << 8);
            rgb[l] = *(const uint2*)&g_wt2[(((size_t)((cl << 8) + n0 + (idx >> 3))) << 10) + k0 + ((idx & 7) << 2)];
        }
    };
    auto sstore = [&]() {
        #pragma unroll
        for (int l = 0; l < 8; l++) {
            int idx = tid + (l << 8);
            Ap[idx >> 7][idx & 127] = rga[l];
        }
        #pragma unroll
        for (int l = 0; l < 2; l++) {
            int idx = tid + (l << 8);
            *(uint2*)&Bs[idx >> 3][(idx & 7) << 1] = rgb[l];
        }
    };

    gload(0); sstore(); __syncthreads();
    for (int k0 = 0; k0 < 1024; k0 += 32) {
        bool more = (k0 + 32) < 1024;
        if (more) gload(k0 + 32);
        #pragma unroll
        for (int ks = 0; ks < 2; ks++) {
            int kb = ks << 3;
            unsigned a[2][4], bf[4][2];
            #pragma unroll
            for (int mt = 0; mt < 2; mt++) {
                int row = (warpM << 5) + (mt << 4) + g;
                a[mt][0] = Ap[kb + tig][row];     a[mt][1] = Ap[kb + tig][row + 8];
                a[mt][2] = Ap[kb + 4 + tig][row]; a[mt][3] = Ap[kb + 4 + tig][row + 8];
            }
            #pragma unroll
            for (int nt = 0; nt < 4; nt++) {
                int col = (warpN << 5) + (nt << 3) + g;
                bf[nt][0] = Bs[col][kb + tig]; bf[nt][1] = Bs[col][kb + 4 + tig];
            }
            #pragma unroll
            for (int mt = 0; mt < 2; mt++)
                #pragma unroll
                for (int nt = 0; nt < 4; nt++)
                    mma_f16(acc[mt][nt], a[mt], bf[nt]);
        }
        __syncthreads();
        if (more) { sstore(); __syncthreads(); }
    }

    #pragma unroll
    for (int mt = 0; mt < 2; mt++)
        #pragma unroll
        for (int nt = 0; nt < 4; nt++) {
            int row = (warpM << 5) + (mt << 4) + g;
            int col = n0 + (warpN << 5) + (nt << 3) + (tig << 1);
            float* c = acc[mt][nt];
            int mm1 = m0 + row;
            int ys1 = (mm1 >> 5) & 31, xs1 = mm1 & 31;
            size_t b1 = (((size_t)((b << 8) + col)) << 12) +
                        ((2 * ys1 + py) << 6) + (2 * xs1 + px);
            g_sbh[b1]        = __float2half(fmaxf(c[0], 0.f));
            g_sbh[b1 + 4096] = __float2half(fmaxf(c[1], 0.f));
            int mm2 = mm1 + 8;
            int ys2 = (mm2 >> 5) & 31, xs2 = mm2 & 31;
            size_t b2 = (((size_t)((b << 8) + col)) << 12) +
                        ((2 * ys2 + py) << 6) + (2 * xs2 + px);
            g_sbh[b2]        = __float2half(fmaxf(c[2], 0.f));
            g_sbh[b2 + 4096] = __float2half(fmaxf(c[3], 0.f));
        }
}

// ---------------------------------------------------------------------------
// K7: global mean pool of attn_c per (b,c)
// ---------------------------------------------------------------------------
__global__ __launch_bounds__(256) void k_pool(void)
{
    int bc = blockIdx.x;
    const float* p = g_ac + (size_t)bc * 4096;
    float s = 0.f;
    for (int i = threadIdx.x; i < 4096; i += 256) s += p[i];
    __shared__ float red[8];
    #pragma unroll
    for (int o = 16; o > 0; o >>= 1) s += __shfl_down_sync(0xffffffffu, s, o);
    int w = threadIdx.x >> 5;
    if ((threadIdx.x & 31) == 0) red[w] = s;
    __syncthreads();
    if (threadIdx.x == 0) {
        float t = 0.f;
        #pragma unroll
        for (int i = 0; i < 8; i++) t += red[i];
        g_pool[bc] = t * (1.0f / 4096.0f);
    }
}

// ---------------------------------------------------------------------------
// K8: SE MLP
// ---------------------------------------------------------------------------
__global__ __launch_bounds__(256) void k_se(const float* __restrict__ Wc1,
                                            const float* __restrict__ Wc2)
{
    int b = blockIdx.x;
    __shared__ float pool[256];
    __shared__ float hid[64];
    int t = threadIdx.x;
    pool[t] = g_pool[b * 256 + t];
    __syncthreads();
    if (t < 64) {
        float s = 0.f;
        for (int c = 0; c < 256; c++) s += pool[c] * Wc1[t * 256 + c];
        hid[t] = fmaxf(s, 0.f);
    }
    __syncthreads();
    float s = 0.f;
    #pragma unroll
    for (int j = 0; j < 64; j++) s += hid[j] * Wc2[t * 64 + j];
    g_gate[b * 256 + t] = 1.0f / (1.0f + __expf(-s));
}

// ---------------------------------------------------------------------------
// K9: fused residual + LayerNorm, smem-transposed tiles.
// ---------------------------------------------------------------------------
__global__ __launch_bounds__(256) void k_fuse(const float* __restrict__ x,
                                              const float* __restrict__ gamma,
                                              const float* __restrict__ beta,
                                              float* __restrict__ out)
{
    __shared__ float tile[256][33];
    __shared__ float red1[8][32], red2[8][32];
    __shared__ float smu[32], sri[32];
    int blk = blockIdx.x;                 // 0..2047
    int b = blk >> 7;
    int hw0 = (blk & 127) << 5;
    int t = threadIdx.x;
    int hw = t & 31, c0 = (t >> 5) << 5;

    {   // load convT output tile (fp16): thread = channel t, 32 contiguous hw
        const __half* src = g_sbh + (((size_t)(b * 256 + t)) << 12) + hw0;
        #pragma unroll
        for (int j = 0; j < 32; j += 8) {
            uint4 raw = *(const uint4*)&src[j];
            const __half2* hp = (const __half2*)&raw;
            #pragma unroll
            for (int q = 0; q < 4; q++) {
                float2 f = __half22float2(hp[q]);
                tile[t][j + (q << 1)]     = f.x;
                tile[t][j + (q << 1) + 1] = f.y;
            }
        }
    }
    __syncthreads();

    float yv[32];
    size_t mi = ((size_t)(b * 4096 + hw0 + hw)) * 256 + c0;
    #pragma unroll
    for (int i = 0; i < 32; i += 4) {
        float4 xv  = *(const float4*)&x[mi + i];
        float4 vs4 = *(const float4*)&g_vs[mi + i];
        yv[i]     = xv.x + tile[c0 + i][hw]     * vs4.x;
        yv[i + 1] = xv.y + tile[c0 + i + 1][hw] * vs4.y;
        yv[i + 2] = xv.z + tile[c0 + i + 2][hw] * vs4.z;
        yv[i + 3] = xv.w + tile[c0 + i + 3][hw] * vs4.w;
    }
    __syncthreads();

    {   // reload tile with softmaxed attn_c (fp32)
        const float* src = g_ac + (((size_t)(b * 256 + t)) << 12) + hw0;
        #pragma unroll
        for (int j = 0; j < 32; j += 4) {
            float4 v = *(const float4*)&src[j];
            tile[t][j] = v.x; tile[t][j + 1] = v.y;
            tile[t][j + 2] = v.z; tile[t][j + 3] = v.w;
        }
    }
    __syncthreads();

    #pragma unroll
    for (int i = 0; i < 32; i += 4) {
        float4 vc4 = *(const float4*)&g_vc[mi + i];
        float4 gt4 = *(const float4*)&g_gate[b * 256 + c0 + i];
        yv[i]     += gt4.x * tile[c0 + i][hw]     * vc4.x;
        yv[i + 1] += gt4.y * tile[c0 + i + 1][hw] * vc4.y;
        yv[i + 2] += gt4.z * tile[c0 + i + 2][hw] * vc4.z;
        yv[i + 3] += gt4.w * tile[c0 + i + 3][hw] * vc4.w;
    }

    float s1 = 0.f, s2 = 0.f;
    #pragma unroll
    for (int i = 0; i < 32; i++) { s1 += yv[i]; s2 += yv[i] * yv[i]; }
    red1[t >> 5][hw] = s1; red2[t >> 5][hw] = s2;
    __syncthreads();
    if (t < 32) {
        float a = 0.f, bb = 0.f;
        #pragma unroll
        for (int w = 0; w < 8; w++) { a += red1[w][t]; bb += red2[w][t]; }
        float mu = a * (1.0f / 256.0f);
        float var = bb * (1.0f / 256.0f) - mu * mu;
        smu[t] = mu; sri[t] = rsqrtf(var + 1e-5f);
    }
    __syncthreads();
    float mu = smu[hw], ri = sri[hw];
    #pragma unroll
    for (int i = 0; i < 32; i += 4) {
        float4 gm = *(const float4*)&gamma[c0 + i];
        float4 bt = *(const float4*)&beta[c0 + i];
        float4 o;
        o.x = (yv[i]     - mu) * ri * gm.x + bt.x;
        o.y = (yv[i + 1] - mu) * ri * gm.y + bt.y;
        o.z = (yv[i + 2] - mu) * ri * gm.z + bt.z;
        o.w = (yv[i + 3] - mu) * ri * gm.w + bt.w;
        *(float4*)&out[mi + i] = o;
    }
}

// ---------------------------------------------------------------------------
extern "C" void kernel_launch(void* const* d_in, const int* in_sizes, int n_in,
                              void* d_out, int out_size)
{
    const float* x      = (const float*)d_in[0];
    const float* Wq     = (const float*)d_in[1];
    const float* Wk     = (const float*)d_in[2];
    const float* Wvc    = (const float*)d_in[3];
    const float* Wvs    = (const float*)d_in[4];
    const float* Wc1    = (const float*)d_in[5];
    const float* Wc2    = (const float*)d_in[6];
    const float* Wconv  = (const float*)d_in[7];
    const float* Wconvt = (const float*)d_in[8];
    const float* gamma  = (const float*)d_in[9];
    const float* beta   = (const float*)d_in[10];
    float* out = (float*)d_out;

    k_proj <<<dim3(512, 16), 256>>>(x, Wq, Wk, Wvc, Wvs);
    k_attn <<<4096, 256>>>();
    k_softmax<<<dim3(256, 2), 256>>>();
    k_packwt<<<4096, 256>>>(Wconvt);
    k_conv <<<dim3(128, 4), 256>>>(Wconv);
    k_convt<<<dim3(128, 4, 4), 256>>>();
    k_pool <<<4096, 256>>>();
    k_se   <<<16, 256>>>(Wc1, Wc2);
    k_fuse <<<2048, 256>>>(x, gamma, beta, out);
}

// round 8
// speedup vs baseline: 3.9853x; 1.5070x over previous
#include <cuda_runtime.h>
#include <cuda_fp16.h>
#include <math.h>

// ---------------------------------------------------------------------------
// EPA_Layer: B=16, H=W=64, C=256, HID=64
// Round 8 (= Round 7 resubmit after infra failure): channels-last fp16 pipeline.
//   - conv/convT implicit GEMM with VECTORIZED A loads (channels-last, k=(tap,ci))
//   - transpose-softmax producing channels-last fp16
//   - fuse/pool read channels-last directly (no smem transposes)
//   - vc/vs stored fp16
// ---------------------------------------------------------------------------

#define NB   16
#define NC   256
#define NHW  4096
#define NM   65536

__device__ __half g_qh [NB * NC * NHW];   // q fp16 [B,C,H,W]
__device__ __half g_kh [NB * NC * NHW];   // k fp16 [B,C,H,W]
__device__ __half g_vch[NM * NC];         // vc fp16 [B,H,W,C]
__device__ __half g_vsh[NM * NC];         // vs fp16 [B,H,W,C]
__device__ float  g_as [NB * NC * NHW];   // attn_s logits fp32 [B,C,64,64]
__device__ float  g_ac [NB * NC * NHW];   // attn_c logits fp32 [B,C,64,64]
__device__ __half g_ash[NB * NHW * NC];   // softmax(attn_s) fp16 [B,64,64,C]
__device__ __half g_ach[NB * NHW * NC];   // softmax(attn_c) fp16 [B,64,64,C]
__device__ __half g_c1h[NB * 1024 * NC];  // conv out fp16 [B,32,32,C]
__device__ __half g_sbh[NB * NHW * NC];   // convT out fp16 [B,64,64,C]
__device__ __half g_wch[NC * 2304];       // conv weights [co][tap*256+ci]
__device__ __half g_wt2[4 * NC * 1024];   // convT weights [cl][co][t*256+ci]
__device__ float  g_poolp[NB * 16 * NC];  // pool partials
__device__ float  g_gate[NB * NC];

__device__ __forceinline__ unsigned packh2(float a, float b) {
    __half2 h = __floats2half2_rn(a, b);
    return *(unsigned*)&h;
}
__device__ __forceinline__ void mma_f16(float* c, const unsigned* a, const unsigned* b) {
    asm volatile(
        "mma.sync.aligned.m16n8k16.row.col.f32.f16.f16.f32 "
        "{%0,%1,%2,%3}, {%4,%5,%6,%7}, {%8,%9}, {%0,%1,%2,%3};"
        : "+f"(c[0]), "+f"(c[1]), "+f"(c[2]), "+f"(c[3])
        : "r"(a[0]), "r"(a[1]), "r"(a[2]), "r"(a[3]), "r"(b[0]), "r"(b[1]));
}
__device__ __forceinline__ void unp8(uint4 u, float* f) {
    const __half2* h = (const __half2*)&u;
    #pragma unroll
    for (int q = 0; q < 4; q++) {
        float2 t = __half22float2(h[q]);
        f[2 * q] = t.x; f[2 * q + 1] = t.y;
    }
}

// ---------------------------------------------------------------------------
// Weight repacks
// ---------------------------------------------------------------------------
__global__ void k_packc(const float* __restrict__ Wconv)
{
    int co = blockIdx.x, ci = threadIdx.x;
    #pragma unroll
    for (int tap = 0; tap < 9; tap++)
        g_wch[co * 2304 + tap * 256 + ci] =
            __float2half(Wconv[co * 2304 + ci * 9 + tap]);
}
__global__ void k_packt(const float* __restrict__ Wconvt)
{
    int cl = blockIdx.x >> 8, co = blockIdx.x & 255, ci = threadIdx.x;
    int py = cl >> 1, px = cl & 1;
    #pragma unroll
    for (int t = 0; t < 4; t++) {
        int tyk = t >> 1, txk = t & 1;
        int ky = 1 - py + 2 * tyk, kx = 1 - px + 2 * txk;
        g_wt2[(size_t)((cl << 8) + co) * 1024 + (t << 8) + ci] =
            __float2half(Wconvt[(size_t)ci * 4096 + co * 16 + (ky << 2) + kx]);
    }
}

// ---------------------------------------------------------------------------
// K1: unified 4-way projection (fp16 mma). BM=128, BN=64, BK=32.
// which: 0=q,1=k (fp16 -> [B,C,HW]); 2=vc,3=vs (fp16 [M,C]).
// ---------------------------------------------------------------------------
__global__ __launch_bounds__(256) void k_proj(
    const float* __restrict__ x,
    const float* __restrict__ Wq, const float* __restrict__ Wk,
    const float* __restrict__ Wvc, const float* __restrict__ Wvs)
{
    __shared__ unsigned As[128][20];
    __shared__ unsigned Bs[64][20];
    int m0 = blockIdx.x << 7;
    int nb = blockIdx.y;
    int which = nb >> 2;
    int d0 = (nb & 3) << 6;
    const float* W = (which == 0) ? Wq : (which == 1) ? Wk : (which == 2) ? Wvc : Wvs;
    int tid = threadIdx.x, lane = tid & 31, wid = tid >> 5;
    int warpM = wid >> 1, warpN = wid & 1;
    int g = lane >> 2, tig = lane & 3;
    float acc[2][4][4] = {};
    float4 ra[4], rb[2];

    auto gload = [&](int k0) {
        #pragma unroll
        for (int l = 0; l < 4; l++) {
            int idx = tid + (l << 8);
            ra[l] = *(const float4*)&x[(size_t)(m0 + (idx >> 3)) * 256 + k0 + ((idx & 7) << 2)];
        }
        #pragma unroll
        for (int l = 0; l < 2; l++) {
            int idx = tid + (l << 8);
            rb[l] = *(const float4*)&W[(size_t)(d0 + (idx >> 3)) * 256 + k0 + ((idx & 7) << 2)];
        }
    };
    auto sstore = [&]() {
        #pragma unroll
        for (int l = 0; l < 4; l++) {
            int idx = tid + (l << 8);
            *(uint2*)&As[idx >> 3][(idx & 7) << 1] =
                make_uint2(packh2(ra[l].x, ra[l].y), packh2(ra[l].z, ra[l].w));
        }
        #pragma unroll
        for (int l = 0; l < 2; l++) {
            int idx = tid + (l << 8);
            *(uint2*)&Bs[idx >> 3][(idx & 7) << 1] =
                make_uint2(packh2(rb[l].x, rb[l].y), packh2(rb[l].z, rb[l].w));
        }
    };

    gload(0); sstore(); __syncthreads();
    for (int k0 = 0; k0 < 256; k0 += 32) {
        bool more = (k0 + 32) < 256;
        if (more) gload(k0 + 32);
        #pragma unroll
        for (int ks = 0; ks < 2; ks++) {
            int kb = ks << 3;
            unsigned a[2][4], bf[4][2];
            #pragma unroll
            for (int mt = 0; mt < 2; mt++) {
                int row = (warpM << 5) + (mt << 4) + g;
                a[mt][0] = As[row][kb + tig];     a[mt][1] = As[row + 8][kb + tig];
                a[mt][2] = As[row][kb + 4 + tig]; a[mt][3] = As[row + 8][kb + 4 + tig];
            }
            #pragma unroll
            for (int nt = 0; nt < 4; nt++) {
                int col = (warpN << 5) + (nt << 3) + g;
                bf[nt][0] = Bs[col][kb + tig]; bf[nt][1] = Bs[col][kb + 4 + tig];
            }
            #pragma unroll
            for (int mt = 0; mt < 2; mt++)
                #pragma unroll
                for (int nt = 0; nt < 4; nt++)
                    mma_f16(acc[mt][nt], a[mt], bf[nt]);
        }
        __syncthreads();
        if (more) { sstore(); __syncthreads(); }
    }

    if (which < 2) {
        __half* dst = which ? g_kh : g_qh;
        int b = m0 >> 12;
        int hw0 = m0 & 4095;
        #pragma unroll
        for (int mt = 0; mt < 2; mt++)
            #pragma unroll
            for (int nt = 0; nt < 4; nt++) {
                int row = (warpM << 5) + (mt << 4) + g;
                int col = (warpN << 5) + (nt << 3) + (tig << 1);
                float* c = acc[mt][nt];
                size_t bi = (size_t)((b << 8) + d0 + col) * 4096 + hw0;
                dst[bi + row]            = __float2half(c[0]);
                dst[bi + 4096 + row]     = __float2half(c[1]);
                dst[bi + row + 8]        = __float2half(c[2]);
                dst[bi + 4096 + row + 8] = __float2half(c[3]);
            }
    } else {
        __half* dst = (which == 2) ? g_vch : g_vsh;
        #pragma unroll
        for (int mt = 0; mt < 2; mt++)
            #pragma unroll
            for (int nt = 0; nt < 4; nt++) {
                int row = (warpM << 5) + (mt << 4) + g;
                int col = (warpN << 5) + (nt << 3) + (tig << 1);
                float* c = acc[mt][nt];
                *(__half2*)&dst[(size_t)(m0 + row) * 256 + d0 + col] =
                    __floats2half2_rn(c[0], c[1]);
                *(__half2*)&dst[(size_t)(m0 + row + 8) * 256 + d0 + col] =
                    __floats2half2_rn(c[2], c[3]);
            }
    }
}

// ---------------------------------------------------------------------------
// K2: per-(b,c) attention logits (fp16 mma). Dual smem images.
// ---------------------------------------------------------------------------
__global__ __launch_bounds__(256) void k_attn(void)
{
    __shared__ __half Qs[64][72];
    __shared__ __half Ks[64][72];
    __shared__ __half Qt[64][72];
    __shared__ __half Kt[64][72];
    int bc = blockIdx.x;
    const __half* Q = g_qh + (size_t)bc * 4096;
    const __half* K = g_kh + (size_t)bc * 4096;
    int tid = threadIdx.x, lane = tid & 31, wid = tid >> 5;
    int warpM = wid >> 1, warpN = wid & 1;
    int g = lane >> 2, tig = lane & 3;

    #pragma unroll
    for (int l = 0; l < 16; l++) {
        int idx = tid + (l << 8);
        int h = idx >> 6, w = idx & 63;
        __half qv = Q[idx], kv = K[idx];
        Qs[h][w] = qv; Ks[h][w] = kv;
        Qt[w][h] = qv; Kt[w][h] = kv;
    }
    __syncthreads();

    {   // Phase 1: S1[h][gg] = sum_w Q[h][w] K[gg][w]
        float acc[4][4] = {};
        #pragma unroll
        for (int ks = 0; ks < 4; ks++) {
            int kh = ks << 4;
            unsigned a[4], b[4][2];
            int row = (warpM << 4) + g;
            a[0] = *(const unsigned*)&Qs[row][kh + (tig << 1)];
            a[1] = *(const unsigned*)&Qs[row + 8][kh + (tig << 1)];
            a[2] = *(const unsigned*)&Qs[row][kh + 8 + (tig << 1)];
            a[3] = *(const unsigned*)&Qs[row + 8][kh + 8 + (tig << 1)];
            #pragma unroll
            for (int nt = 0; nt < 4; nt++) {
                int col = (warpN << 5) + (nt << 3) + g;
                b[nt][0] = *(const unsigned*)&Ks[col][kh + (tig << 1)];
                b[nt][1] = *(const unsigned*)&Ks[col][kh + 8 + (tig << 1)];
            }
            #pragma unroll
            for (int nt = 0; nt < 4; nt++) mma_f16(acc[nt], a, b[nt]);
        }
        float* out = g_as + (size_t)bc * 4096;
        #pragma unroll
        for (int nt = 0; nt < 4; nt++) {
            int row = (warpM << 4) + g;
            int col = (warpN << 5) + (nt << 3) + (tig << 1);
            *(float2*)&out[row * 64 + col]       = make_float2(acc[nt][0], acc[nt][1]);
            *(float2*)&out[(row + 8) * 64 + col] = make_float2(acc[nt][2], acc[nt][3]);
        }
    }
    {   // Phase 2: S2[w][v] = sum_h Q[h][w] K[h][v]
        float acc[4][4] = {};
        #pragma unroll
        for (int ks = 0; ks < 4; ks++) {
            int kh = ks << 4;
            unsigned a[4], b[4][2];
            int row = (warpM << 4) + g;
            a[0] = *(const unsigned*)&Qt[row][kh + (tig << 1)];
            a[1] = *(const unsigned*)&Qt[row + 8][kh + (tig << 1)];
            a[2] = *(const unsigned*)&Qt[row][kh + 8 + (tig << 1)];
            a[3] = *(const unsigned*)&Qt[row + 8][kh + 8 + (tig << 1)];
            #pragma unroll
            for (int nt = 0; nt < 4; nt++) {
                int col = (warpN << 5) + (nt << 3) + g;
                b[nt][0] = *(const unsigned*)&Kt[col][kh + (tig << 1)];
                b[nt][1] = *(const unsigned*)&Kt[col][kh + 8 + (tig << 1)];
            }
            #pragma unroll
            for (int nt = 0; nt < 4; nt++) mma_f16(acc[nt], a, b[nt]);
        }
        float* out = g_ac + (size_t)bc * 4096;
        #pragma unroll
        for (int nt = 0; nt < 4; nt++) {
            int row = (warpM << 4) + g;
            int col = (warpN << 5) + (nt << 3) + (tig << 1);
            *(float2*)&out[row * 64 + col]       = make_float2(acc[nt][0], acc[nt][1]);
            *(float2*)&out[(row + 8) * 64 + col] = make_float2(acc[nt][2], acc[nt][3]);
        }
    }
}

// ---------------------------------------------------------------------------
// K3: transpose-softmax over channel axis.
// Reads [B,C,HW] fp32 logits, writes channels-last fp16 [B,HW,C].
// Block: one b, 32 positions. blockIdx.y: 0=attn_s, 1=attn_c.
// ---------------------------------------------------------------------------
__global__ __launch_bounds__(256) void k_softmax_t(void)
{
    __shared__ float tile[256][33];
    __shared__ float red[8][32];
    __shared__ float Mv[32], Iv[32];
    int which = blockIdx.y;
    const float* src = which ? g_ac : g_as;
    __half* dst = which ? g_ach : g_ash;
    int blk = blockIdx.x;
    int b = blk >> 7;
    int pos0 = (blk & 127) << 5;
    int tid = threadIdx.x, lane = tid & 31, wid = tid >> 5;

    const float* sb = src + (size_t)(b << 8) * 4096 + pos0;
    #pragma unroll 8
    for (int it = 0; it < 32; it++) {
        int c = (it << 3) + wid;
        tile[c][lane] = sb[(size_t)c * 4096 + lane];
    }
    __syncthreads();

    int pos = lane, cq = wid;
    int c0 = cq << 5;
    float m = -3.0e38f;
    #pragma unroll
    for (int j = 0; j < 32; j++) m = fmaxf(m, tile[c0 + j][pos]);
    red[cq][pos] = m;
    __syncthreads();
    if (tid < 32) {
        float M = -3.0e38f;
        #pragma unroll
        for (int j = 0; j < 8; j++) M = fmaxf(M, red[j][tid]);
        Mv[tid] = M;
    }
    __syncthreads();
    float M = Mv[pos];
    float s = 0.f;
    #pragma unroll
    for (int j = 0; j < 32; j++) {
        float e = __expf(tile[c0 + j][pos] - M);
        tile[c0 + j][pos] = e;
        s += e;
    }
    red[cq][pos] = s;
    __syncthreads();
    if (tid < 32) {
        float S = 0.f;
        #pragma unroll
        for (int j = 0; j < 8; j++) S += red[j][tid];
        Iv[tid] = 1.0f / S;
    }
    __syncthreads();
    float inv = Iv[pos];

    size_t rowo = ((size_t)((b << 12) + pos0 + pos)) << 8;
    #pragma unroll
    for (int q = 0; q < 4; q++) {
        int cb = c0 + (q << 3);
        uint4 u;
        u.x = packh2(tile[cb + 0][pos] * inv, tile[cb + 1][pos] * inv);
        u.y = packh2(tile[cb + 2][pos] * inv, tile[cb + 3][pos] * inv);
        u.z = packh2(tile[cb + 4][pos] * inv, tile[cb + 5][pos] * inv);
        u.w = packh2(tile[cb + 6][pos] * inv, tile[cb + 7][pos] * inv);
        *(uint4*)&dst[rowo + cb] = u;
    }
}

// ---------------------------------------------------------------------------
// K4: conv3x3 s2 p1 + relu, channels-last. Implicit GEMM M=16384,N=256,K=2304.
// K order = (tap, ci): vectorized uint4 A loads from g_ash [B,64,64,C].
// ---------------------------------------------------------------------------
__global__ __launch_bounds__(256) void k_conv(void)
{
    __shared__ unsigned As[128][20];
    __shared__ unsigned Bs[64][20];
    int m0 = blockIdx.x << 7;
    int n0 = blockIdx.y << 6;
    int tid = threadIdx.x, lane = tid & 31, wid = tid >> 5;
    int warpM = wid >> 1, warpN = wid & 1;
    int g = lane >> 2, tig = lane & 3;
    int b = m0 >> 10;
    float acc[2][4][4] = {};
    uint4 ra[2], rb;

    auto gload = [&](int k0) {
        int tap = k0 >> 8;
        int ky = tap / 3, kx = tap - ky * 3;
        int cib = (k0 & 255) + ((tid & 3) << 3);
        #pragma unroll
        for (int l = 0; l < 2; l++) {
            int idx = tid + (l << 8);
            int mrow = idx >> 2;
            int r = (m0 + mrow) & 1023;
            int oy = r >> 5, ox = r & 31;
            int iy = 2 * oy - 1 + ky, ix = 2 * ox - 1 + kx;
            if ((unsigned)iy < 64u && (unsigned)ix < 64u)
                ra[l] = *(const uint4*)&g_ash[(((size_t)(b << 12) + (iy << 6) + ix) << 8) + cib];
            else
                ra[l] = make_uint4(0u, 0u, 0u, 0u);
        }
        rb = *(const uint4*)&g_wch[(size_t)(n0 + (tid >> 2)) * 2304 + k0 + ((tid & 3) << 3)];
    };
    auto sstore = [&]() {
        #pragma unroll
        for (int l = 0; l < 2; l++) {
            int idx = tid + (l << 8);
            *(uint4*)&As[idx >> 2][(idx & 3) << 2] = ra[l];
        }
        *(uint4*)&Bs[tid >> 2][(tid & 3) << 2] = rb;
    };

    gload(0); sstore(); __syncthreads();
    for (int k0 = 0; k0 < 2304; k0 += 32) {
        bool more = (k0 + 32) < 2304;
        if (more) gload(k0 + 32);
        #pragma unroll
        for (int ks = 0; ks < 2; ks++) {
            int kb = ks << 3;
            unsigned a[2][4], bf[4][2];
            #pragma unroll
            for (int mt = 0; mt < 2; mt++) {
                int row = (warpM << 5) + (mt << 4) + g;
                a[mt][0] = As[row][kb + tig];     a[mt][1] = As[row + 8][kb + tig];
                a[mt][2] = As[row][kb + 4 + tig]; a[mt][3] = As[row + 8][kb + 4 + tig];
            }
            #pragma unroll
            for (int nt = 0; nt < 4; nt++) {
                int col = (warpN << 5) + (nt << 3) + g;
                bf[nt][0] = Bs[col][kb + tig]; bf[nt][1] = Bs[col][kb + 4 + tig];
            }
            #pragma unroll
            for (int mt = 0; mt < 2; mt++)
                #pragma unroll
                for (int nt = 0; nt < 4; nt++)
                    mma_f16(acc[mt][nt], a[mt], bf[nt]);
        }
        __syncthreads();
        if (more) { sstore(); __syncthreads(); }
    }

    // epilogue: relu, write channels-last [B,32,32,C]
    #pragma unroll
    for (int mt = 0; mt < 2; mt++)
        #pragma unroll
        for (int nt = 0; nt < 4; nt++) {
            int row = (warpM << 5) + (mt << 4) + g;
            int col = n0 + (warpN << 5) + (nt << 3) + (tig << 1);
            float* c = acc[mt][nt];
            int r1 = (m0 + row) & 1023;
            *(__half2*)&g_c1h[(((size_t)(b << 10) + r1) << 8) + col] =
                __floats2half2_rn(fmaxf(c[0], 0.f), fmaxf(c[1], 0.f));
            int r2 = (m0 + row + 8) & 1023;
            *(__half2*)&g_c1h[(((size_t)(b << 10) + r2) << 8) + col] =
                __floats2half2_rn(fmaxf(c[2], 0.f), fmaxf(c[3], 0.f));
        }
}

// ---------------------------------------------------------------------------
// K6: convT 4x4 s2 p1 + relu by parity class, channels-last.
// K order = (t, ci). M=16384, N=256, K=1024 per class.
// ---------------------------------------------------------------------------
__global__ __launch_bounds__(256) void k_convt(void)
{
    __shared__ unsigned As[128][20];
    __shared__ unsigned Bs[64][20];
    int cl = blockIdx.z;
    int py = cl >> 1, px = cl & 1;
    int m0 = blockIdx.x << 7;
    int n0 = blockIdx.y << 6;
    int tid = threadIdx.x, lane = tid & 31, wid = tid >> 5;
    int warpM = wid >> 1, warpN = wid & 1;
    int g = lane >> 2, tig = lane & 3;
    int b = m0 >> 10;
    float acc[2][4][4] = {};
    uint4 ra[2], rb;

    auto gload = [&](int k0) {
        int t = k0 >> 8;
        int tyk = t >> 1, txk = t & 1;
        int cib = (k0 & 255) + ((tid & 3) << 3);
        #pragma unroll
        for (int l = 0; l < 2; l++) {
            int idx = tid + (l << 8);
            int mrow = idx >> 2;
            int r = (m0 + mrow) & 1023;
            int ys = r >> 5, xs = r & 31;
            int ii = ys + py - tyk, jj = xs + px - txk;
            if ((unsigned)ii < 32u && (unsigned)jj < 32u)
                ra[l] = *(const uint4*)&g_c1h[(((size_t)(b << 10) + (ii << 5) + jj) << 8) + cib];
            else
                ra[l] = make_uint4(0u, 0u, 0u, 0u);
        }
        rb = *(const uint4*)&g_wt2[(size_t)((cl << 8) + n0 + (tid >> 2)) * 1024 + k0 + ((tid & 3) << 3)];
    };
    auto sstore = [&]() {
        #pragma unroll
        for (int l = 0; l < 2; l++) {
            int idx = tid + (l << 8);
            *(uint4*)&As[idx >> 2][(idx & 3) << 2] = ra[l];
        }
        *(uint4*)&Bs[tid >> 2][(tid & 3) << 2] = rb;
    };

    gload(0); sstore(); __syncthreads();
    for (int k0 = 0; k0 < 1024; k0 += 32) {
        bool more = (k0 + 32) < 1024;
        if (more) gload(k0 + 32);
        #pragma unroll
        for (int ks = 0; ks < 2; ks++) {
            int kb = ks << 3;
            unsigned a[2][4], bf[4][2];
            #pragma unroll
            for (int mt = 0; mt < 2; mt++) {
                int row = (warpM << 5) + (mt << 4) + g;
                a[mt][0] = As[row][kb + tig];     a[mt][1] = As[row + 8][kb + tig];
                a[mt][2] = As[row][kb + 4 + tig]; a[mt][3] = As[row + 8][kb + 4 + tig];
            }
            #pragma unroll
            for (int nt = 0; nt < 4; nt++) {
                int col = (warpN << 5) + (nt << 3) + g;
                bf[nt][0] = Bs[col][kb + tig]; bf[nt][1] = Bs[col][kb + 4 + tig];
            }
            #pragma unroll
            for (int mt = 0; mt < 2; mt++)
                #pragma unroll
                for (int nt = 0; nt < 4; nt++)
                    mma_f16(acc[mt][nt], a[mt], bf[nt]);
        }
        __syncthreads();
        if (more) { sstore(); __syncthreads(); }
    }

    // epilogue: relu, write channels-last [B,64,64,C] at (2ys+py, 2xs+px)
    #pragma unroll
    for (int mt = 0; mt < 2; mt++)
        #pragma unroll
        for (int nt = 0; nt < 4; nt++) {
            int row = (warpM << 5) + (mt << 4) + g;
            int col = n0 + (warpN << 5) + (nt << 3) + (tig << 1);
            float* c = acc[mt][nt];
            int mm1 = m0 + row;
            int ys1 = (mm1 >> 5) & 31, xs1 = mm1 & 31;
            size_t o1 = (((size_t)(b << 12) + (((ys1 << 1) + py) << 6) + (xs1 << 1) + px) << 8) + col;
            *(__half2*)&g_sbh[o1] = __floats2half2_rn(fmaxf(c[0], 0.f), fmaxf(c[1], 0.f));
            int mm2 = mm1 + 8;
            int ys2 = (mm2 >> 5) & 31, xs2 = mm2 & 31;
            size_t o2 = (((size_t)(b << 12) + (((ys2 << 1) + py) << 6) + (xs2 << 1) + px) << 8) + col;
            *(__half2*)&g_sbh[o2] = __floats2half2_rn(fmaxf(c[2], 0.f), fmaxf(c[3], 0.f));
        }
}

// ---------------------------------------------------------------------------
// K7: pool partials over attn_c (channels-last fp16). grid (16 b, 16 chunks).
// ---------------------------------------------------------------------------
__global__ __launch_bounds__(256) void k_poolp(void)
{
    int b = blockIdx.x, ch = blockIdx.y, c = threadIdx.x;
    const __half* p = g_ach + (((size_t)(b << 12) + (ch << 8)) << 8) + c;
    float s0 = 0.f, s1 = 0.f, s2 = 0.f, s3 = 0.f;
    for (int i = 0; i < 256; i += 4) {
        s0 += __half2float(p[(size_t)(i)     << 8]);
        s1 += __half2float(p[(size_t)(i + 1) << 8]);
        s2 += __half2float(p[(size_t)(i + 2) << 8]);
        s3 += __half2float(p[(size_t)(i + 3) << 8]);
    }
    g_poolp[((b << 4) + ch) * 256 + c] = s0 + s1 + s2 + s3;
}

// ---------------------------------------------------------------------------
// K8: SE MLP (combines pool partials)
// ---------------------------------------------------------------------------
__global__ __launch_bounds__(256) void k_se(const float* __restrict__ Wc1,
                                            const float* __restrict__ Wc2)
{
    int b = blockIdx.x;
    __shared__ float pool[256];
    __shared__ float hid[64];
    int t = threadIdx.x;
    float s = 0.f;
    #pragma unroll
    for (int j = 0; j < 16; j++) s += g_poolp[(((b << 4) + j) << 8) + t];
    pool[t] = s * (1.0f / 4096.0f);
    __syncthreads();
    if (t < 64) {
        float h = 0.f;
        for (int c = 0; c < 256; c++) h += pool[c] * Wc1[t * 256 + c];
        hid[t] = fmaxf(h, 0.f);
    }
    __syncthreads();
    float v = 0.f;
    #pragma unroll
    for (int j = 0; j < 64; j++) v += hid[j] * Wc2[t * 64 + j];
    g_gate[(b << 8) + t] = 1.0f / (1.0f + __expf(-v));
}

// ---------------------------------------------------------------------------
// K9: fused residual + LayerNorm. All inputs channels-last; warp per position.
// ---------------------------------------------------------------------------
__global__ __launch_bounds__(256) void k_fuse(const float* __restrict__ x,
                                              const float* __restrict__ gamma,
                                              const float* __restrict__ beta,
                                              float* __restrict__ out)
{
    int wid = threadIdx.x >> 5, lane = threadIdx.x & 31;
    int pos = (blockIdx.x << 3) + wid;
    int b = pos >> 12;
    size_t row = (size_t)pos << 8;
    int c0 = lane << 3;

    float4 x0 = *(const float4*)&x[row + c0];
    float4 x1 = *(const float4*)&x[row + c0 + 4];
    float vs[8], vc[8], sb[8], ac[8];
    unp8(*(const uint4*)&g_vsh[row + c0], vs);
    unp8(*(const uint4*)&g_vch[row + c0], vc);
    unp8(*(const uint4*)&g_sbh[row + c0], sb);
    unp8(*(const uint4*)&g_ach[row + c0], ac);
    float4 g0 = *(const float4*)&g_gate[(b << 8) + c0];
    float4 g1 = *(const float4*)&g_gate[(b << 8) + c0 + 4];
    float xs[8] = {x0.x, x0.y, x0.z, x0.w, x1.x, x1.y, x1.z, x1.w};
    float gt[8] = {g0.x, g0.y, g0.z, g0.w, g1.x, g1.y, g1.z, g1.w};

    float y[8];
    float s1 = 0.f, s2 = 0.f;
    #pragma unroll
    for (int j = 0; j < 8; j++) {
        y[j] = xs[j] + sb[j] * vs[j] + gt[j] * ac[j] * vc[j];
        s1 += y[j]; s2 += y[j] * y[j];
    }
    #pragma unroll
    for (int o = 16; o > 0; o >>= 1) {
        s1 += __shfl_xor_sync(0xffffffffu, s1, o);
        s2 += __shfl_xor_sync(0xffffffffu, s2, o);
    }
    float mu = s1 * (1.0f / 256.0f);
    float var = s2 * (1.0f / 256.0f) - mu * mu;
    float ri = rsqrtf(var + 1e-5f);

    float4 gm0 = *(const float4*)&gamma[c0];
    float4 gm1 = *(const float4*)&gamma[c0 + 4];
    float4 bt0 = *(const float4*)&beta[c0];
    float4 bt1 = *(const float4*)&beta[c0 + 4];
    float gm[8] = {gm0.x, gm0.y, gm0.z, gm0.w, gm1.x, gm1.y, gm1.z, gm1.w};
    float bt[8] = {bt0.x, bt0.y, bt0.z, bt0.w, bt1.x, bt1.y, bt1.z, bt1.w};
    float4 o0, o1;
    o0.x = (y[0] - mu) * ri * gm[0] + bt[0];
    o0.y = (y[1] - mu) * ri * gm[1] + bt[1];
    o0.z = (y[2] - mu) * ri * gm[2] + bt[2];
    o0.w = (y[3] - mu) * ri * gm[3] + bt[3];
    o1.x = (y[4] - mu) * ri * gm[4] + bt[4];
    o1.y = (y[5] - mu) * ri * gm[5] + bt[5];
    o1.z = (y[6] - mu) * ri * gm[6] + bt[6];
    o1.w = (y[7] - mu) * ri * gm[7] + bt[7];
    *(float4*)&out[row + c0]     = o0;
    *(float4*)&out[row + c0 + 4] = o1;
}

// ---------------------------------------------------------------------------
extern "C" void kernel_launch(void* const* d_in, const int* in_sizes, int n_in,
                              void* d_out, int out_size)
{
    const float* x      = (const float*)d_in[0];
    const float* Wq     = (const float*)d_in[1];
    const float* Wk     = (const float*)d_in[2];
    const float* Wvc    = (const float*)d_in[3];
    const float* Wvs    = (const float*)d_in[4];
    const float* Wc1    = (const float*)d_in[5];
    const float* Wc2    = (const float*)d_in[6];
    const float* Wconv  = (const float*)d_in[7];
    const float* Wconvt = (const float*)d_in[8];
    const float* gamma  = (const float*)d_in[9];
    const float* beta   = (const float*)d_in[10];
    float* out = (float*)d_out;

    k_packc<<<256, 256>>>(Wconv);
    k_packt<<<1024, 256>>>(Wconvt);
    k_proj <<<dim3(512, 16), 256>>>(x, Wq, Wk, Wvc, Wvs);
    k_attn <<<4096, 256>>>();
    k_softmax_t<<<dim3(2048, 2), 256>>>();
    k_conv <<<dim3(128, 4), 256>>>();
    k_convt<<<dim3(128, 4, 4), 256>>>();
    k_poolp<<<dim3(16, 16), 256>>>();
    k_se   <<<16, 256>>>(Wc1, Wc2);
    k_fuse <<<8192, 256>>>(x, gamma, beta, out);
}

// round 11
// speedup vs baseline: 4.8216x; 1.2099x over previous
#include <cuda_runtime.h>
#include <cuda_fp16.h>
#include <math.h>

// ---------------------------------------------------------------------------
// EPA_Layer: B=16, H=W=64, C=256, HID=64
// Round 11 (= Round 9 kernel, third submission after broker failures):
//   channels-last fp16 pipeline, BN=128 tiles (warp 32x64),
//   vectorized k_attn smem build, pool fused into softmax.
// ---------------------------------------------------------------------------

#define NB   16
#define NC   256
#define NHW  4096
#define NM   65536

__device__ __half g_qh [NB * NC * NHW];   // q fp16 [B,C,H,W]
__device__ __half g_kh [NB * NC * NHW];   // k fp16 [B,C,H,W]
__device__ __half g_vch[NM * NC];         // vc fp16 [B,H,W,C]
__device__ __half g_vsh[NM * NC];         // vs fp16 [B,H,W,C]
__device__ float  g_as [NB * NC * NHW];   // attn_s logits fp32 [B,C,64,64]
__device__ float  g_ac [NB * NC * NHW];   // attn_c logits fp32 [B,C,64,64]
__device__ __half g_ash[NB * NHW * NC];   // softmax(attn_s) fp16 [B,64,64,C]
__device__ __half g_ach[NB * NHW * NC];   // softmax(attn_c) fp16 [B,64,64,C]
__device__ __half g_c1h[NB * 1024 * NC];  // conv out fp16 [B,32,32,C]
__device__ __half g_sbh[NB * NHW * NC];   // convT out fp16 [B,64,64,C]
__device__ __half g_wch[NC * 2304];       // conv weights [co][tap*256+ci]
__device__ __half g_wt2[4 * NC * 1024];   // convT weights [cl][co][t*256+ci]
__device__ float  g_poolp[NB * 128 * NC]; // pool partials (per softmax block)
__device__ float  g_gate[NB * NC];

__device__ __forceinline__ unsigned packh2(float a, float b) {
    __half2 h = __floats2half2_rn(a, b);
    return *(unsigned*)&h;
}
__device__ __forceinline__ void mma_f16(float* c, const unsigned* a, const unsigned* b) {
    asm volatile(
        "mma.sync.aligned.m16n8k16.row.col.f32.f16.f16.f32 "
        "{%0,%1,%2,%3}, {%4,%5,%6,%7}, {%8,%9}, {%0,%1,%2,%3};"
        : "+f"(c[0]), "+f"(c[1]), "+f"(c[2]), "+f"(c[3])
        : "r"(a[0]), "r"(a[1]), "r"(a[2]), "r"(a[3]), "r"(b[0]), "r"(b[1]));
}
__device__ __forceinline__ void unp8(uint4 u, float* f) {
    const __half2* h = (const __half2*)&u;
    #pragma unroll
    for (int q = 0; q < 4; q++) {
        float2 t = __half22float2(h[q]);
        f[2 * q] = t.x; f[2 * q + 1] = t.y;
    }
}

// ---------------------------------------------------------------------------
// Weight repacks
// ---------------------------------------------------------------------------
__global__ void k_packc(const float* __restrict__ Wconv)
{
    int co = blockIdx.x, ci = threadIdx.x;
    #pragma unroll
    for (int tap = 0; tap < 9; tap++)
        g_wch[co * 2304 + tap * 256 + ci] =
            __float2half(Wconv[co * 2304 + ci * 9 + tap]);
}
__global__ void k_packt(const float* __restrict__ Wconvt)
{
    int cl = blockIdx.x >> 8, co = blockIdx.x & 255, ci = threadIdx.x;
    int py = cl >> 1, px = cl & 1;
    #pragma unroll
    for (int t = 0; t < 4; t++) {
        int tyk = t >> 1, txk = t & 1;
        int ky = 1 - py + 2 * tyk, kx = 1 - px + 2 * txk;
        g_wt2[(size_t)((cl << 8) + co) * 1024 + (t << 8) + ci] =
            __float2half(Wconvt[(size_t)ci * 4096 + co * 16 + (ky << 2) + kx]);
    }
}

// ---------------------------------------------------------------------------
// K1: unified 4-way projection (fp16 mma). BM=128, BN=128, BK=32.
// blockIdx.y: which = y>>1 (0=q,1=k,2=vc,3=vs), d0 = (y&1)*128.
// Warp layout 4x2; warp tile 32x64.
// ---------------------------------------------------------------------------
__global__ __launch_bounds__(256) void k_proj(
    const float* __restrict__ x,
    const float* __restrict__ Wq, const float* __restrict__ Wk,
    const float* __restrict__ Wvc, const float* __restrict__ Wvs)
{
    __shared__ unsigned As[128][20];
    __shared__ unsigned Bs[128][20];
    int m0 = blockIdx.x << 7;
    int nb = blockIdx.y;
    int which = nb >> 1;
    int d0 = (nb & 1) << 7;
    const float* W = (which == 0) ? Wq : (which == 1) ? Wk : (which == 2) ? Wvc : Wvs;
    int tid = threadIdx.x, lane = tid & 31, wid = tid >> 5;
    int warpM = wid >> 1, warpN = wid & 1;
    int g = lane >> 2, tig = lane & 3;
    float acc[2][8][4] = {};
    float4 ra[4], rb[4];

    auto gload = [&](int k0) {
        #pragma unroll
        for (int l = 0; l < 4; l++) {
            int idx = tid + (l << 8);
            ra[l] = *(const float4*)&x[(size_t)(m0 + (idx >> 3)) * 256 + k0 + ((idx & 7) << 2)];
            rb[l] = *(const float4*)&W[(size_t)(d0 + (idx >> 3)) * 256 + k0 + ((idx & 7) << 2)];
        }
    };
    auto sstore = [&]() {
        #pragma unroll
        for (int l = 0; l < 4; l++) {
            int idx = tid + (l << 8);
            *(uint2*)&As[idx >> 3][(idx & 7) << 1] =
                make_uint2(packh2(ra[l].x, ra[l].y), packh2(ra[l].z, ra[l].w));
            *(uint2*)&Bs[idx >> 3][(idx & 7) << 1] =
                make_uint2(packh2(rb[l].x, rb[l].y), packh2(rb[l].z, rb[l].w));
        }
    };

    gload(0); sstore(); __syncthreads();
    for (int k0 = 0; k0 < 256; k0 += 32) {
        bool more = (k0 + 32) < 256;
        if (more) gload(k0 + 32);
        #pragma unroll
        for (int ks = 0; ks < 2; ks++) {
            int kb = ks << 3;
            unsigned a[2][4], bf[8][2];
            #pragma unroll
            for (int mt = 0; mt < 2; mt++) {
                int row = (warpM << 5) + (mt << 4) + g;
                a[mt][0] = As[row][kb + tig];     a[mt][1] = As[row + 8][kb + tig];
                a[mt][2] = As[row][kb + 4 + tig]; a[mt][3] = As[row + 8][kb + 4 + tig];
            }
            #pragma unroll
            for (int nt = 0; nt < 8; nt++) {
                int col = (warpN << 6) + (nt << 3) + g;
                bf[nt][0] = Bs[col][kb + tig]; bf[nt][1] = Bs[col][kb + 4 + tig];
            }
            #pragma unroll
            for (int mt = 0; mt < 2; mt++)
                #pragma unroll
                for (int nt = 0; nt < 8; nt++)
                    mma_f16(acc[mt][nt], a[mt], bf[nt]);
        }
        __syncthreads();
        if (more) { sstore(); __syncthreads(); }
    }

    if (which < 2) {
        __half* dst = which ? g_kh : g_qh;
        int b = m0 >> 12;
        int hw0 = m0 & 4095;
        #pragma unroll
        for (int mt = 0; mt < 2; mt++)
            #pragma unroll
            for (int nt = 0; nt < 8; nt++) {
                int row = (warpM << 5) + (mt << 4) + g;
                int col = d0 + (warpN << 6) + (nt << 3) + (tig << 1);
                float* c = acc[mt][nt];
                size_t bi = (size_t)((b << 8) + col) * 4096 + hw0;
                dst[bi + row]            = __float2half(c[0]);
                dst[bi + 4096 + row]     = __float2half(c[1]);
                dst[bi + row + 8]        = __float2half(c[2]);
                dst[bi + 4096 + row + 8] = __float2half(c[3]);
            }
    } else {
        __half* dst = (which == 2) ? g_vch : g_vsh;
        #pragma unroll
        for (int mt = 0; mt < 2; mt++)
            #pragma unroll
            for (int nt = 0; nt < 8; nt++) {
                int row = (warpM << 5) + (mt << 4) + g;
                int col = d0 + (warpN << 6) + (nt << 3) + (tig << 1);
                float* c = acc[mt][nt];
                *(__half2*)&dst[(size_t)(m0 + row) * 256 + col] =
                    __floats2half2_rn(c[0], c[1]);
                *(__half2*)&dst[(size_t)(m0 + row + 8) * 256 + col] =
                    __floats2half2_rn(c[2], c[3]);
            }
    }
}

// ---------------------------------------------------------------------------
// K2: per-(b,c) attention logits (fp16 mma). Vectorized smem build:
// uint4 loads + uint4 natural store; transposed image scattered from regs.
// ---------------------------------------------------------------------------
__global__ __launch_bounds__(256) void k_attn(void)
{
    __shared__ __half Qs[64][72];
    __shared__ __half Ks[64][72];
    __shared__ __half Qt[64][72];
    __shared__ __half Kt[64][72];
    int bc = blockIdx.x;
    const __half* Q = g_qh + (size_t)bc * 4096;
    const __half* K = g_kh + (size_t)bc * 4096;
    int tid = threadIdx.x, lane = tid & 31, wid = tid >> 5;
    int warpM = wid >> 1, warpN = wid & 1;
    int g = lane >> 2, tig = lane & 3;

    #pragma unroll
    for (int l = 0; l < 2; l++) {
        int idx = tid + (l << 8);          // 0..511
        int h = idx >> 3, wq = (idx & 7) << 3;
        uint4 qv = *(const uint4*)&Q[(h << 6) + wq];
        uint4 kv = *(const uint4*)&K[(h << 6) + wq];
        *(uint4*)&Qs[h][wq] = qv;
        *(uint4*)&Ks[h][wq] = kv;
        const __half* qp = (const __half*)&qv;
        const __half* kp = (const __half*)&kv;
        #pragma unroll
        for (int j = 0; j < 8; j++) {
            Qt[wq + j][h] = qp[j];
            Kt[wq + j][h] = kp[j];
        }
    }
    __syncthreads();

    {   // Phase 1: S1[h][gg] = sum_w Q[h][w] K[gg][w]
        float acc[4][4] = {};
        #pragma unroll
        for (int ks = 0; ks < 4; ks++) {
            int kh = ks << 4;
            unsigned a[4], b[4][2];
            int row = (warpM << 4) + g;
            a[0] = *(const unsigned*)&Qs[row][kh + (tig << 1)];
            a[1] = *(const unsigned*)&Qs[row + 8][kh + (tig << 1)];
            a[2] = *(const unsigned*)&Qs[row][kh + 8 + (tig << 1)];
            a[3] = *(const unsigned*)&Qs[row + 8][kh + 8 + (tig << 1)];
            #pragma unroll
            for (int nt = 0; nt < 4; nt++) {
                int col = (warpN << 5) + (nt << 3) + g;
                b[nt][0] = *(const unsigned*)&Ks[col][kh + (tig << 1)];
                b[nt][1] = *(const unsigned*)&Ks[col][kh + 8 + (tig << 1)];
            }
            #pragma unroll
            for (int nt = 0; nt < 4; nt++) mma_f16(acc[nt], a, b[nt]);
        }
        float* out = g_as + (size_t)bc * 4096;
        #pragma unroll
        for (int nt = 0; nt < 4; nt++) {
            int row = (warpM << 4) + g;
            int col = (warpN << 5) + (nt << 3) + (tig << 1);
            *(float2*)&out[row * 64 + col]       = make_float2(acc[nt][0], acc[nt][1]);
            *(float2*)&out[(row + 8) * 64 + col] = make_float2(acc[nt][2], acc[nt][3]);
        }
    }
    {   // Phase 2: S2[w][v] = sum_h Q[h][w] K[h][v]
        float acc[4][4] = {};
        #pragma unroll
        for (int ks = 0; ks < 4; ks++) {
            int kh = ks << 4;
            unsigned a[4], b[4][2];
            int row = (warpM << 4) + g;
            a[0] = *(const unsigned*)&Qt[row][kh + (tig << 1)];
            a[1] = *(const unsigned*)&Qt[row + 8][kh + (tig << 1)];
            a[2] = *(const unsigned*)&Qt[row][kh + 8 + (tig << 1)];
            a[3] = *(const unsigned*)&Qt[row + 8][kh + 8 + (tig << 1)];
            #pragma unroll
            for (int nt = 0; nt < 4; nt++) {
                int col = (warpN << 5) + (nt << 3) + g;
                b[nt][0] = *(const unsigned*)&Kt[col][kh + (tig << 1)];
                b[nt][1] = *(const unsigned*)&Kt[col][kh + 8 + (tig << 1)];
            }
            #pragma unroll
            for (int nt = 0; nt < 4; nt++) mma_f16(acc[nt], a, b[nt]);
        }
        float* out = g_ac + (size_t)bc * 4096;
        #pragma unroll
        for (int nt = 0; nt < 4; nt++) {
            int row = (warpM << 4) + g;
            int col = (warpN << 5) + (nt << 3) + (tig << 1);
            *(float2*)&out[row * 64 + col]       = make_float2(acc[nt][0], acc[nt][1]);
            *(float2*)&out[(row + 8) * 64 + col] = make_float2(acc[nt][2], acc[nt][3]);
        }
    }
}

// ---------------------------------------------------------------------------
// K3: transpose-softmax over channel axis; which=1 also emits pool partials.
// Reads [B,C,HW] fp32 logits, writes channels-last fp16 [B,HW,C].
// ---------------------------------------------------------------------------
__global__ __launch_bounds__(256) void k_softmax_t(void)
{
    __shared__ float tile[256][33];
    __shared__ float red[8][32];
    __shared__ float Mv[32], Iv[32];
    int which = blockIdx.y;
    const float* src = which ? g_ac : g_as;
    __half* dst = which ? g_ach : g_ash;
    int blk = blockIdx.x;
    int b = blk >> 7;
    int pos0 = (blk & 127) << 5;
    int tid = threadIdx.x, lane = tid & 31, wid = tid >> 5;

    const float* sb = src + (size_t)(b << 8) * 4096 + pos0;
    #pragma unroll 8
    for (int it = 0; it < 32; it++) {
        int c = (it << 3) + wid;
        tile[c][lane] = sb[(size_t)c * 4096 + lane];
    }
    __syncthreads();

    int pos = lane, cq = wid;
    int c0 = cq << 5;
    float m = -3.0e38f;
    #pragma unroll
    for (int j = 0; j < 32; j++) m = fmaxf(m, tile[c0 + j][pos]);
    red[cq][pos] = m;
    __syncthreads();
    if (tid < 32) {
        float M = -3.0e38f;
        #pragma unroll
        for (int j = 0; j < 8; j++) M = fmaxf(M, red[j][tid]);
        Mv[tid] = M;
    }
    __syncthreads();
    float M = Mv[pos];
    float s = 0.f;
    #pragma unroll
    for (int j = 0; j < 32; j++) {
        float e = __expf(tile[c0 + j][pos] - M);
        tile[c0 + j][pos] = e;
        s += e;
    }
    red[cq][pos] = s;
    __syncthreads();
    if (tid < 32) {
        float S = 0.f;
        #pragma unroll
        for (int j = 0; j < 8; j++) S += red[j][tid];
        Iv[tid] = 1.0f / S;
    }
    __syncthreads();
    float inv = Iv[pos];

    size_t rowo = ((size_t)((b << 12) + pos0 + pos)) << 8;
    #pragma unroll
    for (int q = 0; q < 4; q++) {
        int cb = c0 + (q << 3);
        uint4 u;
        u.x = packh2(tile[cb + 0][pos] * inv, tile[cb + 1][pos] * inv);
        u.y = packh2(tile[cb + 2][pos] * inv, tile[cb + 3][pos] * inv);
        u.z = packh2(tile[cb + 4][pos] * inv, tile[cb + 5][pos] * inv);
        u.w = packh2(tile[cb + 6][pos] * inv, tile[cb + 7][pos] * inv);
        *(uint4*)&dst[rowo + cb] = u;
    }

    if (which) {   // pool partial: sum over this block's 32 positions per channel
        int c = tid;
        float sp = 0.f;
        #pragma unroll 8
        for (int j = 0; j < 32; j++) sp += tile[c][j] * Iv[j];
        g_poolp[(size_t)((b << 7) + (blk & 127)) * 256 + c] = sp;
    }
}

// ---------------------------------------------------------------------------
// K4: conv3x3 s2 p1 + relu, channels-last. BM=128, BN=128, K=2304.
// ---------------------------------------------------------------------------
__global__ __launch_bounds__(256) void k_conv(void)
{
    __shared__ unsigned As[128][20];
    __shared__ unsigned Bs[128][20];
    int m0 = blockIdx.x << 7;
    int n0 = blockIdx.y << 7;
    int tid = threadIdx.x, lane = tid & 31, wid = tid >> 5;
    int warpM = wid >> 1, warpN = wid & 1;
    int g = lane >> 2, tig = lane & 3;
    int b = m0 >> 10;
    float acc[2][8][4] = {};
    uint4 ra[2], rb[2];

    auto gload = [&](int k0) {
        int tap = k0 >> 8;
        int ky = tap / 3, kx = tap - ky * 3;
        int cib = (k0 & 255) + ((tid & 3) << 3);
        #pragma unroll
        for (int l = 0; l < 2; l++) {
            int idx = tid + (l << 8);
            int mrow = idx >> 2;
            int r = (m0 + mrow) & 1023;
            int oy = r >> 5, ox = r & 31;
            int iy = 2 * oy - 1 + ky, ix = 2 * ox - 1 + kx;
            if ((unsigned)iy < 64u && (unsigned)ix < 64u)
                ra[l] = *(const uint4*)&g_ash[(((size_t)(b << 12) + (iy << 6) + ix) << 8) + cib];
            else
                ra[l] = make_uint4(0u, 0u, 0u, 0u);
            rb[l] = *(const uint4*)&g_wch[(size_t)(n0 + mrow) * 2304 + k0 + ((idx & 3) << 3)];
        }
    };
    auto sstore = [&]() {
        #pragma unroll
        for (int l = 0; l < 2; l++) {
            int idx = tid + (l << 8);
            *(uint4*)&As[idx >> 2][(idx & 3) << 2] = ra[l];
            *(uint4*)&Bs[idx >> 2][(idx & 3) << 2] = rb[l];
        }
    };

    gload(0); sstore(); __syncthreads();
    for (int k0 = 0; k0 < 2304; k0 += 32) {
        bool more = (k0 + 32) < 2304;
        if (more) gload(k0 + 32);
        #pragma unroll
        for (int ks = 0; ks < 2; ks++) {
            int kb = ks << 3;
            unsigned a[2][4], bf[8][2];
            #pragma unroll
            for (int mt = 0; mt < 2; mt++) {
                int row = (warpM << 5) + (mt << 4) + g;
                a[mt][0] = As[row][kb + tig];     a[mt][1] = As[row + 8][kb + tig];
                a[mt][2] = As[row][kb + 4 + tig]; a[mt][3] = As[row + 8][kb + 4 + tig];
            }
            #pragma unroll
            for (int nt = 0; nt < 8; nt++) {
                int col = (warpN << 6) + (nt << 3) + g;
                bf[nt][0] = Bs[col][kb + tig]; bf[nt][1] = Bs[col][kb + 4 + tig];
            }
            #pragma unroll
            for (int mt = 0; mt < 2; mt++)
                #pragma unroll
                for (int nt = 0; nt < 8; nt++)
                    mma_f16(acc[mt][nt], a[mt], bf[nt]);
        }
        __syncthreads();
        if (more) { sstore(); __syncthreads(); }
    }

    #pragma unroll
    for (int mt = 0; mt < 2; mt++)
        #pragma unroll
        for (int nt = 0; nt < 8; nt++) {
            int row = (warpM << 5) + (mt << 4) + g;
            int col = n0 + (warpN << 6) + (nt << 3) + (tig << 1);
            float* c = acc[mt][nt];
            int r1 = (m0 + row) & 1023;
            *(__half2*)&g_c1h[(((size_t)(b << 10) + r1) << 8) + col] =
                __floats2half2_rn(fmaxf(c[0], 0.f), fmaxf(c[1], 0.f));
            int r2 = (m0 + row + 8) & 1023;
            *(__half2*)&g_c1h[(((size_t)(b << 10) + r2) << 8) + col] =
                __floats2half2_rn(fmaxf(c[2], 0.f), fmaxf(c[3], 0.f));
        }
}

// ---------------------------------------------------------------------------
// K6: convT 4x4 s2 p1 + relu by parity class, channels-last.
// BM=128, BN=128, K=1024 per class.
// ---------------------------------------------------------------------------
__global__ __launch_bounds__(256) void k_convt(void)
{
    __shared__ unsigned As[128][20];
    __shared__ unsigned Bs[128][20];
    int cl = blockIdx.z;
    int py = cl >> 1, px = cl & 1;
    int m0 = blockIdx.x << 7;
    int n0 = blockIdx.y << 7;
    int tid = threadIdx.x, lane = tid & 31, wid = tid >> 5;
    int warpM = wid >> 1, warpN = wid & 1;
    int g = lane >> 2, tig = lane & 3;
    int b = m0 >> 10;
    float acc[2][8][4] = {};
    uint4 ra[2], rb[2];

    auto gload = [&](int k0) {
        int t = k0 >> 8;
        int tyk = t >> 1, txk = t & 1;
        int cib = (k0 & 255) + ((tid & 3) << 3);
        #pragma unroll
        for (int l = 0; l < 2; l++) {
            int idx = tid + (l << 8);
            int mrow = idx >> 2;
            int r = (m0 + mrow) & 1023;
            int ys = r >> 5, xs = r & 31;
            int ii = ys + py - tyk, jj = xs + px - txk;
            if ((unsigned)ii < 32u && (unsigned)jj < 32u)
                ra[l] = *(const uint4*)&g_c1h[(((size_t)(b << 10) + (ii << 5) + jj) << 8) + cib];
            else
                ra[l] = make_uint4(0u, 0u, 0u, 0u);
            rb[l] = *(const uint4*)&g_wt2[(((size_t)((cl << 8) + n0 + mrow)) << 10) + k0 + ((idx & 3) << 3)];
        }
    };
    auto sstore = [&]() {
        #pragma unroll
        for (int l = 0; l < 2; l++) {
            int idx = tid + (l << 8);
            *(uint4*)&As[idx >> 2][(idx & 3) << 2] = ra[l];
            *(uint4*)&Bs[idx >> 2][(idx & 3) << 2] = rb[l];
        }
    };

    gload(0); sstore(); __syncthreads();
    for (int k0 = 0; k0 < 1024; k0 += 32) {
        bool more = (k0 + 32) < 1024;
        if (more) gload(k0 + 32);
        #pragma unroll
        for (int ks = 0; ks < 2; ks++) {
            int kb = ks << 3;
            unsigned a[2][4], bf[8][2];
            #pragma unroll
            for (int mt = 0; mt < 2; mt++) {
                int row = (warpM << 5) + (mt << 4) + g;
                a[mt][0] = As[row][kb + tig];     a[mt][1] = As[row + 8][kb + tig];
                a[mt][2] = As[row][kb + 4 + tig]; a[mt][3] = As[row + 8][kb + 4 + tig];
            }
            #pragma unroll
            for (int nt = 0; nt < 8; nt++) {
                int col = (warpN << 6) + (nt << 3) + g;
                bf[nt][0] = Bs[col][kb + tig]; bf[nt][1] = Bs[col][kb + 4 + tig];
            }
            #pragma unroll
            for (int mt = 0; mt < 2; mt++)
                #pragma unroll
                for (int nt = 0; nt < 8; nt++)
                    mma_f16(acc[mt][nt], a[mt], bf[nt]);
        }
        __syncthreads();
        if (more) { sstore(); __syncthreads(); }
    }

    #pragma unroll
    for (int mt = 0; mt < 2; mt++)
        #pragma unroll
        for (int nt = 0; nt < 8; nt++) {
            int row = (warpM << 5) + (mt << 4) + g;
            int col = n0 + (warpN << 6) + (nt << 3) + (tig << 1);
            float* c = acc[mt][nt];
            int mm1 = m0 + row;
            int ys1 = (mm1 >> 5) & 31, xs1 = mm1 & 31;
            size_t o1 = (((size_t)(b << 12) + (((ys1 << 1) + py) << 6) + (xs1 << 1) + px) << 8) + col;
            *(__half2*)&g_sbh[o1] = __floats2half2_rn(fmaxf(c[0], 0.f), fmaxf(c[1], 0.f));
            int mm2 = mm1 + 8;
            int ys2 = (mm2 >> 5) & 31, xs2 = mm2 & 31;
            size_t o2 = (((size_t)(b << 12) + (((ys2 << 1) + py) << 6) + (xs2 << 1) + px) << 8) + col;
            *(__half2*)&g_sbh[o2] = __floats2half2_rn(fmaxf(c[2], 0.f), fmaxf(c[3], 0.f));
        }
}

// ---------------------------------------------------------------------------
// K8: SE MLP (combines 128 pool partials per b)
// ---------------------------------------------------------------------------
__global__ __launch_bounds__(256) void k_se(const float* __restrict__ Wc1,
                                            const float* __restrict__ Wc2)
{
    int b = blockIdx.x;
    __shared__ float pool[256];
    __shared__ float hid[64];
    int t = threadIdx.x;
    float s = 0.f;
    #pragma unroll 16
    for (int j = 0; j < 128; j++) s += g_poolp[(size_t)((b << 7) + j) * 256 + t];
    pool[t] = s * (1.0f / 4096.0f);
    __syncthreads();
    if (t < 64) {
        float h = 0.f;
        for (int c = 0; c < 256; c++) h += pool[c] * Wc1[t * 256 + c];
        hid[t] = fmaxf(h, 0.f);
    }
    __syncthreads();
    float v = 0.f;
    #pragma unroll
    for (int j = 0; j < 64; j++) v += hid[j] * Wc2[t * 64 + j];
    g_gate[(b << 8) + t] = 1.0f / (1.0f + __expf(-v));
}

// ---------------------------------------------------------------------------
// K9: fused residual + LayerNorm. All inputs channels-last; warp per position.
// ---------------------------------------------------------------------------
__global__ __launch_bounds__(256) void k_fuse(const float* __restrict__ x,
                                              const float* __restrict__ gamma,
                                              const float* __restrict__ beta,
                                              float* __restrict__ out)
{
    int wid = threadIdx.x >> 5, lane = threadIdx.x & 31;
    int pos = (blockIdx.x << 3) + wid;
    int b = pos >> 12;
    size_t row = (size_t)pos << 8;
    int c0 = lane << 3;

    float4 x0 = *(const float4*)&x[row + c0];
    float4 x1 = *(const float4*)&x[row + c0 + 4];
    float vs[8], vc[8], sb[8], ac[8];
    unp8(*(const uint4*)&g_vsh[row + c0], vs);
    unp8(*(const uint4*)&g_vch[row + c0], vc);
    unp8(*(const uint4*)&g_sbh[row + c0], sb);
    unp8(*(const uint4*)&g_ach[row + c0], ac);
    float4 g0 = *(const float4*)&g_gate[(b << 8) + c0];
    float4 g1 = *(const float4*)&g_gate[(b << 8) + c0 + 4];
    float xs[8] = {x0.x, x0.y, x0.z, x0.w, x1.x, x1.y, x1.z, x1.w};
    float gt[8] = {g0.x, g0.y, g0.z, g0.w, g1.x, g1.y, g1.z, g1.w};

    float y[8];
    float s1 = 0.f, s2 = 0.f;
    #pragma unroll
    for (int j = 0; j < 8; j++) {
        y[j] = xs[j] + sb[j] * vs[j] + gt[j] * ac[j] * vc[j];
        s1 += y[j]; s2 += y[j] * y[j];
    }
    #pragma unroll
    for (int o = 16; o > 0; o >>= 1) {
        s1 += __shfl_xor_sync(0xffffffffu, s1, o);
        s2 += __shfl_xor_sync(0xffffffffu, s2, o);
    }
    float mu = s1 * (1.0f / 256.0f);
    float var = s2 * (1.0f / 256.0f) - mu * mu;
    float ri = rsqrtf(var + 1e-5f);

    float4 gm0 = *(const float4*)&gamma[c0];
    float4 gm1 = *(const float4*)&gamma[c0 + 4];
    float4 bt0 = *(const float4*)&beta[c0];
    float4 bt1 = *(const float4*)&beta[c0 + 4];
    float gm[8] = {gm0.x, gm0.y, gm0.z, gm0.w, gm1.x, gm1.y, gm1.z, gm1.w};
    float bt[8] = {bt0.x, bt0.y, bt0.z, bt0.w, bt1.x, bt1.y, bt1.z, bt1.w};
    float4 o0, o1;
    o0.x = (y[0] - mu) * ri * gm[0] + bt[0];
    o0.y = (y[1] - mu) * ri * gm[1] + bt[1];
    o0.z = (y[2] - mu) * ri * gm[2] + bt[2];
    o0.w = (y[3] - mu) * ri * gm[3] + bt[3];
    o1.x = (y[4] - mu) * ri * gm[4] + bt[4];
    o1.y = (y[5] - mu) * ri * gm[5] + bt[5];
    o1.z = (y[6] - mu) * ri * gm[6] + bt[6];
    o1.w = (y[7] - mu) * ri * gm[7] + bt[7];
    *(float4*)&out[row + c0]     = o0;
    *(float4*)&out[row + c0 + 4] = o1;
}

// ---------------------------------------------------------------------------
extern "C" void kernel_launch(void* const* d_in, const int* in_sizes, int n_in,
                              void* d_out, int out_size)
{
    const float* x      = (const float*)d_in[0];
    const float* Wq     = (const float*)d_in[1];
    const float* Wk     = (const float*)d_in[2];
    const float* Wvc    = (const float*)d_in[3];
    const float* Wvs    = (const float*)d_in[4];
    const float* Wc1    = (const float*)d_in[5];
    const float* Wc2    = (const float*)d_in[6];
    const float* Wconv  = (const float*)d_in[7];
    const float* Wconvt = (const float*)d_in[8];
    const float* gamma  = (const float*)d_in[9];
    const float* beta   = (const float*)d_in[10];
    float* out = (float*)d_out;

    k_packc<<<256, 256>>>(Wconv);
    k_packt<<<1024, 256>>>(Wconvt);
    k_proj <<<dim3(512, 8), 256>>>(x, Wq, Wk, Wvc, Wvs);
    k_attn <<<4096, 256>>>();
    k_softmax_t<<<dim3(2048, 2), 256>>>();
    k_conv <<<dim3(128, 2), 256>>>();
    k_convt<<<dim3(128, 2, 4), 256>>>();
    k_se   <<<16, 256>>>(Wc1, Wc2);
    k_fuse <<<8192, 256>>>(x, gamma, beta, out);
}

// round 14
// speedup vs baseline: 5.0731x; 1.0521x over previous
#include <cuda_runtime.h>
#include <cuda_fp16.h>
#include <math.h>

// ---------------------------------------------------------------------------
// EPA_Layer: B=16, H=W=64, C=256, HID=64
// Round 14 (= Round 12 ldmatrix kernel, third submission after broker flakes):
//   k_attn via ldmatrix/.trans on a single natural smem image (kills the
//   16-way STS conflicts of the dual-image build). Rest = Round 11 pipeline
//   (channels-last fp16, BN=128 tiles, pool fused into softmax).
// ---------------------------------------------------------------------------

#define NB   16
#define NC   256
#define NHW  4096
#define NM   65536

__device__ __half g_qh [NB * NC * NHW];   // q fp16 [B,C,H,W]
__device__ __half g_kh [NB * NC * NHW];   // k fp16 [B,C,H,W]
__device__ __half g_vch[NM * NC];         // vc fp16 [B,H,W,C]
__device__ __half g_vsh[NM * NC];         // vs fp16 [B,H,W,C]
__device__ float  g_as [NB * NC * NHW];   // attn_s logits fp32 [B,C,64,64]
__device__ float  g_ac [NB * NC * NHW];   // attn_c logits fp32 [B,C,64,64]
__device__ __half g_ash[NB * NHW * NC];   // softmax(attn_s) fp16 [B,64,64,C]
__device__ __half g_ach[NB * NHW * NC];   // softmax(attn_c) fp16 [B,64,64,C]
__device__ __half g_c1h[NB * 1024 * NC];  // conv out fp16 [B,32,32,C]
__device__ __half g_sbh[NB * NHW * NC];   // convT out fp16 [B,64,64,C]
__device__ __half g_wch[NC * 2304];       // conv weights [co][tap*256+ci]
__device__ __half g_wt2[4 * NC * 1024];   // convT weights [cl][co][t*256+ci]
__device__ float  g_poolp[NB * 128 * NC]; // pool partials (per softmax block)
__device__ float  g_gate[NB * NC];

__device__ __forceinline__ unsigned packh2(float a, float b) {
    __half2 h = __floats2half2_rn(a, b);
    return *(unsigned*)&h;
}
__device__ __forceinline__ void mma_f16(float* c, const unsigned* a, const unsigned* b) {
    asm volatile(
        "mma.sync.aligned.m16n8k16.row.col.f32.f16.f16.f32 "
        "{%0,%1,%2,%3}, {%4,%5,%6,%7}, {%8,%9}, {%0,%1,%2,%3};"
        : "+f"(c[0]), "+f"(c[1]), "+f"(c[2]), "+f"(c[3])
        : "r"(a[0]), "r"(a[1]), "r"(a[2]), "r"(a[3]), "r"(b[0]), "r"(b[1]));
}
__device__ __forceinline__ void unp8(uint4 u, float* f) {
    const __half2* h = (const __half2*)&u;
    #pragma unroll
    for (int q = 0; q < 4; q++) {
        float2 t = __half22float2(h[q]);
        f[2 * q] = t.x; f[2 * q + 1] = t.y;
    }
}
__device__ __forceinline__ unsigned sptr(const void* p) {
    return (unsigned)__cvta_generic_to_shared(p);
}
__device__ __forceinline__ void ldsm_x4(unsigned& r0, unsigned& r1,
                                        unsigned& r2, unsigned& r3, unsigned addr) {
    asm volatile("ldmatrix.sync.aligned.m8n8.x4.shared.b16 {%0,%1,%2,%3}, [%4];"
        : "=r"(r0), "=r"(r1), "=r"(r2), "=r"(r3) : "r"(addr));
}
__device__ __forceinline__ void ldsm_x4t(unsigned& r0, unsigned& r1,
                                         unsigned& r2, unsigned& r3, unsigned addr) {
    asm volatile("ldmatrix.sync.aligned.m8n8.x4.trans.shared.b16 {%0,%1,%2,%3}, [%4];"
        : "=r"(r0), "=r"(r1), "=r"(r2), "=r"(r3) : "r"(addr));
}

// ---------------------------------------------------------------------------
// Weight repacks
// ---------------------------------------------------------------------------
__global__ void k_packc(const float* __restrict__ Wconv)
{
    int co = blockIdx.x, ci = threadIdx.x;
    #pragma unroll
    for (int tap = 0; tap < 9; tap++)
        g_wch[co * 2304 + tap * 256 + ci] =
            __float2half(Wconv[co * 2304 + ci * 9 + tap]);
}
__global__ void k_packt(const float* __restrict__ Wconvt)
{
    int cl = blockIdx.x >> 8, co = blockIdx.x & 255, ci = threadIdx.x;
    int py = cl >> 1, px = cl & 1;
    #pragma unroll
    for (int t = 0; t < 4; t++) {
        int tyk = t >> 1, txk = t & 1;
        int ky = 1 - py + 2 * tyk, kx = 1 - px + 2 * txk;
        g_wt2[(size_t)((cl << 8) + co) * 1024 + (t << 8) + ci] =
            __float2half(Wconvt[(size_t)ci * 4096 + co * 16 + (ky << 2) + kx]);
    }
}

// ---------------------------------------------------------------------------
// K1: unified 4-way projection (fp16 mma). BM=128, BN=128, BK=32.
// ---------------------------------------------------------------------------
__global__ __launch_bounds__(256) void k_proj(
    const float* __restrict__ x,
    const float* __restrict__ Wq, const float* __restrict__ Wk,
    const float* __restrict__ Wvc, const float* __restrict__ Wvs)
{
    __shared__ unsigned As[128][20];
    __shared__ unsigned Bs[128][20];
    int m0 = blockIdx.x << 7;
    int nb = blockIdx.y;
    int which = nb >> 1;
    int d0 = (nb & 1) << 7;
    const float* W = (which == 0) ? Wq : (which == 1) ? Wk : (which == 2) ? Wvc : Wvs;
    int tid = threadIdx.x, lane = tid & 31, wid = tid >> 5;
    int warpM = wid >> 1, warpN = wid & 1;
    int g = lane >> 2, tig = lane & 3;
    float acc[2][8][4] = {};
    float4 ra[4], rb[4];

    auto gload = [&](int k0) {
        #pragma unroll
        for (int l = 0; l < 4; l++) {
            int idx = tid + (l << 8);
            ra[l] = *(const float4*)&x[(size_t)(m0 + (idx >> 3)) * 256 + k0 + ((idx & 7) << 2)];
            rb[l] = *(const float4*)&W[(size_t)(d0 + (idx >> 3)) * 256 + k0 + ((idx & 7) << 2)];
        }
    };
    auto sstore = [&]() {
        #pragma unroll
        for (int l = 0; l < 4; l++) {
            int idx = tid + (l << 8);
            *(uint2*)&As[idx >> 3][(idx & 7) << 1] =
                make_uint2(packh2(ra[l].x, ra[l].y), packh2(ra[l].z, ra[l].w));
            *(uint2*)&Bs[idx >> 3][(idx & 7) << 1] =
                make_uint2(packh2(rb[l].x, rb[l].y), packh2(rb[l].z, rb[l].w));
        }
    };

    gload(0); sstore(); __syncthreads();
    for (int k0 = 0; k0 < 256; k0 += 32) {
        bool more = (k0 + 32) < 256;
        if (more) gload(k0 + 32);
        #pragma unroll
        for (int ks = 0; ks < 2; ks++) {
            int kb = ks << 3;
            unsigned a[2][4], bf[8][2];
            #pragma unroll
            for (int mt = 0; mt < 2; mt++) {
                int row = (warpM << 5) + (mt << 4) + g;
                a[mt][0] = As[row][kb + tig];     a[mt][1] = As[row + 8][kb + tig];
                a[mt][2] = As[row][kb + 4 + tig]; a[mt][3] = As[row + 8][kb + 4 + tig];
            }
            #pragma unroll
            for (int nt = 0; nt < 8; nt++) {
                int col = (warpN << 6) + (nt << 3) + g;
                bf[nt][0] = Bs[col][kb + tig]; bf[nt][1] = Bs[col][kb + 4 + tig];
            }
            #pragma unroll
            for (int mt = 0; mt < 2; mt++)
                #pragma unroll
                for (int nt = 0; nt < 8; nt++)
                    mma_f16(acc[mt][nt], a[mt], bf[nt]);
        }
        __syncthreads();
        if (more) { sstore(); __syncthreads(); }
    }

    if (which < 2) {
        __half* dst = which ? g_kh : g_qh;
        int b = m0 >> 12;
        int hw0 = m0 & 4095;
        #pragma unroll
        for (int mt = 0; mt < 2; mt++)
            #pragma unroll
            for (int nt = 0; nt < 8; nt++) {
                int row = (warpM << 5) + (mt << 4) + g;
                int col = d0 + (warpN << 6) + (nt << 3) + (tig << 1);
                float* c = acc[mt][nt];
                size_t bi = (size_t)((b << 8) + col) * 4096 + hw0;
                dst[bi + row]            = __float2half(c[0]);
                dst[bi + 4096 + row]     = __float2half(c[1]);
                dst[bi + row + 8]        = __float2half(c[2]);
                dst[bi + 4096 + row + 8] = __float2half(c[3]);
            }
    } else {
        __half* dst = (which == 2) ? g_vch : g_vsh;
        #pragma unroll
        for (int mt = 0; mt < 2; mt++)
            #pragma unroll
            for (int nt = 0; nt < 8; nt++) {
                int row = (warpM << 5) + (mt << 4) + g;
                int col = d0 + (warpN << 6) + (nt << 3) + (tig << 1);
                float* c = acc[mt][nt];
                *(__half2*)&dst[(size_t)(m0 + row) * 256 + col] =
                    __floats2half2_rn(c[0], c[1]);
                *(__half2*)&dst[(size_t)(m0 + row + 8) * 256 + col] =
                    __floats2half2_rn(c[2], c[3]);
            }
    }
}

// ---------------------------------------------------------------------------
// K2: per-(b,c) attention logits (fp16 mma via ldmatrix).
// Single natural smem image [h][w]; phase 1 uses plain ldmatrix,
// phase 2 (Q^T K) uses ldmatrix.trans on the SAME image.
// ---------------------------------------------------------------------------
__global__ __launch_bounds__(256) void k_attn(void)
{
    __shared__ alignas(16) __half Qs[64][72];
    __shared__ alignas(16) __half Ks[64][72];
    int bc = blockIdx.x;
    const __half* Q = g_qh + (size_t)bc * 4096;
    const __half* K = g_kh + (size_t)bc * 4096;
    int tid = threadIdx.x, lane = tid & 31, wid = tid >> 5;
    int warpM = wid >> 1, warpN = wid & 1;
    int g = lane >> 2, tig = lane & 3;
    int sub = lane >> 3, r = lane & 7;
    int rowA = warpM << 4;          // 16-row A tile base
    int colB = warpN << 5;          // 32-col B tile base

    #pragma unroll
    for (int l = 0; l < 2; l++) {
        int idx = tid + (l << 8);          // 0..511 rows-of-8
        int h = idx >> 3, wq = (idx & 7) << 3;
        *(uint4*)&Qs[h][wq] = *(const uint4*)&Q[(h << 6) + wq];
        *(uint4*)&Ks[h][wq] = *(const uint4*)&K[(h << 6) + wq];
    }
    __syncthreads();

    {   // Phase 1: S1[h][gg] = sum_w Q[h][w] K[gg][w]
        float acc[4][4] = {};
        #pragma unroll
        for (int ks = 0; ks < 4; ks++) {
            int kh = ks << 4;
            unsigned a[4], bf[4][2];
            ldsm_x4(a[0], a[1], a[2], a[3],
                sptr(&Qs[rowA + ((sub & 1) << 3) + r][kh + ((sub >> 1) << 3)]));
            #pragma unroll
            for (int np = 0; np < 2; np++) {
                unsigned b0, b1, b2, b3;
                ldsm_x4(b0, b1, b2, b3,
                    sptr(&Ks[colB + (np << 4) + ((sub >> 1) << 3) + r][kh + ((sub & 1) << 3)]));
                bf[2 * np][0] = b0; bf[2 * np][1] = b1;
                bf[2 * np + 1][0] = b2; bf[2 * np + 1][1] = b3;
            }
            #pragma unroll
            for (int nt = 0; nt < 4; nt++) mma_f16(acc[nt], a, bf[nt]);
        }
        float* out = g_as + (size_t)bc * 4096;
        #pragma unroll
        for (int nt = 0; nt < 4; nt++) {
            int row = rowA + g;
            int col = colB + (nt << 3) + (tig << 1);
            *(float2*)&out[row * 64 + col]       = make_float2(acc[nt][0], acc[nt][1]);
            *(float2*)&out[(row + 8) * 64 + col] = make_float2(acc[nt][2], acc[nt][3]);
        }
    }
    {   // Phase 2: S2[w][v] = sum_h Q[h][w] K[h][v]  (trans reads of same image)
        float acc[4][4] = {};
        #pragma unroll
        for (int ks = 0; ks < 4; ks++) {
            int kh = ks << 4;
            unsigned a[4], bf[4][2];
            ldsm_x4t(a[0], a[1], a[2], a[3],
                sptr(&Qs[kh + ((sub >> 1) << 3) + r][rowA + ((sub & 1) << 3)]));
            #pragma unroll
            for (int np = 0; np < 2; np++) {
                unsigned b0, b1, b2, b3;
                ldsm_x4t(b0, b1, b2, b3,
                    sptr(&Ks[kh + ((sub & 1) << 3) + r][colB + (np << 4) + ((sub >> 1) << 3)]));
                bf[2 * np][0] = b0; bf[2 * np][1] = b1;
                bf[2 * np + 1][0] = b2; bf[2 * np + 1][1] = b3;
            }
            #pragma unroll
            for (int nt = 0; nt < 4; nt++) mma_f16(acc[nt], a, bf[nt]);
        }
        float* out = g_ac + (size_t)bc * 4096;
        #pragma unroll
        for (int nt = 0; nt < 4; nt++) {
            int row = rowA + g;
            int col = colB + (nt << 3) + (tig << 1);
            *(float2*)&out[row * 64 + col]       = make_float2(acc[nt][0], acc[nt][1]);
            *(float2*)&out[(row + 8) * 64 + col] = make_float2(acc[nt][2], acc[nt][3]);
        }
    }
}

// ---------------------------------------------------------------------------
// K3: transpose-softmax over channel axis; which=1 also emits pool partials.
// ---------------------------------------------------------------------------
__global__ __launch_bounds__(256) void k_softmax_t(void)
{
    __shared__ float tile[256][33];
    __shared__ float red[8][32];
    __shared__ float Mv[32], Iv[32];
    int which = blockIdx.y;
    const float* src = which ? g_ac : g_as;
    __half* dst = which ? g_ach : g_ash;
    int blk = blockIdx.x;
    int b = blk >> 7;
    int pos0 = (blk & 127) << 5;
    int tid = threadIdx.x, lane = tid & 31, wid = tid >> 5;

    const float* sb = src + (size_t)(b << 8) * 4096 + pos0;
    #pragma unroll 8
    for (int it = 0; it < 32; it++) {
        int c = (it << 3) + wid;
        tile[c][lane] = sb[(size_t)c * 4096 + lane];
    }
    __syncthreads();

    int pos = lane, cq = wid;
    int c0 = cq << 5;
    float m = -3.0e38f;
    #pragma unroll
    for (int j = 0; j < 32; j++) m = fmaxf(m, tile[c0 + j][pos]);
    red[cq][pos] = m;
    __syncthreads();
    if (tid < 32) {
        float M = -3.0e38f;
        #pragma unroll
        for (int j = 0; j < 8; j++) M = fmaxf(M, red[j][tid]);
        Mv[tid] = M;
    }
    __syncthreads();
    float M = Mv[pos];
    float s = 0.f;
    #pragma unroll
    for (int j = 0; j < 32; j++) {
        float e = __expf(tile[c0 + j][pos] - M);
        tile[c0 + j][pos] = e;
        s += e;
    }
    red[cq][pos] = s;
    __syncthreads();
    if (tid < 32) {
        float S = 0.f;
        #pragma unroll
        for (int j = 0; j < 8; j++) S += red[j][tid];
        Iv[tid] = 1.0f / S;
    }
    __syncthreads();
    float inv = Iv[pos];

    size_t rowo = ((size_t)((b << 12) + pos0 + pos)) << 8;
    #pragma unroll
    for (int q = 0; q < 4; q++) {
        int cb = c0 + (q << 3);
        uint4 u;
        u.x = packh2(tile[cb + 0][pos] * inv, tile[cb + 1][pos] * inv);
        u.y = packh2(tile[cb + 2][pos] * inv, tile[cb + 3][pos] * inv);
        u.z = packh2(tile[cb + 4][pos] * inv, tile[cb + 5][pos] * inv);
        u.w = packh2(tile[cb + 6][pos] * inv, tile[cb + 7][pos] * inv);
        *(uint4*)&dst[rowo + cb] = u;
    }

    if (which) {
        int c = tid;
        float sp = 0.f;
        #pragma unroll 8
        for (int j = 0; j < 32; j++) sp += tile[c][j] * Iv[j];
        g_poolp[(size_t)((b << 7) + (blk & 127)) * 256 + c] = sp;
    }
}

// ---------------------------------------------------------------------------
// K4: conv3x3 s2 p1 + relu, channels-last. BM=128, BN=128, K=2304.
// ---------------------------------------------------------------------------
__global__ __launch_bounds__(256) void k_conv(void)
{
    __shared__ unsigned As[128][20];
    __shared__ unsigned Bs[128][20];
    int m0 = blockIdx.x << 7;
    int n0 = blockIdx.y << 7;
    int tid = threadIdx.x, lane = tid & 31, wid = tid >> 5;
    int warpM = wid >> 1, warpN = wid & 1;
    int g = lane >> 2, tig = lane & 3;
    int b = m0 >> 10;
    float acc[2][8][4] = {};
    uint4 ra[2], rb[2];

    auto gload = [&](int k0) {
        int tap = k0 >> 8;
        int ky = tap / 3, kx = tap - ky * 3;
        int cib = (k0 & 255) + ((tid & 3) << 3);
        #pragma unroll
        for (int l = 0; l < 2; l++) {
            int idx = tid + (l << 8);
            int mrow = idx >> 2;
            int r = (m0 + mrow) & 1023;
            int oy = r >> 5, ox = r & 31;
            int iy = 2 * oy - 1 + ky, ix = 2 * ox - 1 + kx;
            if ((unsigned)iy < 64u && (unsigned)ix < 64u)
                ra[l] = *(const uint4*)&g_ash[(((size_t)(b << 12) + (iy << 6) + ix) << 8) + cib];
            else
                ra[l] = make_uint4(0u, 0u, 0u, 0u);
            rb[l] = *(const uint4*)&g_wch[(size_t)(n0 + mrow) * 2304 + k0 + ((idx & 3) << 3)];
        }
    };
    auto sstore = [&]() {
        #pragma unroll
        for (int l = 0; l < 2; l++) {
            int idx = tid + (l << 8);
            *(uint4*)&As[idx >> 2][(idx & 3) << 2] = ra[l];
            *(uint4*)&Bs[idx >> 2][(idx & 3) << 2] = rb[l];
        }
    };

    gload(0); sstore(); __syncthreads();
    for (int k0 = 0; k0 < 2304; k0 += 32) {
        bool more = (k0 + 32) < 2304;
        if (more) gload(k0 + 32);
        #pragma unroll
        for (int ks = 0; ks < 2; ks++) {
            int kb = ks << 3;
            unsigned a[2][4], bf[8][2];
            #pragma unroll
            for (int mt = 0; mt < 2; mt++) {
                int row = (warpM << 5) + (mt << 4) + g;
                a[mt][0] = As[row][kb + tig];     a[mt][1] = As[row + 8][kb + tig];
                a[mt][2] = As[row][kb + 4 + tig]; a[mt][3] = As[row + 8][kb + 4 + tig];
            }
            #pragma unroll
            for (int nt = 0; nt < 8; nt++) {
                int col = (warpN << 6) + (nt << 3) + g;
                bf[nt][0] = Bs[col][kb + tig]; bf[nt][1] = Bs[col][kb + 4 + tig];
            }
            #pragma unroll
            for (int mt = 0; mt < 2; mt++)
                #pragma unroll
                for (int nt = 0; nt < 8; nt++)
                    mma_f16(acc[mt][nt], a[mt], bf[nt]);
        }
        __syncthreads();
        if (more) { sstore(); __syncthreads(); }
    }

    #pragma unroll
    for (int mt = 0; mt < 2; mt++)
        #pragma unroll
        for (int nt = 0; nt < 8; nt++) {
            int row = (warpM << 5) + (mt << 4) + g;
            int col = n0 + (warpN << 6) + (nt << 3) + (tig << 1);
            float* c = acc[mt][nt];
            int r1 = (m0 + row) & 1023;
            *(__half2*)&g_c1h[(((size_t)(b << 10) + r1) << 8) + col] =
                __floats2half2_rn(fmaxf(c[0], 0.f), fmaxf(c[1], 0.f));
            int r2 = (m0 + row + 8) & 1023;
            *(__half2*)&g_c1h[(((size_t)(b << 10) + r2) << 8) + col] =
                __floats2half2_rn(fmaxf(c[2], 0.f), fmaxf(c[3], 0.f));
        }
}

// ---------------------------------------------------------------------------
// K6: convT 4x4 s2 p1 + relu by parity class, channels-last.
// ---------------------------------------------------------------------------
__global__ __launch_bounds__(256) void k_convt(void)
{
    __shared__ unsigned As[128][20];
    __shared__ unsigned Bs[128][20];
    int cl = blockIdx.z;
    int py = cl >> 1, px = cl & 1;
    int m0 = blockIdx.x << 7;
    int n0 = blockIdx.y << 7;
    int tid = threadIdx.x, lane = tid & 31, wid = tid >> 5;
    int warpM = wid >> 1, warpN = wid & 1;
    int g = lane >> 2, tig = lane & 3;
    int b = m0 >> 10;
    float acc[2][8][4] = {};
    uint4 ra[2], rb[2];

    auto gload = [&](int k0) {
        int t = k0 >> 8;
        int tyk = t >> 1, txk = t & 1;
        int cib = (k0 & 255) + ((tid & 3) << 3);
        #pragma unroll
        for (int l = 0; l < 2; l++) {
            int idx = tid + (l << 8);
            int mrow = idx >> 2;
            int r = (m0 + mrow) & 1023;
            int ys = r >> 5, xs = r & 31;
            int ii = ys + py - tyk, jj = xs + px - txk;
            if ((unsigned)ii < 32u && (unsigned)jj < 32u)
                ra[l] = *(const uint4*)&g_c1h[(((size_t)(b << 10) + (ii << 5) + jj) << 8) + cib];
            else
                ra[l] = make_uint4(0u, 0u, 0u, 0u);
            rb[l] = *(const uint4*)&g_wt2[(((size_t)((cl << 8) + n0 + mrow)) << 10) + k0 + ((idx & 3) << 3)];
        }
    };
    auto sstore = [&]() {
        #pragma unroll
        for (int l = 0; l < 2; l++) {
            int idx = tid + (l << 8);
            *(uint4*)&As[idx >> 2][(idx & 3) << 2] = ra[l];
            *(uint4*)&Bs[idx >> 2][(idx & 3) << 2] = rb[l];
        }
    };

    gload(0); sstore(); __syncthreads();
    for (int k0 = 0; k0 < 1024; k0 += 32) {
        bool more = (k0 + 32) < 1024;
        if (more) gload(k0 + 32);
        #pragma unroll
        for (int ks = 0; ks < 2; ks++) {
            int kb = ks << 3;
            unsigned a[2][4], bf[8][2];
            #pragma unroll
            for (int mt = 0; mt < 2; mt++) {
                int row = (warpM << 5) + (mt << 4) + g;
                a[mt][0] = As[row][kb + tig];     a[mt][1] = As[row + 8][kb + tig];
                a[mt][2] = As[row][kb + 4 + tig]; a[mt][3] = As[row + 8][kb + 4 + tig];
            }
            #pragma unroll
            for (int nt = 0; nt < 8; nt++) {
                int col = (warpN << 6) + (nt << 3) + g;
                bf[nt][0] = Bs[col][kb + tig]; bf[nt][1] = Bs[col][kb + 4 + tig];
            }
            #pragma unroll
            for (int mt = 0; mt < 2; mt++)
                #pragma unroll
                for (int nt = 0; nt < 8; nt++)
                    mma_f16(acc[mt][nt], a[mt], bf[nt]);
        }
        __syncthreads();
        if (more) { sstore(); __syncthreads(); }
    }

    #pragma unroll
    for (int mt = 0; mt < 2; mt++)
        #pragma unroll
        for (int nt = 0; nt < 8; nt++) {
            int row = (warpM << 5) + (mt << 4) + g;
            int col = n0 + (warpN << 6) + (nt << 3) + (tig << 1);
            float* c = acc[mt][nt];
            int mm1 = m0 + row;
            int ys1 = (mm1 >> 5) & 31, xs1 = mm1 & 31;
            size_t o1 = (((size_t)(b << 12) + (((ys1 << 1) + py) << 6) + (xs1 << 1) + px) << 8) + col;
            *(__half2*)&g_sbh[o1] = __floats2half2_rn(fmaxf(c[0], 0.f), fmaxf(c[1], 0.f));
            int mm2 = mm1 + 8;
            int ys2 = (mm2 >> 5) & 31, xs2 = mm2 & 31;
            size_t o2 = (((size_t)(b << 12) + (((ys2 << 1) + py) << 6) + (xs2 << 1) + px) << 8) + col;
            *(__half2*)&g_sbh[o2] = __floats2half2_rn(fmaxf(c[2], 0.f), fmaxf(c[3], 0.f));
        }
}

// ---------------------------------------------------------------------------
// K8: SE MLP (combines 128 pool partials per b)
// ---------------------------------------------------------------------------
__global__ __launch_bounds__(256) void k_se(const float* __restrict__ Wc1,
                                            const float* __restrict__ Wc2)
{
    int b = blockIdx.x;
    __shared__ float pool[256];
    __shared__ float hid[64];
    int t = threadIdx.x;
    float s = 0.f;
    #pragma unroll 16
    for (int j = 0; j < 128; j++) s += g_poolp[(size_t)((b << 7) + j) * 256 + t];
    pool[t] = s * (1.0f / 4096.0f);
    __syncthreads();
    if (t < 64) {
        float h = 0.f;
        for (int c = 0; c < 256; c++) h += pool[c] * Wc1[t * 256 + c];
        hid[t] = fmaxf(h, 0.f);
    }
    __syncthreads();
    float v = 0.f;
    #pragma unroll
    for (int j = 0; j < 64; j++) v += hid[j] * Wc2[t * 64 + j];
    g_gate[(b << 8) + t] = 1.0f / (1.0f + __expf(-v));
}

// ---------------------------------------------------------------------------
// K9: fused residual + LayerNorm. All inputs channels-last; warp per position.
// ---------------------------------------------------------------------------
__global__ __launch_bounds__(256) void k_fuse(const float* __restrict__ x,
                                              const float* __restrict__ gamma,
                                              const float* __restrict__ beta,
                                              float* __restrict__ out)
{
    int wid = threadIdx.x >> 5, lane = threadIdx.x & 31;
    int pos = (blockIdx.x << 3) + wid;
    int b = pos >> 12;
    size_t row = (size_t)pos << 8;
    int c0 = lane << 3;

    float4 x0 = *(const float4*)&x[row + c0];
    float4 x1 = *(const float4*)&x[row + c0 + 4];
    float vs[8], vc[8], sb[8], ac[8];
    unp8(*(const uint4*)&g_vsh[row + c0], vs);
    unp8(*(const uint4*)&g_vch[row + c0], vc);
    unp8(*(const uint4*)&g_sbh[row + c0], sb);
    unp8(*(const uint4*)&g_ach[row + c0], ac);
    float4 g0 = *(const float4*)&g_gate[(b << 8) + c0];
    float4 g1 = *(const float4*)&g_gate[(b << 8) + c0 + 4];
    float xs[8] = {x0.x, x0.y, x0.z, x0.w, x1.x, x1.y, x1.z, x1.w};
    float gt[8] = {g0.x, g0.y, g0.z, g0.w, g1.x, g1.y, g1.z, g1.w};

    float y[8];
    float s1 = 0.f, s2 = 0.f;
    #pragma unroll
    for (int j = 0; j < 8; j++) {
        y[j] = xs[j] + sb[j] * vs[j] + gt[j] * ac[j] * vc[j];
        s1 += y[j]; s2 += y[j] * y[j];
    }
    #pragma unroll
    for (int o = 16; o > 0; o >>= 1) {
        s1 += __shfl_xor_sync(0xffffffffu, s1, o);
        s2 += __shfl_xor_sync(0xffffffffu, s2, o);
    }
    float mu = s1 * (1.0f / 256.0f);
    float var = s2 * (1.0f / 256.0f) - mu * mu;
    float ri = rsqrtf(var + 1e-5f);

    float4 gm0 = *(const float4*)&gamma[c0];
    float4 gm1 = *(const float4*)&gamma[c0 + 4];
    float4 bt0 = *(const float4*)&beta[c0];
    float4 bt1 = *(const float4*)&beta[c0 + 4];
    float gm[8] = {gm0.x, gm0.y, gm0.z, gm0.w, gm1.x, gm1.y, gm1.z, gm1.w};
    float bt[8] = {bt0.x, bt0.y, bt0.z, bt0.w, bt1.x, bt1.y, bt1.z, bt1.w};
    float4 o0, o1;
    o0.x = (y[0] - mu) * ri * gm[0] + bt[0];
    o0.y = (y[1] - mu) * ri * gm[1] + bt[1];
    o0.z = (y[2] - mu) * ri * gm[2] + bt[2];
    o0.w = (y[3] - mu) * ri * gm[3] + bt[3];
    o1.x = (y[4] - mu) * ri * gm[4] + bt[4];
    o1.y = (y[5] - mu) * ri * gm[5] + bt[5];
    o1.z = (y[6] - mu) * ri * gm[6] + bt[6];
    o1.w = (y[7] - mu) * ri * gm[7] + bt[7];
    *(float4*)&out[row + c0]     = o0;
    *(float4*)&out[row + c0 + 4] = o1;
}

// ---------------------------------------------------------------------------
extern "C" void kernel_launch(void* const* d_in, const int* in_sizes, int n_in,
                              void* d_out, int out_size)
{
    const float* x      = (const float*)d_in[0];
    const float* Wq     = (const float*)d_in[1];
    const float* Wk     = (const float*)d_in[2];
    const float* Wvc    = (const float*)d_in[3];
    const float* Wvs    = (const float*)d_in[4];
    const float* Wc1    = (const float*)d_in[5];
    const float* Wc2    = (const float*)d_in[6];
    const float* Wconv  = (const float*)d_in[7];
    const float* Wconvt = (const float*)d_in[8];
    const float* gamma  = (const float*)d_in[9];
    const float* beta   = (const float*)d_in[10];
    float* out = (float*)d_out;

    k_packc<<<256, 256>>>(Wconv);
    k_packt<<<1024, 256>>>(Wconvt);
    k_proj <<<dim3(512, 8), 256>>>(x, Wq, Wk, Wvc, Wvs);
    k_attn <<<4096, 256>>>();
    k_softmax_t<<<dim3(2048, 2), 256>>>();
    k_conv <<<dim3(128, 2), 256>>>();
    k_convt<<<dim3(128, 2, 4), 256>>>();
    k_se   <<<16, 256>>>(Wc1, Wc2);
    k_fuse <<<8192, 256>>>(x, gamma, beta, out);
}